// round 1
// baseline (speedup 1.0000x reference)
#include <cuda_runtime.h>
#include <cuda_bf16.h>

// Problem constants: B=2, S=2048, DM=1024, H=16, DH=64
#define BATCH 2
#define SEQ 2048
#define DMODEL 1024
#define HEADS 16
#define HDIM 64
#define MROWS (BATCH*SEQ)          // 4096
#define QKV_ELEMS (BATCH*HEADS*SEQ*HDIM)  // 4,194,304

// ---------------- device scratch ----------------
__device__ float g_q[QKV_ELEMS];
__device__ float g_k[QKV_ELEMS];
__device__ float g_v[QKV_ELEMS];
// absmax slots (uint-encoded non-negative floats):
// 0=q_max 1=k_max 2=qk_raw_max 3=aw_max 4=v_max
__device__ unsigned g_mx[5];

__global__ void init_kernel() {
    if (threadIdx.x < 5) g_mx[threadIdx.x] = 0u;
}

// ---------------- fused QKV projection GEMM ----------------
// out[m,n] = sum_k X[m,k] * W[n,k] + bias[n]   (torch Linear)
// stored into g_{q,k,v} with layout [B,H,S,DH]
#define GBM 64
#define GBN 64
#define GBK 16

__global__ __launch_bounds__(256) void qkv_gemm(
    const float* __restrict__ X,
    const float* __restrict__ Wq, const float* __restrict__ bq,
    const float* __restrict__ Wk, const float* __restrict__ bk,
    const float* __restrict__ Wv, const float* __restrict__ bv)
{
    const int z = blockIdx.z;
    const float* __restrict__ W    = (z == 0) ? Wq : (z == 1) ? Wk : Wv;
    const float* __restrict__ bias = (z == 0) ? bq : (z == 1) ? bk : bv;
    float* __restrict__ O = (z == 0) ? g_q : (z == 1) ? g_k : g_v;
    const int mslot = (z == 0) ? 0 : (z == 1) ? 1 : 4;

    __shared__ float As[GBK][GBM + 4];
    __shared__ float Bs[GBK][GBN + 4];
    __shared__ unsigned smax;

    const int tid = threadIdx.x;
    const int tx = tid & 15;       // 0..15 -> n
    const int ty = tid >> 4;       // 0..15 -> m
    const int m0 = blockIdx.y * GBM;
    const int n0 = blockIdx.x * GBN;

    const int lm  = tid >> 2;        // 0..63
    const int lk4 = (tid & 3) << 2;  // 0,4,8,12

    float acc[4][4];
    #pragma unroll
    for (int i = 0; i < 4; i++)
        #pragma unroll
        for (int j = 0; j < 4; j++) acc[i][j] = 0.f;

    for (int k0 = 0; k0 < DMODEL; k0 += GBK) {
        float4 a4 = *(const float4*)&X[(size_t)(m0 + lm) * DMODEL + k0 + lk4];
        float4 b4 = *(const float4*)&W[(size_t)(n0 + lm) * DMODEL + k0 + lk4];
        __syncthreads();
        As[lk4 + 0][lm] = a4.x; As[lk4 + 1][lm] = a4.y;
        As[lk4 + 2][lm] = a4.z; As[lk4 + 3][lm] = a4.w;
        Bs[lk4 + 0][lm] = b4.x; Bs[lk4 + 1][lm] = b4.y;
        Bs[lk4 + 2][lm] = b4.z; Bs[lk4 + 3][lm] = b4.w;
        __syncthreads();
        #pragma unroll
        for (int kk = 0; kk < GBK; kk++) {
            float4 av = *(const float4*)&As[kk][ty << 2];
            float4 bv = *(const float4*)&Bs[kk][tx << 2];
            float a[4] = {av.x, av.y, av.z, av.w};
            float b[4] = {bv.x, bv.y, bv.z, bv.w};
            #pragma unroll
            for (int i = 0; i < 4; i++)
                #pragma unroll
                for (int j = 0; j < 4; j++) acc[i][j] += a[i] * b[j];
        }
    }

    float lmax = 0.f;
    #pragma unroll
    for (int i = 0; i < 4; i++) {
        const int m = m0 + (ty << 2) + i;
        const int bb = m >> 11;        // /2048
        const int s  = m & 2047;
        #pragma unroll
        for (int j = 0; j < 4; j++) {
            const int n = n0 + (tx << 2) + j;
            const int h = n >> 6;
            const int d = n & 63;
            float v = acc[i][j] + bias[n];
            lmax = fmaxf(lmax, fabsf(v));
            O[((((size_t)bb * HEADS + h) * SEQ) + s) * HDIM + d] = v;
        }
    }

    if (tid == 0) smax = 0u;
    __syncthreads();
    atomicMax(&smax, __float_as_uint(lmax));
    __syncthreads();
    if (tid == 0) atomicMax(&g_mx[mslot], smax);
}

// ---------------- flash-style attention ----------------
#define ABM 128   // q rows per block (1 per thread)
#define ABN 32    // k/v tile
#define QSH_STRIDE (ABM + 1)
#define ATTN_SMEM_FLOATS (HDIM * QSH_STRIDE + 2 * ABN * HDIM)
#define ATTN_SMEM_BYTES (ATTN_SMEM_FLOATS * 4)

__global__ __launch_bounds__(128) void attn_kernel(float* __restrict__ out)
{
    extern __shared__ float sh[];
    float* q_sh = sh;                          // [64][ABM+1] transposed
    float* k_sh = sh + HDIM * QSH_STRIDE;      // [ABN][64]
    float* v_sh = k_sh + ABN * HDIM;           // [ABN][64]
    __shared__ unsigned s_raw, s_aw;

    const int tid = threadIdx.x;
    const int bh = blockIdx.y;                 // b*16 + h
    const int b  = bh >> 4;
    const int h  = bh & 15;
    const int r0 = blockIdx.x * ABM;

    const float* __restrict__ Q = g_q + (size_t)bh * SEQ * HDIM;
    const float* __restrict__ K = g_k + (size_t)bh * SEQ * HDIM;
    const float* __restrict__ V = g_v + (size_t)bh * SEQ * HDIM;

    // load Q tile transposed: q_sh[d][r]
    for (int i = tid * 4; i < ABM * HDIM; i += 128 * 4) {
        const int r = i >> 6;
        const int d = i & 63;
        float4 qv = *(const float4*)&Q[(size_t)(r0 + r) * HDIM + d];
        q_sh[(d + 0) * QSH_STRIDE + r] = qv.x;
        q_sh[(d + 1) * QSH_STRIDE + r] = qv.y;
        q_sh[(d + 2) * QSH_STRIDE + r] = qv.z;
        q_sh[(d + 3) * QSH_STRIDE + r] = qv.w;
    }

    float o[HDIM];
    #pragma unroll
    for (int d = 0; d < HDIM; d++) o[d] = 0.f;
    float m = -1e30f, l = 0.f;
    float rawmax = 0.f;

    for (int j0 = 0; j0 < SEQ; j0 += ABN) {
        __syncthreads();  // previous tile fully consumed (also covers q load)
        for (int i = tid * 4; i < ABN * HDIM; i += 128 * 4) {
            const int j = i >> 6;
            const int d = i & 63;
            *(float4*)&k_sh[j * HDIM + d] = *(const float4*)&K[(size_t)(j0 + j) * HDIM + d];
            *(float4*)&v_sh[j * HDIM + d] = *(const float4*)&V[(size_t)(j0 + j) * HDIM + d];
        }
        __syncthreads();

        float s[ABN];
        #pragma unroll
        for (int j = 0; j < ABN; j++) s[j] = 0.f;

        #pragma unroll 1
        for (int d0 = 0; d0 < HDIM; d0 += 16) {
            float qreg[16];
            #pragma unroll
            for (int dd = 0; dd < 16; dd++)
                qreg[dd] = q_sh[(d0 + dd) * QSH_STRIDE + tid];
            #pragma unroll
            for (int j = 0; j < ABN; j++) {
                #pragma unroll
                for (int dd = 0; dd < 16; dd++)
                    s[j] += qreg[dd] * k_sh[j * HDIM + d0 + dd];
            }
        }

        // raw absmax (pre-scale), then scale by 1/sqrt(64)
        float bmax = -1e30f;
        #pragma unroll
        for (int j = 0; j < ABN; j++) {
            rawmax = fmaxf(rawmax, fabsf(s[j]));
            s[j] *= 0.125f;
            bmax = fmaxf(bmax, s[j]);
        }
        const float mnew = fmaxf(m, bmax);
        const float factor = __expf(m - mnew);
        float psum = 0.f;
        #pragma unroll
        for (int j = 0; j < ABN; j++) {
            s[j] = __expf(s[j] - mnew);
            psum += s[j];
        }
        l = l * factor + psum;
        m = mnew;
        #pragma unroll
        for (int d = 0; d < HDIM; d++) o[d] *= factor;
        #pragma unroll
        for (int j = 0; j < ABN; j++) {
            const float pj = s[j];
            #pragma unroll
            for (int d = 0; d < HDIM; d++)
                o[d] += pj * v_sh[j * HDIM + d];
        }
    }

    const float invl = 1.f / l;
    // attn_output layout [B, S, H*DH]
    const size_t obase = ((size_t)b * SEQ + (r0 + tid)) * DMODEL + (size_t)h * HDIM;
    #pragma unroll
    for (int d = 0; d < HDIM; d += 4) {
        float4 w;
        w.x = o[d + 0] * invl; w.y = o[d + 1] * invl;
        w.z = o[d + 2] * invl; w.w = o[d + 3] * invl;
        *(float4*)&out[obase + d] = w;
    }

    if (tid == 0) { s_raw = 0u; s_aw = 0u; }
    __syncthreads();
    atomicMax(&s_raw, __float_as_uint(rawmax));
    atomicMax(&s_aw, __float_as_uint(invl));   // max softmax prob this row = 1/l
    __syncthreads();
    if (tid == 0) {
        atomicMax(&g_mx[2], s_raw);
        atomicMax(&g_mx[3], s_aw);
    }
}

// ---------------- finalize scalars ----------------
__global__ void finalize_kernel(float* __restrict__ out, int base)
{
    if (threadIdx.x == 0) {
        const float qm  = __uint_as_float(g_mx[0]);
        const float km  = __uint_as_float(g_mx[1]);
        const float qkm = __uint_as_float(g_mx[2]);
        const float awm = __uint_as_float(g_mx[3]);
        const float vm  = __uint_as_float(g_mx[4]);
        out[base + 0] = qm;   // q_max
        out[base + 1] = km;   // kT_max
        out[base + 2] = qkm;  // qk_out_max
        out[base + 3] = awm;  // aw_max
        out[base + 4] = vm;   // v_max
        out[base + 5] = awm;  // v_out_max (source bug: re-reads attn_weights)
    }
}

// ---------------- launch ----------------
extern "C" void kernel_launch(void* const* d_in, const int* in_sizes, int n_in,
                              void* d_out, int out_size)
{
    const float* X  = (const float*)d_in[0];
    const float* Wq = (const float*)d_in[1];
    const float* bq = (const float*)d_in[2];
    const float* Wk = (const float*)d_in[3];
    const float* bk = (const float*)d_in[4];
    const float* Wv = (const float*)d_in[5];
    const float* bv = (const float*)d_in[6];
    float* out = (float*)d_out;

    cudaFuncSetAttribute(attn_kernel,
                         cudaFuncAttributeMaxDynamicSharedMemorySize,
                         ATTN_SMEM_BYTES);

    init_kernel<<<1, 32>>>();
    qkv_gemm<<<dim3(DMODEL / GBN, MROWS / GBM, 3), 256>>>(X, Wq, bq, Wk, bk, Wv, bv);
    attn_kernel<<<dim3(SEQ / ABM, BATCH * HEADS), 128, ATTN_SMEM_BYTES>>>(out);
    finalize_kernel<<<1, 32>>>(out, out_size - 6);
}

// round 3
// speedup vs baseline: 2.9788x; 2.9788x over previous
#include <cuda_runtime.h>
#include <cuda_bf16.h>
#include <cstdint>

// Problem constants: B=2, S=2048, DM=1024, H=16, DH=64
#define BATCH 2
#define SEQ 2048
#define DMODEL 1024
#define HEADS 16
#define HDIM 64
#define MROWS (BATCH*SEQ)                 // 4096
#define QKV_ELEMS (BATCH*HEADS*SEQ*HDIM)  // 4,194,304

// ---------------- device scratch ----------------
__device__ __nv_bfloat16 g_xhi[MROWS * DMODEL];
__device__ __nv_bfloat16 g_xlo[MROWS * DMODEL];
__device__ __nv_bfloat16 g_whi[3 * DMODEL * DMODEL];
__device__ __nv_bfloat16 g_wlo[3 * DMODEL * DMODEL];
__device__ __nv_bfloat16 g_qhi[QKV_ELEMS], g_qlo[QKV_ELEMS];
__device__ __nv_bfloat16 g_khi[QKV_ELEMS], g_klo[QKV_ELEMS];
__device__ __nv_bfloat16 g_vhi[QKV_ELEMS], g_vlo[QKV_ELEMS];
// absmax slots: 0=q 1=k 2=qk_raw 3=aw 4=v
__device__ unsigned g_mx[5];

__global__ void init_kernel() {
    if (threadIdx.x < 5) g_mx[threadIdx.x] = 0u;
}
__global__ void spacer_kernel() {}   // shifts attn to launch idx 5 for ncu -s 5

// ---------------- helpers ----------------
__device__ __forceinline__ void mma_bf16(float (&c)[4], const uint32_t (&a)[4],
                                         uint32_t b0, uint32_t b1) {
    asm volatile(
        "mma.sync.aligned.m16n8k16.row.col.f32.bf16.bf16.f32 "
        "{%0,%1,%2,%3}, {%4,%5,%6,%7}, {%8,%9}, {%0,%1,%2,%3};"
        : "+f"(c[0]), "+f"(c[1]), "+f"(c[2]), "+f"(c[3])
        : "r"(a[0]), "r"(a[1]), "r"(a[2]), "r"(a[3]), "r"(b0), "r"(b1));
}
__device__ __forceinline__ uint32_t packb(float lo, float hi) {
    uint32_t r;
    asm("cvt.rn.bf16x2.f32 %0, %1, %2;" : "=r"(r) : "f"(hi), "f"(lo));
    return r;
}

// ---------------- fp32 -> bf16 hi/lo split conversion ----------------
__global__ __launch_bounds__(256) void convert_x(const float* __restrict__ X) {
    size_t i4 = ((size_t)blockIdx.x * 256 + threadIdx.x) * 4;
    float4 v = *(const float4*)(X + i4);
    float f[4] = {v.x, v.y, v.z, v.w};
    __nv_bfloat16 h[4], l[4];
#pragma unroll
    for (int j = 0; j < 4; j++) {
        h[j] = __float2bfloat16_rn(f[j]);
        l[j] = __float2bfloat16_rn(f[j] - __bfloat162float(h[j]));
    }
    *(__nv_bfloat162*)(g_xhi + i4 + 0) = __nv_bfloat162(h[0], h[1]);
    *(__nv_bfloat162*)(g_xhi + i4 + 2) = __nv_bfloat162(h[2], h[3]);
    *(__nv_bfloat162*)(g_xlo + i4 + 0) = __nv_bfloat162(l[0], l[1]);
    *(__nv_bfloat162*)(g_xlo + i4 + 2) = __nv_bfloat162(l[2], l[3]);
}

__global__ __launch_bounds__(256) void convert_w(
    const float* __restrict__ Wq, const float* __restrict__ Wk,
    const float* __restrict__ Wv) {
    const int z = blockIdx.z;
    const float* W = (z == 0) ? Wq : (z == 1) ? Wk : Wv;
    size_t base = (size_t)z * DMODEL * DMODEL;
    size_t i4 = ((size_t)blockIdx.x * 256 + threadIdx.x) * 4;
    float4 v = *(const float4*)(W + i4);
    float f[4] = {v.x, v.y, v.z, v.w};
    __nv_bfloat16 h[4], l[4];
#pragma unroll
    for (int j = 0; j < 4; j++) {
        h[j] = __float2bfloat16_rn(f[j]);
        l[j] = __float2bfloat16_rn(f[j] - __bfloat162float(h[j]));
    }
    *(__nv_bfloat162*)(g_whi + base + i4 + 0) = __nv_bfloat162(h[0], h[1]);
    *(__nv_bfloat162*)(g_whi + base + i4 + 2) = __nv_bfloat162(h[2], h[3]);
    *(__nv_bfloat162*)(g_wlo + base + i4 + 0) = __nv_bfloat162(l[0], l[1]);
    *(__nv_bfloat162*)(g_wlo + base + i4 + 2) = __nv_bfloat162(l[2], l[3]);
}

// ---------------- split-bf16 QKV GEMM via mma.sync ----------------
// C[m,n] = X[m,:]·W[n,:] + bias[n]  (torch Linear), M=N tile 128, Kc=32
#define GKC 32
#define GST 40                       // smem row stride (bf16), 80B, 16B-aligned
#define GMAT (128 * GST)             // elems per matrix per stage
#define GSTAGE (4 * GMAT)            // Ah Al Bh Bl
#define GEMM_SMEM_BYTES (2 * GSTAGE * 2)

__global__ __launch_bounds__(256, 1) void qkv_gemm_mma(
    const float* __restrict__ bq, const float* __restrict__ bk,
    const float* __restrict__ bv)
{
    extern __shared__ __nv_bfloat16 sm[];
    __shared__ unsigned s_amax;

    const int tid = threadIdx.x;
    const int wid = tid >> 5;
    const int lane = tid & 31;
    const int g = lane >> 2;          // 0..7
    const int t = lane & 3;           // 0..3
    const int wm = wid & 1;           // warp m: 0..1 (64 rows each)
    const int wn = wid >> 1;          // warp n: 0..3 (32 cols each)

    const int z = blockIdx.z;
    const int m0 = blockIdx.y * 128;
    const int n0 = blockIdx.x * 128;

    const float* __restrict__ bias = (z == 0) ? bq : (z == 1) ? bk : bv;
    __nv_bfloat16* __restrict__ Ohi = (z == 0) ? g_qhi : (z == 1) ? g_khi : g_vhi;
    __nv_bfloat16* __restrict__ Olo = (z == 0) ? g_qlo : (z == 1) ? g_klo : g_vlo;
    const int mslot = (z == 0) ? 0 : (z == 1) ? 1 : 4;

    const __nv_bfloat16* __restrict__ Ah = g_xhi + (size_t)m0 * DMODEL;
    const __nv_bfloat16* __restrict__ Al = g_xlo + (size_t)m0 * DMODEL;
    const __nv_bfloat16* __restrict__ Bh = g_whi + (size_t)z * DMODEL * DMODEL + (size_t)n0 * DMODEL;
    const __nv_bfloat16* __restrict__ Bl = g_wlo + (size_t)z * DMODEL * DMODEL + (size_t)n0 * DMODEL;

    if (tid == 0) s_amax = 0u;

    float c[4][4][4];
#pragma unroll
    for (int mt = 0; mt < 4; mt++)
#pragma unroll
        for (int nt = 0; nt < 4; nt++)
#pragma unroll
            for (int r = 0; r < 4; r++) c[mt][nt][r] = 0.f;

    uint4 ld[8];
    // prologue: load chunk 0
    {
        const int k0 = 0;
#pragma unroll
        for (int i = 0; i < 2; i++) {
            const int u = tid + i * 256;
            const int row = u >> 2, cu = u & 3;
            const size_t off = (size_t)row * DMODEL + k0 + cu * 8;
            ld[i * 4 + 0] = *(const uint4*)(Ah + off);
            ld[i * 4 + 1] = *(const uint4*)(Al + off);
            ld[i * 4 + 2] = *(const uint4*)(Bh + off);
            ld[i * 4 + 3] = *(const uint4*)(Bl + off);
        }
    }
#pragma unroll
    for (int i = 0; i < 2; i++) {
        const int u = tid + i * 256;
        const int row = u >> 2, cu = u & 3;
        const int so = row * GST + cu * 8;
        *(uint4*)(sm + 0 * GMAT + so) = ld[i * 4 + 0];
        *(uint4*)(sm + 1 * GMAT + so) = ld[i * 4 + 1];
        *(uint4*)(sm + 2 * GMAT + so) = ld[i * 4 + 2];
        *(uint4*)(sm + 3 * GMAT + so) = ld[i * 4 + 3];
    }
    __syncthreads();

    const int NCH = DMODEL / GKC;     // 32
    for (int ch = 0; ch < NCH; ch++) {
        if (ch + 1 < NCH) {
            const int k0 = (ch + 1) * GKC;
#pragma unroll
            for (int i = 0; i < 2; i++) {
                const int u = tid + i * 256;
                const int row = u >> 2, cu = u & 3;
                const size_t off = (size_t)row * DMODEL + k0 + cu * 8;
                ld[i * 4 + 0] = *(const uint4*)(Ah + off);
                ld[i * 4 + 1] = *(const uint4*)(Al + off);
                ld[i * 4 + 2] = *(const uint4*)(Bh + off);
                ld[i * 4 + 3] = *(const uint4*)(Bl + off);
            }
        }
        // compute on stage ch&1
        const __nv_bfloat16* sAh = sm + (ch & 1) * GSTAGE + 0 * GMAT;
        const __nv_bfloat16* sAl = sm + (ch & 1) * GSTAGE + 1 * GMAT;
        const __nv_bfloat16* sBh = sm + (ch & 1) * GSTAGE + 2 * GMAT;
        const __nv_bfloat16* sBl = sm + (ch & 1) * GSTAGE + 3 * GMAT;
#pragma unroll
        for (int ks = 0; ks < 2; ks++) {
            const int kc = ks * 16 + 2 * t;
            uint32_t ah[4][4], al[4][4];
#pragma unroll
            for (int mt = 0; mt < 4; mt++) {
                const int row = wm * 64 + mt * 16 + g;
                const int a00 = row * GST + kc;
                ah[mt][0] = *(const uint32_t*)(sAh + a00);
                ah[mt][1] = *(const uint32_t*)(sAh + a00 + 8 * GST);
                ah[mt][2] = *(const uint32_t*)(sAh + a00 + 8);
                ah[mt][3] = *(const uint32_t*)(sAh + a00 + 8 * GST + 8);
                al[mt][0] = *(const uint32_t*)(sAl + a00);
                al[mt][1] = *(const uint32_t*)(sAl + a00 + 8 * GST);
                al[mt][2] = *(const uint32_t*)(sAl + a00 + 8);
                al[mt][3] = *(const uint32_t*)(sAl + a00 + 8 * GST + 8);
            }
            uint32_t bhf[4][2], blf[4][2];
#pragma unroll
            for (int nt = 0; nt < 4; nt++) {
                const int n = wn * 32 + nt * 8 + g;
                const int b00 = n * GST + kc;
                bhf[nt][0] = *(const uint32_t*)(sBh + b00);
                bhf[nt][1] = *(const uint32_t*)(sBh + b00 + 8);
                blf[nt][0] = *(const uint32_t*)(sBl + b00);
                blf[nt][1] = *(const uint32_t*)(sBl + b00 + 8);
            }
#pragma unroll
            for (int mt = 0; mt < 4; mt++)
#pragma unroll
                for (int nt = 0; nt < 4; nt++) {
                    mma_bf16(c[mt][nt], ah[mt], bhf[nt][0], bhf[nt][1]);
                    mma_bf16(c[mt][nt], ah[mt], blf[nt][0], blf[nt][1]);
                    mma_bf16(c[mt][nt], al[mt], bhf[nt][0], bhf[nt][1]);
                }
        }
        if (ch + 1 < NCH) {
            __syncthreads();
            const int st = (ch + 1) & 1;
#pragma unroll
            for (int i = 0; i < 2; i++) {
                const int u = tid + i * 256;
                const int row = u >> 2, cu = u & 3;
                const int so = st * GSTAGE + row * GST + cu * 8;
                *(uint4*)(sm + so + 0 * GMAT) = ld[i * 4 + 0];
                *(uint4*)(sm + so + 1 * GMAT) = ld[i * 4 + 1];
                *(uint4*)(sm + so + 2 * GMAT) = ld[i * 4 + 2];
                *(uint4*)(sm + so + 3 * GMAT) = ld[i * 4 + 3];
            }
            __syncthreads();
        }
    }

    // epilogue: bias, absmax, split -> bf16 hi/lo, layout [BH][S][64]
    float lmax = 0.f;
#pragma unroll
    for (int nt = 0; nt < 4; nt++) {
        const int n = n0 + wn * 32 + nt * 8 + 2 * t;
        const float bn0 = bias[n], bn1 = bias[n + 1];
        const int h = n >> 6, d = n & 63;
#pragma unroll
        for (int mt = 0; mt < 4; mt++) {
            const int mr0 = m0 + wm * 64 + mt * 16 + g;
            const int mr1 = mr0 + 8;
            float v0 = c[mt][nt][0] + bn0;
            float v1 = c[mt][nt][1] + bn1;
            float v2 = c[mt][nt][2] + bn0;
            float v3 = c[mt][nt][3] + bn1;
            lmax = fmaxf(lmax, fmaxf(fmaxf(fabsf(v0), fabsf(v1)),
                                     fmaxf(fabsf(v2), fabsf(v3))));
            const int bb0 = mr0 >> 11, s0 = mr0 & 2047;
            const int bb1 = mr1 >> 11, s1 = mr1 & 2047;
            const size_t o0 = (((size_t)(bb0 * HEADS + h)) * SEQ + s0) * HDIM + d;
            const size_t o1 = (((size_t)(bb1 * HEADS + h)) * SEQ + s1) * HDIM + d;
            uint32_t h0 = packb(v0, v1), h1 = packb(v2, v3);
            __nv_bfloat162 hb0 = *(__nv_bfloat162*)&h0;
            __nv_bfloat162 hb1 = *(__nv_bfloat162*)&h1;
            uint32_t l0 = packb(v0 - __bfloat162float(hb0.x), v1 - __bfloat162float(hb0.y));
            uint32_t l1 = packb(v2 - __bfloat162float(hb1.x), v3 - __bfloat162float(hb1.y));
            *(uint32_t*)(Ohi + o0) = h0;
            *(uint32_t*)(Ohi + o1) = h1;
            *(uint32_t*)(Olo + o0) = l0;
            *(uint32_t*)(Olo + o1) = l1;
        }
    }
    atomicMax(&s_amax, __float_as_uint(lmax));
    __syncthreads();
    if (tid == 0) atomicMax(&g_mx[mslot], s_amax);
}

// ---------------- warp-MMA flash attention (split-bf16) ----------------
// block: 256 thr (8 warps), 128 q rows (16/warp), kv tiles of 64
#define KST 72   // K/V smem row stride (bf16), 144B, 16B-aligned

__global__ __launch_bounds__(256, 1) void attn_mma(float* __restrict__ out)
{
    __shared__ __align__(16) __nv_bfloat16 kh[64 * KST], kl[64 * KST];
    __shared__ __align__(16) __nv_bfloat16 vh[64 * KST], vl[64 * KST];
    __shared__ unsigned s_raw, s_aw;

    const int tid = threadIdx.x;
    const int wid = tid >> 5;
    const int lane = tid & 31;
    const int g = lane >> 2;
    const int t = lane & 3;

    const int bh = blockIdx.y;
    const int b = bh >> 4, h = bh & 15;
    const int q0 = blockIdx.x * 128;

    if (tid == 0) { s_raw = 0u; s_aw = 0u; }

    // Q fragments (hi/lo), loaded once from global
    const size_t qbase = ((size_t)bh * SEQ + q0 + wid * 16) * HDIM;
    const __nv_bfloat16* Qh = g_qhi + qbase;
    const __nv_bfloat16* Ql = g_qlo + qbase;
    uint32_t qh[4][4], ql[4][4];
#pragma unroll
    for (int kk = 0; kk < 4; kk++) {
        const int c0 = kk * 16 + 2 * t;
        qh[kk][0] = *(const uint32_t*)(Qh + g * HDIM + c0);
        qh[kk][1] = *(const uint32_t*)(Qh + (g + 8) * HDIM + c0);
        qh[kk][2] = *(const uint32_t*)(Qh + g * HDIM + c0 + 8);
        qh[kk][3] = *(const uint32_t*)(Qh + (g + 8) * HDIM + c0 + 8);
        ql[kk][0] = *(const uint32_t*)(Ql + g * HDIM + c0);
        ql[kk][1] = *(const uint32_t*)(Ql + (g + 8) * HDIM + c0);
        ql[kk][2] = *(const uint32_t*)(Ql + g * HDIM + c0 + 8);
        ql[kk][3] = *(const uint32_t*)(Ql + (g + 8) * HDIM + c0 + 8);
    }

    const __nv_bfloat16* Kh = g_khi + (size_t)bh * SEQ * HDIM;
    const __nv_bfloat16* Kl = g_klo + (size_t)bh * SEQ * HDIM;
    const __nv_bfloat16* Vh = g_vhi + (size_t)bh * SEQ * HDIM;
    const __nv_bfloat16* Vl = g_vlo + (size_t)bh * SEQ * HDIM;

    float o[8][4];
#pragma unroll
    for (int j = 0; j < 8; j++)
#pragma unroll
        for (int r = 0; r < 4; r++) o[j][r] = 0.f;
    float m0 = -1e30f, m1 = -1e30f, l0 = 0.f, l1 = 0.f, raw = 0.f;

    for (int kv0 = 0; kv0 < SEQ; kv0 += 64) {
        __syncthreads();
#pragma unroll
        for (int i = 0; i < 2; i++) {
            const int u = tid + i * 256;
            const int row = u >> 3, du = u & 7;
            const size_t go = (size_t)(kv0 + row) * HDIM + du * 8;
            const int so = row * KST + du * 8;
            *(uint4*)(kh + so) = *(const uint4*)(Kh + go);
            *(uint4*)(kl + so) = *(const uint4*)(Kl + go);
            *(uint4*)(vh + so) = *(const uint4*)(Vh + go);
            *(uint4*)(vl + so) = *(const uint4*)(Vl + go);
        }
        __syncthreads();

        // S = Q K^T (split, 3 passes)
        float s[8][4];
#pragma unroll
        for (int j = 0; j < 8; j++)
#pragma unroll
            for (int r = 0; r < 4; r++) s[j][r] = 0.f;
#pragma unroll
        for (int kk = 0; kk < 4; kk++) {
#pragma unroll
            for (int j = 0; j < 8; j++) {
                const int ka = (8 * j + g) * KST + kk * 16 + 2 * t;
                uint32_t bh0 = *(const uint32_t*)(kh + ka);
                uint32_t bh1 = *(const uint32_t*)(kh + ka + 8);
                uint32_t bl0 = *(const uint32_t*)(kl + ka);
                uint32_t bl1 = *(const uint32_t*)(kl + ka + 8);
                mma_bf16(s[j], qh[kk], bh0, bh1);
                mma_bf16(s[j], qh[kk], bl0, bl1);
                mma_bf16(s[j], ql[kk], bh0, bh1);
            }
        }

        // raw absmax (pre-scale), scale, online softmax
        float rm0 = -1e30f, rm1 = -1e30f;
#pragma unroll
        for (int j = 0; j < 8; j++) {
#pragma unroll
            for (int r = 0; r < 4; r++) {
                raw = fmaxf(raw, fabsf(s[j][r]));
                s[j][r] *= 0.125f;
            }
            rm0 = fmaxf(rm0, fmaxf(s[j][0], s[j][1]));
            rm1 = fmaxf(rm1, fmaxf(s[j][2], s[j][3]));
        }
        rm0 = fmaxf(rm0, __shfl_xor_sync(0xffffffffu, rm0, 1));
        rm0 = fmaxf(rm0, __shfl_xor_sync(0xffffffffu, rm0, 2));
        rm1 = fmaxf(rm1, __shfl_xor_sync(0xffffffffu, rm1, 1));
        rm1 = fmaxf(rm1, __shfl_xor_sync(0xffffffffu, rm1, 2));
        const float mn0 = fmaxf(m0, rm0), mn1 = fmaxf(m1, rm1);
        const float f0 = __expf(m0 - mn0), f1 = __expf(m1 - mn1);
        float ps0 = 0.f, ps1 = 0.f;
#pragma unroll
        for (int j = 0; j < 8; j++) {
            s[j][0] = __expf(s[j][0] - mn0);
            s[j][1] = __expf(s[j][1] - mn0);
            s[j][2] = __expf(s[j][2] - mn1);
            s[j][3] = __expf(s[j][3] - mn1);
            ps0 += s[j][0] + s[j][1];
            ps1 += s[j][2] + s[j][3];
        }
        ps0 += __shfl_xor_sync(0xffffffffu, ps0, 1);
        ps0 += __shfl_xor_sync(0xffffffffu, ps0, 2);
        ps1 += __shfl_xor_sync(0xffffffffu, ps1, 1);
        ps1 += __shfl_xor_sync(0xffffffffu, ps1, 2);
        l0 = l0 * f0 + ps0;
        l1 = l1 * f1 + ps1;
        m0 = mn0; m1 = mn1;
#pragma unroll
        for (int j = 0; j < 8; j++) {
            o[j][0] *= f0; o[j][1] *= f0;
            o[j][2] *= f1; o[j][3] *= f1;
        }

        // P -> split bf16 fragments
        uint32_t ph[8][2], pl[8][2];
#pragma unroll
        for (int j = 0; j < 8; j++) {
            uint32_t p0 = packb(s[j][0], s[j][1]);
            uint32_t p1 = packb(s[j][2], s[j][3]);
            __nv_bfloat162 b0 = *(__nv_bfloat162*)&p0;
            __nv_bfloat162 b1 = *(__nv_bfloat162*)&p1;
            ph[j][0] = p0; ph[j][1] = p1;
            pl[j][0] = packb(s[j][0] - __bfloat162float(b0.x),
                             s[j][1] - __bfloat162float(b0.y));
            pl[j][1] = packb(s[j][2] - __bfloat162float(b1.x),
                             s[j][3] - __bfloat162float(b1.y));
        }

        // O += P V (split, 3 passes); V row-major, B frag via paired u16
        const unsigned short* vhu = (const unsigned short*)vh;
        const unsigned short* vlu = (const unsigned short*)vl;
#pragma unroll
        for (int kk = 0; kk < 4; kk++) {
            uint32_t pah[4] = {ph[2 * kk][0], ph[2 * kk][1],
                               ph[2 * kk + 1][0], ph[2 * kk + 1][1]};
            uint32_t pal[4] = {pl[2 * kk][0], pl[2 * kk][1],
                               pl[2 * kk + 1][0], pl[2 * kk + 1][1]};
#pragma unroll
            for (int j = 0; j < 8; j++) {
                const int base = (16 * kk + 2 * t) * KST + 8 * j + g;
                uint32_t bh0 = (uint32_t)vhu[base] | ((uint32_t)vhu[base + KST] << 16);
                uint32_t bh1 = (uint32_t)vhu[base + 8 * KST] | ((uint32_t)vhu[base + 9 * KST] << 16);
                uint32_t bl0 = (uint32_t)vlu[base] | ((uint32_t)vlu[base + KST] << 16);
                uint32_t bl1 = (uint32_t)vlu[base + 8 * KST] | ((uint32_t)vlu[base + 9 * KST] << 16);
                mma_bf16(o[j], pah, bh0, bh1);
                mma_bf16(o[j], pah, bl0, bl1);
                mma_bf16(o[j], pal, bh0, bh1);
            }
        }
    }

    // epilogue
    const float i0 = 1.f / l0, i1 = 1.f / l1;
    const int r0g = q0 + wid * 16 + g;
    const int r1g = r0g + 8;
    const size_t ob0 = ((size_t)b * SEQ + r0g) * DMODEL + h * HDIM;
    const size_t ob1 = ((size_t)b * SEQ + r1g) * DMODEL + h * HDIM;
#pragma unroll
    for (int j = 0; j < 8; j++) {
        const int d = 8 * j + 2 * t;
        float2 w0 = {o[j][0] * i0, o[j][1] * i0};
        float2 w1 = {o[j][2] * i1, o[j][3] * i1};
        *(float2*)(out + ob0 + d) = w0;
        *(float2*)(out + ob1 + d) = w1;
    }
    atomicMax(&s_raw, __float_as_uint(raw));
    atomicMax(&s_aw, __float_as_uint(fmaxf(i0, i1)));
    __syncthreads();
    if (tid == 0) {
        atomicMax(&g_mx[2], s_raw);
        atomicMax(&g_mx[3], s_aw);
    }
}

// ---------------- finalize scalars ----------------
__global__ void finalize_kernel(float* __restrict__ out, int base)
{
    if (threadIdx.x == 0) {
        const float qm  = __uint_as_float(g_mx[0]);
        const float km  = __uint_as_float(g_mx[1]);
        const float qkm = __uint_as_float(g_mx[2]);
        const float awm = __uint_as_float(g_mx[3]);
        const float vm  = __uint_as_float(g_mx[4]);
        out[base + 0] = qm;
        out[base + 1] = km;
        out[base + 2] = qkm;
        out[base + 3] = awm;
        out[base + 4] = vm;
        out[base + 5] = awm;  // v_out_max (faithful source bug)
    }
}

// ---------------- launch ----------------
extern "C" void kernel_launch(void* const* d_in, const int* in_sizes, int n_in,
                              void* d_out, int out_size)
{
    const float* X  = (const float*)d_in[0];
    const float* Wq = (const float*)d_in[1];
    const float* bq = (const float*)d_in[2];
    const float* Wk = (const float*)d_in[3];
    const float* bk = (const float*)d_in[4];
    const float* Wv = (const float*)d_in[5];
    const float* bv = (const float*)d_in[6];
    float* out = (float*)d_out;

    cudaFuncSetAttribute(qkv_gemm_mma,
                         cudaFuncAttributeMaxDynamicSharedMemorySize,
                         GEMM_SMEM_BYTES);

    init_kernel<<<1, 32>>>();                                           // 0
    convert_x<<<MROWS * DMODEL / 4 / 256, 256>>>(X);                    // 1
    convert_w<<<dim3(DMODEL * DMODEL / 4 / 256, 1, 3), 256>>>(Wq, Wk, Wv); // 2
    qkv_gemm_mma<<<dim3(DMODEL / 128, MROWS / 128, 3), 256,
                   GEMM_SMEM_BYTES>>>(bq, bk, bv);                      // 3
    spacer_kernel<<<1, 32>>>();                                         // 4
    attn_mma<<<dim3(SEQ / 128, BATCH * HEADS), 256>>>(out);             // 5
    finalize_kernel<<<1, 32>>>(out, out_size - 6);                      // 6
}

// round 4
// speedup vs baseline: 3.4012x; 1.1418x over previous
#include <cuda_runtime.h>
#include <cuda_bf16.h>
#include <cstdint>

// Problem constants: B=2, S=2048, DM=1024, H=16, DH=64
#define BATCH 2
#define SEQ 2048
#define DMODEL 1024
#define HEADS 16
#define HDIM 64
#define MROWS (BATCH*SEQ)                 // 4096
#define QKV_ELEMS (BATCH*HEADS*SEQ*HDIM)  // 4,194,304

// ---------------- device scratch ----------------
__device__ __nv_bfloat16 g_xhi[MROWS * DMODEL];
__device__ __nv_bfloat16 g_xlo[MROWS * DMODEL];
__device__ __nv_bfloat16 g_whi[3 * DMODEL * DMODEL];
__device__ __nv_bfloat16 g_wlo[3 * DMODEL * DMODEL];
__device__ __nv_bfloat16 g_qhi[QKV_ELEMS], g_qlo[QKV_ELEMS];
__device__ __nv_bfloat16 g_khi[QKV_ELEMS], g_klo[QKV_ELEMS];
__device__ __nv_bfloat16 g_vhi[QKV_ELEMS], g_vlo[QKV_ELEMS];
// absmax slots: 0=q 1=k 2=qk_raw 3=aw 4=v
__device__ unsigned g_mx[5];

__global__ void init_kernel() {
    if (threadIdx.x < 5) g_mx[threadIdx.x] = 0u;
}
__global__ void spacer_kernel() {}   // shifts attn to launch idx 5 for ncu -s 5

// ---------------- helpers ----------------
__device__ __forceinline__ void mma_bf16(float (&c)[4], const uint32_t (&a)[4],
                                         uint32_t b0, uint32_t b1) {
    asm volatile(
        "mma.sync.aligned.m16n8k16.row.col.f32.bf16.bf16.f32 "
        "{%0,%1,%2,%3}, {%4,%5,%6,%7}, {%8,%9}, {%0,%1,%2,%3};"
        : "+f"(c[0]), "+f"(c[1]), "+f"(c[2]), "+f"(c[3])
        : "r"(a[0]), "r"(a[1]), "r"(a[2]), "r"(a[3]), "r"(b0), "r"(b1));
}
__device__ __forceinline__ uint32_t packb(float lo, float hi) {
    uint32_t r;
    asm("cvt.rn.bf16x2.f32 %0, %1, %2;" : "=r"(r) : "f"(hi), "f"(lo));
    return r;
}
__device__ __forceinline__ uint32_t smem_u32(const void* p) {
    uint32_t a;
    asm("{ .reg .u64 t; cvta.to.shared.u64 t, %1; cvt.u32.u64 %0, t; }"
        : "=r"(a) : "l"(p));
    return a;
}
#define LDSM_X4(r0, r1, r2, r3, addr) \
    asm volatile("ldmatrix.sync.aligned.m8n8.x4.shared.b16 {%0,%1,%2,%3}, [%4];" \
                 : "=r"(r0), "=r"(r1), "=r"(r2), "=r"(r3) : "r"(addr))
#define LDSM_X4_T(r0, r1, r2, r3, addr) \
    asm volatile("ldmatrix.sync.aligned.m8n8.x4.trans.shared.b16 {%0,%1,%2,%3}, [%4];" \
                 : "=r"(r0), "=r"(r1), "=r"(r2), "=r"(r3) : "r"(addr))

// ---------------- fp32 -> bf16 hi/lo split conversion ----------------
__global__ __launch_bounds__(256) void convert_x(const float* __restrict__ X) {
    size_t i4 = ((size_t)blockIdx.x * 256 + threadIdx.x) * 4;
    float4 v = *(const float4*)(X + i4);
    float f[4] = {v.x, v.y, v.z, v.w};
    __nv_bfloat16 h[4], l[4];
#pragma unroll
    for (int j = 0; j < 4; j++) {
        h[j] = __float2bfloat16_rn(f[j]);
        l[j] = __float2bfloat16_rn(f[j] - __bfloat162float(h[j]));
    }
    *(__nv_bfloat162*)(g_xhi + i4 + 0) = __nv_bfloat162(h[0], h[1]);
    *(__nv_bfloat162*)(g_xhi + i4 + 2) = __nv_bfloat162(h[2], h[3]);
    *(__nv_bfloat162*)(g_xlo + i4 + 0) = __nv_bfloat162(l[0], l[1]);
    *(__nv_bfloat162*)(g_xlo + i4 + 2) = __nv_bfloat162(l[2], l[3]);
}

__global__ __launch_bounds__(256) void convert_w(
    const float* __restrict__ Wq, const float* __restrict__ Wk,
    const float* __restrict__ Wv) {
    const int z = blockIdx.z;
    const float* W = (z == 0) ? Wq : (z == 1) ? Wk : Wv;
    size_t base = (size_t)z * DMODEL * DMODEL;
    size_t i4 = ((size_t)blockIdx.x * 256 + threadIdx.x) * 4;
    float4 v = *(const float4*)(W + i4);
    float f[4] = {v.x, v.y, v.z, v.w};
    __nv_bfloat16 h[4], l[4];
#pragma unroll
    for (int j = 0; j < 4; j++) {
        h[j] = __float2bfloat16_rn(f[j]);
        l[j] = __float2bfloat16_rn(f[j] - __bfloat162float(h[j]));
    }
    *(__nv_bfloat162*)(g_whi + base + i4 + 0) = __nv_bfloat162(h[0], h[1]);
    *(__nv_bfloat162*)(g_whi + base + i4 + 2) = __nv_bfloat162(h[2], h[3]);
    *(__nv_bfloat162*)(g_wlo + base + i4 + 0) = __nv_bfloat162(l[0], l[1]);
    *(__nv_bfloat162*)(g_wlo + base + i4 + 2) = __nv_bfloat162(l[2], l[3]);
}

// ---------------- split-bf16 QKV GEMM via mma.sync + ldmatrix ----------------
#define GKC 32
#define GST 40                       // smem row stride (bf16), 80B
#define GMAT (128 * GST)
#define GSTAGE (4 * GMAT)            // Ah Al Bh Bl
#define GEMM_SMEM_BYTES (2 * GSTAGE * 2)

__global__ __launch_bounds__(256, 1) void qkv_gemm_mma(
    const float* __restrict__ bq, const float* __restrict__ bk,
    const float* __restrict__ bv)
{
    extern __shared__ __nv_bfloat16 sm[];
    __shared__ unsigned s_amax;

    const int tid = threadIdx.x;
    const int wid = tid >> 5;
    const int lane = tid & 31;
    const int g = lane >> 2;
    const int t = lane & 3;
    const int wm = wid & 1;           // 0..1 (64 rows)
    const int wn = wid >> 1;          // 0..3 (32 cols)

    const int z = blockIdx.z;
    const int m0 = blockIdx.y * 128;
    const int n0 = blockIdx.x * 128;

    const float* __restrict__ bias = (z == 0) ? bq : (z == 1) ? bk : bv;
    __nv_bfloat16* __restrict__ Ohi = (z == 0) ? g_qhi : (z == 1) ? g_khi : g_vhi;
    __nv_bfloat16* __restrict__ Olo = (z == 0) ? g_qlo : (z == 1) ? g_klo : g_vlo;
    const int mslot = (z == 0) ? 0 : (z == 1) ? 1 : 4;

    const __nv_bfloat16* __restrict__ Ah = g_xhi + (size_t)m0 * DMODEL;
    const __nv_bfloat16* __restrict__ Al = g_xlo + (size_t)m0 * DMODEL;
    const __nv_bfloat16* __restrict__ Bh = g_whi + (size_t)z * DMODEL * DMODEL + (size_t)n0 * DMODEL;
    const __nv_bfloat16* __restrict__ Bl = g_wlo + (size_t)z * DMODEL * DMODEL + (size_t)n0 * DMODEL;

    if (tid == 0) s_amax = 0u;

    const uint32_t sbase = smem_u32(sm);
    // ldmatrix per-lane offsets
    const int a_lrow = lane & 15;
    const int a_lcol = ((lane >> 4) & 1) * 8;
    const int b_lrow = (lane & 7) + (lane >> 4) * 8;
    const int b_lcol = ((lane >> 3) & 1) * 8;

    float c[4][4][4];
#pragma unroll
    for (int mt = 0; mt < 4; mt++)
#pragma unroll
        for (int nt = 0; nt < 4; nt++)
#pragma unroll
            for (int r = 0; r < 4; r++) c[mt][nt][r] = 0.f;

    uint4 ld[8];
    {
#pragma unroll
        for (int i = 0; i < 2; i++) {
            const int u = tid + i * 256;
            const int row = u >> 2, cu = u & 3;
            const size_t off = (size_t)row * DMODEL + cu * 8;
            ld[i * 4 + 0] = *(const uint4*)(Ah + off);
            ld[i * 4 + 1] = *(const uint4*)(Al + off);
            ld[i * 4 + 2] = *(const uint4*)(Bh + off);
            ld[i * 4 + 3] = *(const uint4*)(Bl + off);
        }
    }
#pragma unroll
    for (int i = 0; i < 2; i++) {
        const int u = tid + i * 256;
        const int row = u >> 2, cu = u & 3;
        const int so = row * GST + cu * 8;
        *(uint4*)(sm + 0 * GMAT + so) = ld[i * 4 + 0];
        *(uint4*)(sm + 1 * GMAT + so) = ld[i * 4 + 1];
        *(uint4*)(sm + 2 * GMAT + so) = ld[i * 4 + 2];
        *(uint4*)(sm + 3 * GMAT + so) = ld[i * 4 + 3];
    }
    __syncthreads();

    const int NCH = DMODEL / GKC;     // 32
    for (int ch = 0; ch < NCH; ch++) {
        if (ch + 1 < NCH) {
            const int k0 = (ch + 1) * GKC;
#pragma unroll
            for (int i = 0; i < 2; i++) {
                const int u = tid + i * 256;
                const int row = u >> 2, cu = u & 3;
                const size_t off = (size_t)row * DMODEL + k0 + cu * 8;
                ld[i * 4 + 0] = *(const uint4*)(Ah + off);
                ld[i * 4 + 1] = *(const uint4*)(Al + off);
                ld[i * 4 + 2] = *(const uint4*)(Bh + off);
                ld[i * 4 + 3] = *(const uint4*)(Bl + off);
            }
        }
        const uint32_t st_off = (uint32_t)(ch & 1) * (GSTAGE * 2);
        const uint32_t bAh = sbase + st_off;
        const uint32_t bAl = bAh + GMAT * 2;
        const uint32_t bBh = bAl + GMAT * 2;
        const uint32_t bBl = bBh + GMAT * 2;
#pragma unroll
        for (int ks = 0; ks < 2; ks++) {
            const int kc = ks * 16;
            uint32_t ah[4][4], al[4][4];
#pragma unroll
            for (int mt = 0; mt < 4; mt++) {
                const uint32_t off =
                    (uint32_t)(((wm * 64 + mt * 16 + a_lrow) * GST + kc + a_lcol) * 2);
                LDSM_X4(ah[mt][0], ah[mt][1], ah[mt][2], ah[mt][3], bAh + off);
                LDSM_X4(al[mt][0], al[mt][1], al[mt][2], al[mt][3], bAl + off);
            }
            uint32_t bhf[4][2], blf[4][2];
#pragma unroll
            for (int ntp = 0; ntp < 2; ntp++) {
                const uint32_t off =
                    (uint32_t)(((wn * 32 + ntp * 16 + b_lrow) * GST + kc + b_lcol) * 2);
                LDSM_X4(bhf[2 * ntp][0], bhf[2 * ntp][1],
                        bhf[2 * ntp + 1][0], bhf[2 * ntp + 1][1], bBh + off);
                LDSM_X4(blf[2 * ntp][0], blf[2 * ntp][1],
                        blf[2 * ntp + 1][0], blf[2 * ntp + 1][1], bBl + off);
            }
#pragma unroll
            for (int mt = 0; mt < 4; mt++)
#pragma unroll
                for (int nt = 0; nt < 4; nt++) {
                    mma_bf16(c[mt][nt], ah[mt], bhf[nt][0], bhf[nt][1]);
                    mma_bf16(c[mt][nt], ah[mt], blf[nt][0], blf[nt][1]);
                    mma_bf16(c[mt][nt], al[mt], bhf[nt][0], bhf[nt][1]);
                }
        }
        if (ch + 1 < NCH) {
            __syncthreads();
            const int st = (ch + 1) & 1;
#pragma unroll
            for (int i = 0; i < 2; i++) {
                const int u = tid + i * 256;
                const int row = u >> 2, cu = u & 3;
                const int so = st * GSTAGE + row * GST + cu * 8;
                *(uint4*)(sm + so + 0 * GMAT) = ld[i * 4 + 0];
                *(uint4*)(sm + so + 1 * GMAT) = ld[i * 4 + 1];
                *(uint4*)(sm + so + 2 * GMAT) = ld[i * 4 + 2];
                *(uint4*)(sm + so + 3 * GMAT) = ld[i * 4 + 3];
            }
            __syncthreads();
        }
    }

    // epilogue: bias, absmax, split -> bf16 hi/lo, layout [BH][S][64]
    float lmax = 0.f;
#pragma unroll
    for (int nt = 0; nt < 4; nt++) {
        const int n = n0 + wn * 32 + nt * 8 + 2 * t;
        const float bn0 = bias[n], bn1 = bias[n + 1];
        const int h = n >> 6, d = n & 63;
#pragma unroll
        for (int mt = 0; mt < 4; mt++) {
            const int mr0 = m0 + wm * 64 + mt * 16 + g;
            const int mr1 = mr0 + 8;
            float v0 = c[mt][nt][0] + bn0;
            float v1 = c[mt][nt][1] + bn1;
            float v2 = c[mt][nt][2] + bn0;
            float v3 = c[mt][nt][3] + bn1;
            lmax = fmaxf(lmax, fmaxf(fmaxf(fabsf(v0), fabsf(v1)),
                                     fmaxf(fabsf(v2), fabsf(v3))));
            const int bb0 = mr0 >> 11, s0 = mr0 & 2047;
            const int bb1 = mr1 >> 11, s1 = mr1 & 2047;
            const size_t o0 = (((size_t)(bb0 * HEADS + h)) * SEQ + s0) * HDIM + d;
            const size_t o1 = (((size_t)(bb1 * HEADS + h)) * SEQ + s1) * HDIM + d;
            uint32_t h0 = packb(v0, v1), h1 = packb(v2, v3);
            __nv_bfloat162 hb0 = *(__nv_bfloat162*)&h0;
            __nv_bfloat162 hb1 = *(__nv_bfloat162*)&h1;
            uint32_t l0 = packb(v0 - __bfloat162float(hb0.x), v1 - __bfloat162float(hb0.y));
            uint32_t l1 = packb(v2 - __bfloat162float(hb1.x), v3 - __bfloat162float(hb1.y));
            *(uint32_t*)(Ohi + o0) = h0;
            *(uint32_t*)(Ohi + o1) = h1;
            *(uint32_t*)(Olo + o0) = l0;
            *(uint32_t*)(Olo + o1) = l1;
        }
    }
    atomicMax(&s_amax, __float_as_uint(lmax));
    __syncthreads();
    if (tid == 0) atomicMax(&g_mx[mslot], s_amax);
}

// ---------------- warp-MMA flash attention (split-bf16 + ldmatrix) ----------------
#define KST 72   // K/V smem row stride (bf16), 144B

__global__ __launch_bounds__(256, 1) void attn_mma(float* __restrict__ out)
{
    __shared__ __align__(16) __nv_bfloat16 kh[64 * KST], kl[64 * KST];
    __shared__ __align__(16) __nv_bfloat16 vh[64 * KST], vl[64 * KST];
    __shared__ unsigned s_raw, s_aw;

    const int tid = threadIdx.x;
    const int wid = tid >> 5;
    const int lane = tid & 31;
    const int g = lane >> 2;
    const int t = lane & 3;

    const int bh = blockIdx.y;
    const int b = bh >> 4, h = bh & 15;
    const int q0 = blockIdx.x * 128;

    if (tid == 0) { s_raw = 0u; s_aw = 0u; }

    const uint32_t kh_b = smem_u32(kh), kl_b = smem_u32(kl);
    const uint32_t vh_b = smem_u32(vh), vl_b = smem_u32(vl);
    // K (non-trans) lane offsets
    const int b_lrow = (lane & 7) + (lane >> 4) * 8;
    const int b_lcol = ((lane >> 3) & 1) * 8;
    // V (trans) lane offsets
    const int v_lrow = (lane & 7) + ((lane >> 3) & 1) * 8;
    const int v_lcol = (lane >> 4) * 8;

    // Q fragments (hi/lo), loaded once from global
    const size_t qbase = ((size_t)bh * SEQ + q0 + wid * 16) * HDIM;
    const __nv_bfloat16* Qh = g_qhi + qbase;
    const __nv_bfloat16* Ql = g_qlo + qbase;
    uint32_t qh[4][4], ql[4][4];
#pragma unroll
    for (int kk = 0; kk < 4; kk++) {
        const int c0 = kk * 16 + 2 * t;
        qh[kk][0] = *(const uint32_t*)(Qh + g * HDIM + c0);
        qh[kk][1] = *(const uint32_t*)(Qh + (g + 8) * HDIM + c0);
        qh[kk][2] = *(const uint32_t*)(Qh + g * HDIM + c0 + 8);
        qh[kk][3] = *(const uint32_t*)(Qh + (g + 8) * HDIM + c0 + 8);
        ql[kk][0] = *(const uint32_t*)(Ql + g * HDIM + c0);
        ql[kk][1] = *(const uint32_t*)(Ql + (g + 8) * HDIM + c0);
        ql[kk][2] = *(const uint32_t*)(Ql + g * HDIM + c0 + 8);
        ql[kk][3] = *(const uint32_t*)(Ql + (g + 8) * HDIM + c0 + 8);
    }

    const __nv_bfloat16* Kh = g_khi + (size_t)bh * SEQ * HDIM;
    const __nv_bfloat16* Kl = g_klo + (size_t)bh * SEQ * HDIM;
    const __nv_bfloat16* Vh = g_vhi + (size_t)bh * SEQ * HDIM;
    const __nv_bfloat16* Vl = g_vlo + (size_t)bh * SEQ * HDIM;

    float o[8][4];
#pragma unroll
    for (int j = 0; j < 8; j++)
#pragma unroll
        for (int r = 0; r < 4; r++) o[j][r] = 0.f;
    float m0 = -1e30f, m1 = -1e30f, l0 = 0.f, l1 = 0.f, raw = 0.f;

    for (int kv0 = 0; kv0 < SEQ; kv0 += 64) {
        __syncthreads();
#pragma unroll
        for (int i = 0; i < 2; i++) {
            const int u = tid + i * 256;
            const int row = u >> 3, du = u & 7;
            const size_t go = (size_t)(kv0 + row) * HDIM + du * 8;
            const int so = row * KST + du * 8;
            *(uint4*)(kh + so) = *(const uint4*)(Kh + go);
            *(uint4*)(kl + so) = *(const uint4*)(Kl + go);
            *(uint4*)(vh + so) = *(const uint4*)(Vh + go);
            *(uint4*)(vl + so) = *(const uint4*)(Vl + go);
        }
        __syncthreads();

        // S = Q K^T (split, 3 passes), K fragments via ldmatrix.x4
        float s[8][4];
#pragma unroll
        for (int j = 0; j < 8; j++)
#pragma unroll
            for (int r = 0; r < 4; r++) s[j][r] = 0.f;
#pragma unroll
        for (int kk = 0; kk < 4; kk++) {
            uint32_t kbh[8][2], kbl[8][2];
#pragma unroll
            for (int jp = 0; jp < 4; jp++) {
                const uint32_t off =
                    (uint32_t)(((jp * 16 + b_lrow) * KST + kk * 16 + b_lcol) * 2);
                LDSM_X4(kbh[2 * jp][0], kbh[2 * jp][1],
                        kbh[2 * jp + 1][0], kbh[2 * jp + 1][1], kh_b + off);
                LDSM_X4(kbl[2 * jp][0], kbl[2 * jp][1],
                        kbl[2 * jp + 1][0], kbl[2 * jp + 1][1], kl_b + off);
            }
#pragma unroll
            for (int j = 0; j < 8; j++) {
                mma_bf16(s[j], qh[kk], kbh[j][0], kbh[j][1]);
                mma_bf16(s[j], qh[kk], kbl[j][0], kbl[j][1]);
                mma_bf16(s[j], ql[kk], kbh[j][0], kbh[j][1]);
            }
        }

        // raw absmax (pre-scale), scale, online softmax
        float rm0 = -1e30f, rm1 = -1e30f;
#pragma unroll
        for (int j = 0; j < 8; j++) {
#pragma unroll
            for (int r = 0; r < 4; r++) {
                raw = fmaxf(raw, fabsf(s[j][r]));
                s[j][r] *= 0.125f;
            }
            rm0 = fmaxf(rm0, fmaxf(s[j][0], s[j][1]));
            rm1 = fmaxf(rm1, fmaxf(s[j][2], s[j][3]));
        }
        rm0 = fmaxf(rm0, __shfl_xor_sync(0xffffffffu, rm0, 1));
        rm0 = fmaxf(rm0, __shfl_xor_sync(0xffffffffu, rm0, 2));
        rm1 = fmaxf(rm1, __shfl_xor_sync(0xffffffffu, rm1, 1));
        rm1 = fmaxf(rm1, __shfl_xor_sync(0xffffffffu, rm1, 2));
        const float mn0 = fmaxf(m0, rm0), mn1 = fmaxf(m1, rm1);
        const float f0 = __expf(m0 - mn0), f1 = __expf(m1 - mn1);
        float ps0 = 0.f, ps1 = 0.f;
#pragma unroll
        for (int j = 0; j < 8; j++) {
            s[j][0] = __expf(s[j][0] - mn0);
            s[j][1] = __expf(s[j][1] - mn0);
            s[j][2] = __expf(s[j][2] - mn1);
            s[j][3] = __expf(s[j][3] - mn1);
            ps0 += s[j][0] + s[j][1];
            ps1 += s[j][2] + s[j][3];
        }
        ps0 += __shfl_xor_sync(0xffffffffu, ps0, 1);
        ps0 += __shfl_xor_sync(0xffffffffu, ps0, 2);
        ps1 += __shfl_xor_sync(0xffffffffu, ps1, 1);
        ps1 += __shfl_xor_sync(0xffffffffu, ps1, 2);
        l0 = l0 * f0 + ps0;
        l1 = l1 * f1 + ps1;
        m0 = mn0; m1 = mn1;
#pragma unroll
        for (int j = 0; j < 8; j++) {
            o[j][0] *= f0; o[j][1] *= f0;
            o[j][2] *= f1; o[j][3] *= f1;
        }

        // P -> split bf16 fragments
        uint32_t ph[8][2], pl[8][2];
#pragma unroll
        for (int j = 0; j < 8; j++) {
            uint32_t p0 = packb(s[j][0], s[j][1]);
            uint32_t p1 = packb(s[j][2], s[j][3]);
            __nv_bfloat162 b0 = *(__nv_bfloat162*)&p0;
            __nv_bfloat162 b1 = *(__nv_bfloat162*)&p1;
            ph[j][0] = p0; ph[j][1] = p1;
            pl[j][0] = packb(s[j][0] - __bfloat162float(b0.x),
                             s[j][1] - __bfloat162float(b0.y));
            pl[j][1] = packb(s[j][2] - __bfloat162float(b1.x),
                             s[j][3] - __bfloat162float(b1.y));
        }

        // O += P V (split, 3 passes); V fragments via ldmatrix.x4.trans
#pragma unroll
        for (int kk = 0; kk < 4; kk++) {
            uint32_t pah[4] = {ph[2 * kk][0], ph[2 * kk][1],
                               ph[2 * kk + 1][0], ph[2 * kk + 1][1]};
            uint32_t pal[4] = {pl[2 * kk][0], pl[2 * kk][1],
                               pl[2 * kk + 1][0], pl[2 * kk + 1][1]};
            uint32_t vbh[8][2], vbl[8][2];
#pragma unroll
            for (int jp = 0; jp < 4; jp++) {
                const uint32_t off =
                    (uint32_t)(((kk * 16 + v_lrow) * KST + jp * 16 + v_lcol) * 2);
                LDSM_X4_T(vbh[2 * jp][0], vbh[2 * jp][1],
                          vbh[2 * jp + 1][0], vbh[2 * jp + 1][1], vh_b + off);
                LDSM_X4_T(vbl[2 * jp][0], vbl[2 * jp][1],
                          vbl[2 * jp + 1][0], vbl[2 * jp + 1][1], vl_b + off);
            }
#pragma unroll
            for (int j = 0; j < 8; j++) {
                mma_bf16(o[j], pah, vbh[j][0], vbh[j][1]);
                mma_bf16(o[j], pah, vbl[j][0], vbl[j][1]);
                mma_bf16(o[j], pal, vbh[j][0], vbh[j][1]);
            }
        }
    }

    // epilogue
    const float i0 = 1.f / l0, i1 = 1.f / l1;
    const int r0g = q0 + wid * 16 + g;
    const int r1g = r0g + 8;
    const size_t ob0 = ((size_t)b * SEQ + r0g) * DMODEL + h * HDIM;
    const size_t ob1 = ((size_t)b * SEQ + r1g) * DMODEL + h * HDIM;
#pragma unroll
    for (int j = 0; j < 8; j++) {
        const int d = 8 * j + 2 * t;
        float2 w0 = {o[j][0] * i0, o[j][1] * i0};
        float2 w1 = {o[j][2] * i1, o[j][3] * i1};
        *(float2*)(out + ob0 + d) = w0;
        *(float2*)(out + ob1 + d) = w1;
    }
    atomicMax(&s_raw, __float_as_uint(raw));
    atomicMax(&s_aw, __float_as_uint(fmaxf(i0, i1)));
    __syncthreads();
    if (tid == 0) {
        atomicMax(&g_mx[2], s_raw);
        atomicMax(&g_mx[3], s_aw);
    }
}

// ---------------- finalize scalars ----------------
__global__ void finalize_kernel(float* __restrict__ out, int base)
{
    if (threadIdx.x == 0) {
        const float qm  = __uint_as_float(g_mx[0]);
        const float km  = __uint_as_float(g_mx[1]);
        const float qkm = __uint_as_float(g_mx[2]);
        const float awm = __uint_as_float(g_mx[3]);
        const float vm  = __uint_as_float(g_mx[4]);
        out[base + 0] = qm;
        out[base + 1] = km;
        out[base + 2] = qkm;
        out[base + 3] = awm;
        out[base + 4] = vm;
        out[base + 5] = awm;  // v_out_max (faithful source bug)
    }
}

// ---------------- launch ----------------
extern "C" void kernel_launch(void* const* d_in, const int* in_sizes, int n_in,
                              void* d_out, int out_size)
{
    const float* X  = (const float*)d_in[0];
    const float* Wq = (const float*)d_in[1];
    const float* bq = (const float*)d_in[2];
    const float* Wk = (const float*)d_in[3];
    const float* bk = (const float*)d_in[4];
    const float* Wv = (const float*)d_in[5];
    const float* bv = (const float*)d_in[6];
    float* out = (float*)d_out;

    cudaFuncSetAttribute(qkv_gemm_mma,
                         cudaFuncAttributeMaxDynamicSharedMemorySize,
                         GEMM_SMEM_BYTES);

    init_kernel<<<1, 32>>>();                                           // 0
    convert_x<<<MROWS * DMODEL / 4 / 256, 256>>>(X);                    // 1
    convert_w<<<dim3(DMODEL * DMODEL / 4 / 256, 1, 3), 256>>>(Wq, Wk, Wv); // 2
    qkv_gemm_mma<<<dim3(DMODEL / 128, MROWS / 128, 3), 256,
                   GEMM_SMEM_BYTES>>>(bq, bk, bv);                      // 3
    spacer_kernel<<<1, 32>>>();                                         // 4
    attn_mma<<<dim3(SEQ / 128, BATCH * HEADS), 256>>>(out);             // 5
    finalize_kernel<<<1, 32>>>(out, out_size - 6);                      // 6
}

// round 5
// speedup vs baseline: 3.6087x; 1.0610x over previous
#include <cuda_runtime.h>
#include <cuda_bf16.h>
#include <cstdint>

// Problem constants: B=2, S=2048, DM=1024, H=16, DH=64
#define BATCH 2
#define SEQ 2048
#define DMODEL 1024
#define HEADS 16
#define HDIM 64
#define MROWS (BATCH*SEQ)                 // 4096
#define QKV_ELEMS (BATCH*HEADS*SEQ*HDIM)  // 4,194,304

// ---------------- device scratch ----------------
__device__ __nv_bfloat16 g_xhi[MROWS * DMODEL];
__device__ __nv_bfloat16 g_xlo[MROWS * DMODEL];
__device__ __nv_bfloat16 g_whi[3 * DMODEL * DMODEL];
__device__ __nv_bfloat16 g_wlo[3 * DMODEL * DMODEL];
__device__ __nv_bfloat16 g_qhi[QKV_ELEMS], g_qlo[QKV_ELEMS];
__device__ __nv_bfloat16 g_khi[QKV_ELEMS], g_klo[QKV_ELEMS];
__device__ __nv_bfloat16 g_vhi[QKV_ELEMS], g_vlo[QKV_ELEMS];
// absmax slots: 0=q 1=k 2=qk_raw 3=aw 4=v
__device__ unsigned g_mx[5];

__global__ void init_kernel() {
    if (threadIdx.x < 5) g_mx[threadIdx.x] = 0u;
}
__global__ void spacer_kernel() {}   // shifts attn to launch idx 5 for ncu -s 5

// ---------------- helpers ----------------
__device__ __forceinline__ void mma_bf16(float (&c)[4], const uint32_t (&a)[4],
                                         uint32_t b0, uint32_t b1) {
    asm volatile(
        "mma.sync.aligned.m16n8k16.row.col.f32.bf16.bf16.f32 "
        "{%0,%1,%2,%3}, {%4,%5,%6,%7}, {%8,%9}, {%0,%1,%2,%3};"
        : "+f"(c[0]), "+f"(c[1]), "+f"(c[2]), "+f"(c[3])
        : "r"(a[0]), "r"(a[1]), "r"(a[2]), "r"(a[3]), "r"(b0), "r"(b1));
}
__device__ __forceinline__ uint32_t packb(float lo, float hi) {
    uint32_t r;
    asm("cvt.rn.bf16x2.f32 %0, %1, %2;" : "=r"(r) : "f"(hi), "f"(lo));
    return r;
}
__device__ __forceinline__ uint32_t smem_u32(const void* p) {
    uint32_t a;
    asm("{ .reg .u64 t; cvta.to.shared.u64 t, %1; cvt.u32.u64 %0, t; }"
        : "=r"(a) : "l"(p));
    return a;
}
#define LDSM_X4(r0, r1, r2, r3, addr) \
    asm volatile("ldmatrix.sync.aligned.m8n8.x4.shared.b16 {%0,%1,%2,%3}, [%4];" \
                 : "=r"(r0), "=r"(r1), "=r"(r2), "=r"(r3) : "r"(addr))
#define LDSM_X4_T(r0, r1, r2, r3, addr) \
    asm volatile("ldmatrix.sync.aligned.m8n8.x4.trans.shared.b16 {%0,%1,%2,%3}, [%4];" \
                 : "=r"(r0), "=r"(r1), "=r"(r2), "=r"(r3) : "r"(addr))
#define CP_ASYNC16(dst, src) \
    asm volatile("cp.async.cg.shared.global [%0], [%1], 16;" \
                 :: "r"(dst), "l"(src))
#define CP_COMMIT() asm volatile("cp.async.commit_group;" ::: "memory")
#define CP_WAIT1() asm volatile("cp.async.wait_group 1;" ::: "memory")

// ---------------- fp32 -> bf16 hi/lo split conversion ----------------
__global__ __launch_bounds__(256) void convert_x(const float* __restrict__ X) {
    size_t i4 = ((size_t)blockIdx.x * 256 + threadIdx.x) * 4;
    float4 v = *(const float4*)(X + i4);
    float f[4] = {v.x, v.y, v.z, v.w};
    __nv_bfloat16 h[4], l[4];
#pragma unroll
    for (int j = 0; j < 4; j++) {
        h[j] = __float2bfloat16_rn(f[j]);
        l[j] = __float2bfloat16_rn(f[j] - __bfloat162float(h[j]));
    }
    *(__nv_bfloat162*)(g_xhi + i4 + 0) = __nv_bfloat162(h[0], h[1]);
    *(__nv_bfloat162*)(g_xhi + i4 + 2) = __nv_bfloat162(h[2], h[3]);
    *(__nv_bfloat162*)(g_xlo + i4 + 0) = __nv_bfloat162(l[0], l[1]);
    *(__nv_bfloat162*)(g_xlo + i4 + 2) = __nv_bfloat162(l[2], l[3]);
}

__global__ __launch_bounds__(256) void convert_w(
    const float* __restrict__ Wq, const float* __restrict__ Wk,
    const float* __restrict__ Wv) {
    const int z = blockIdx.z;
    const float* W = (z == 0) ? Wq : (z == 1) ? Wk : Wv;
    size_t base = (size_t)z * DMODEL * DMODEL;
    size_t i4 = ((size_t)blockIdx.x * 256 + threadIdx.x) * 4;
    float4 v = *(const float4*)(W + i4);
    float f[4] = {v.x, v.y, v.z, v.w};
    __nv_bfloat16 h[4], l[4];
#pragma unroll
    for (int j = 0; j < 4; j++) {
        h[j] = __float2bfloat16_rn(f[j]);
        l[j] = __float2bfloat16_rn(f[j] - __bfloat162float(h[j]));
    }
    *(__nv_bfloat162*)(g_whi + base + i4 + 0) = __nv_bfloat162(h[0], h[1]);
    *(__nv_bfloat162*)(g_whi + base + i4 + 2) = __nv_bfloat162(h[2], h[3]);
    *(__nv_bfloat162*)(g_wlo + base + i4 + 0) = __nv_bfloat162(l[0], l[1]);
    *(__nv_bfloat162*)(g_wlo + base + i4 + 2) = __nv_bfloat162(l[2], l[3]);
}

// ---------------- split-bf16 QKV GEMM: mma.sync + ldmatrix + cp.async x3 ----
#define GKC 32
#define GST 40                           // smem row stride (bf16), 80B
#define GTILE_B (128 * GST * 2)          // 10240 B per tile
#define GSTG_B (4 * GTILE_B)             // Ah Al Bh Bl = 40960 B per stage
#define GEMM_SMEM_BYTES (3 * GSTG_B)     // 122880

__global__ __launch_bounds__(256, 1) void qkv_gemm_mma(
    const float* __restrict__ bq, const float* __restrict__ bk,
    const float* __restrict__ bv)
{
    extern __shared__ __nv_bfloat16 sm[];
    __shared__ unsigned s_amax;

    const int tid = threadIdx.x;
    const int wid = tid >> 5;
    const int lane = tid & 31;
    const int g = lane >> 2;
    const int t = lane & 3;
    const int wm = wid & 1;           // 0..1 (64 rows)
    const int wn = wid >> 1;          // 0..3 (32 cols)

    const int z = blockIdx.z;
    const int m0 = blockIdx.y * 128;
    const int n0 = blockIdx.x * 128;

    const float* __restrict__ bias = (z == 0) ? bq : (z == 1) ? bk : bv;
    __nv_bfloat16* __restrict__ Ohi = (z == 0) ? g_qhi : (z == 1) ? g_khi : g_vhi;
    __nv_bfloat16* __restrict__ Olo = (z == 0) ? g_qlo : (z == 1) ? g_klo : g_vlo;
    const int mslot = (z == 0) ? 0 : (z == 1) ? 1 : 4;

    const __nv_bfloat16* __restrict__ Ah = g_xhi + (size_t)m0 * DMODEL;
    const __nv_bfloat16* __restrict__ Al = g_xlo + (size_t)m0 * DMODEL;
    const __nv_bfloat16* __restrict__ Bh = g_whi + (size_t)z * DMODEL * DMODEL + (size_t)n0 * DMODEL;
    const __nv_bfloat16* __restrict__ Bl = g_wlo + (size_t)z * DMODEL * DMODEL + (size_t)n0 * DMODEL;

    if (tid == 0) s_amax = 0u;

    const uint32_t sbase = smem_u32(sm);
    // per-thread load coords: 8 x 16B cp.async per stage
    // u = tid + i*256, row = u>>2 (0..127), cu = u&3 (16B unit in 32-col row)
    // ldmatrix per-lane offsets
    const int a_lrow = lane & 15;
    const int a_lcol = ((lane >> 4) & 1) * 8;
    const int b_lrow = (lane & 7) + (lane >> 4) * 8;
    const int b_lcol = ((lane >> 3) & 1) * 8;

    float c[4][4][4];
#pragma unroll
    for (int mt = 0; mt < 4; mt++)
#pragma unroll
        for (int nt = 0; nt < 4; nt++)
#pragma unroll
            for (int r = 0; r < 4; r++) c[mt][nt][r] = 0.f;

    const int NCH = DMODEL / GKC;     // 32

    // stage loader: chunk ch -> stage st
#define GEMM_LOAD_STAGE(ch, st) do {                                          \
        const int k0 = (ch) * GKC;                                            \
        const uint32_t stb = sbase + (uint32_t)(st) * GSTG_B;                 \
        _Pragma("unroll")                                                     \
        for (int i = 0; i < 2; i++) {                                         \
            const int u = tid + i * 256;                                      \
            const int row = u >> 2, cu = u & 3;                               \
            const size_t go = (size_t)row * DMODEL + k0 + cu * 8;             \
            const uint32_t so = stb + (uint32_t)(row * GST + cu * 8) * 2;     \
            CP_ASYNC16(so + 0 * GTILE_B, (const void*)(Ah + go));             \
            CP_ASYNC16(so + 1 * GTILE_B, (const void*)(Al + go));             \
            CP_ASYNC16(so + 2 * GTILE_B, (const void*)(Bh + go));             \
            CP_ASYNC16(so + 3 * GTILE_B, (const void*)(Bl + go));             \
        }                                                                     \
    } while (0)

    GEMM_LOAD_STAGE(0, 0); CP_COMMIT();
    GEMM_LOAD_STAGE(1, 1); CP_COMMIT();

    int st = 0;
    for (int ch = 0; ch < NCH; ch++) {
        CP_WAIT1();
        __syncthreads();
        if (ch + 2 < NCH) {
            const int st2 = (st + 2 >= 3) ? st - 1 : st + 2;
            GEMM_LOAD_STAGE(ch + 2, st2);
        }
        CP_COMMIT();

        const uint32_t bAh = sbase + (uint32_t)st * GSTG_B;
        const uint32_t bAl = bAh + GTILE_B;
        const uint32_t bBh = bAl + GTILE_B;
        const uint32_t bBl = bBh + GTILE_B;
#pragma unroll
        for (int ks = 0; ks < 2; ks++) {
            const int kc = ks * 16;
            uint32_t ah[4][4], al[4][4];
#pragma unroll
            for (int mt = 0; mt < 4; mt++) {
                const uint32_t off =
                    (uint32_t)(((wm * 64 + mt * 16 + a_lrow) * GST + kc + a_lcol) * 2);
                LDSM_X4(ah[mt][0], ah[mt][1], ah[mt][2], ah[mt][3], bAh + off);
                LDSM_X4(al[mt][0], al[mt][1], al[mt][2], al[mt][3], bAl + off);
            }
            uint32_t bhf[4][2], blf[4][2];
#pragma unroll
            for (int ntp = 0; ntp < 2; ntp++) {
                const uint32_t off =
                    (uint32_t)(((wn * 32 + ntp * 16 + b_lrow) * GST + kc + b_lcol) * 2);
                LDSM_X4(bhf[2 * ntp][0], bhf[2 * ntp][1],
                        bhf[2 * ntp + 1][0], bhf[2 * ntp + 1][1], bBh + off);
                LDSM_X4(blf[2 * ntp][0], blf[2 * ntp][1],
                        blf[2 * ntp + 1][0], blf[2 * ntp + 1][1], bBl + off);
            }
#pragma unroll
            for (int mt = 0; mt < 4; mt++)
#pragma unroll
                for (int nt = 0; nt < 4; nt++) {
                    mma_bf16(c[mt][nt], ah[mt], bhf[nt][0], bhf[nt][1]);
                    mma_bf16(c[mt][nt], ah[mt], blf[nt][0], blf[nt][1]);
                    mma_bf16(c[mt][nt], al[mt], bhf[nt][0], bhf[nt][1]);
                }
        }
        __syncthreads();
        st = (st + 1 >= 3) ? 0 : st + 1;
    }
#undef GEMM_LOAD_STAGE

    // epilogue: bias, absmax, split -> bf16 hi/lo, layout [BH][S][64]
    float lmax = 0.f;
#pragma unroll
    for (int nt = 0; nt < 4; nt++) {
        const int n = n0 + wn * 32 + nt * 8 + 2 * t;
        const float bn0 = bias[n], bn1 = bias[n + 1];
        const int h = n >> 6, d = n & 63;
#pragma unroll
        for (int mt = 0; mt < 4; mt++) {
            const int mr0 = m0 + wm * 64 + mt * 16 + g;
            const int mr1 = mr0 + 8;
            float v0 = c[mt][nt][0] + bn0;
            float v1 = c[mt][nt][1] + bn1;
            float v2 = c[mt][nt][2] + bn0;
            float v3 = c[mt][nt][3] + bn1;
            lmax = fmaxf(lmax, fmaxf(fmaxf(fabsf(v0), fabsf(v1)),
                                     fmaxf(fabsf(v2), fabsf(v3))));
            const int bb0 = mr0 >> 11, s0 = mr0 & 2047;
            const int bb1 = mr1 >> 11, s1 = mr1 & 2047;
            const size_t o0 = (((size_t)(bb0 * HEADS + h)) * SEQ + s0) * HDIM + d;
            const size_t o1 = (((size_t)(bb1 * HEADS + h)) * SEQ + s1) * HDIM + d;
            uint32_t h0 = packb(v0, v1), h1 = packb(v2, v3);
            __nv_bfloat162 hb0 = *(__nv_bfloat162*)&h0;
            __nv_bfloat162 hb1 = *(__nv_bfloat162*)&h1;
            uint32_t l0 = packb(v0 - __bfloat162float(hb0.x), v1 - __bfloat162float(hb0.y));
            uint32_t l1 = packb(v2 - __bfloat162float(hb1.x), v3 - __bfloat162float(hb1.y));
            *(uint32_t*)(Ohi + o0) = h0;
            *(uint32_t*)(Ohi + o1) = h1;
            *(uint32_t*)(Olo + o0) = l0;
            *(uint32_t*)(Olo + o1) = l1;
        }
    }
    atomicMax(&s_amax, __float_as_uint(lmax));
    __syncthreads();
    if (tid == 0) atomicMax(&g_mx[mslot], s_amax);
}

// ---------- warp-MMA flash attention: split-bf16 + ldmatrix + cp.async x3 ----
#define KST 72                            // K/V smem row stride (bf16), 144B
#define ATILE_B (64 * KST * 2)            // 9216 B per tile
#define ASTG_B (4 * ATILE_B)              // kh kl vh vl = 36864 B per stage
#define ATTN_SMEM_BYTES (3 * ASTG_B)      // 110592

__global__ __launch_bounds__(256, 1) void attn_mma(float* __restrict__ out)
{
    extern __shared__ __nv_bfloat16 asm_buf[];
    __shared__ unsigned s_raw, s_aw;

    const int tid = threadIdx.x;
    const int wid = tid >> 5;
    const int lane = tid & 31;
    const int g = lane >> 2;
    const int t = lane & 3;

    const int bh = blockIdx.y;
    const int b = bh >> 4, h = bh & 15;
    const int q0 = blockIdx.x * 128;

    if (tid == 0) { s_raw = 0u; s_aw = 0u; }

    const uint32_t sbase = smem_u32(asm_buf);
    // K (non-trans) lane offsets
    const int b_lrow = (lane & 7) + (lane >> 4) * 8;
    const int b_lcol = ((lane >> 3) & 1) * 8;
    // V (trans) lane offsets
    const int v_lrow = (lane & 7) + ((lane >> 3) & 1) * 8;
    const int v_lcol = (lane >> 4) * 8;

    // Q fragments (hi/lo), loaded once from global
    const size_t qbase = ((size_t)bh * SEQ + q0 + wid * 16) * HDIM;
    const __nv_bfloat16* Qh = g_qhi + qbase;
    const __nv_bfloat16* Ql = g_qlo + qbase;
    uint32_t qh[4][4], ql[4][4];
#pragma unroll
    for (int kk = 0; kk < 4; kk++) {
        const int c0 = kk * 16 + 2 * t;
        qh[kk][0] = *(const uint32_t*)(Qh + g * HDIM + c0);
        qh[kk][1] = *(const uint32_t*)(Qh + (g + 8) * HDIM + c0);
        qh[kk][2] = *(const uint32_t*)(Qh + g * HDIM + c0 + 8);
        qh[kk][3] = *(const uint32_t*)(Qh + (g + 8) * HDIM + c0 + 8);
        ql[kk][0] = *(const uint32_t*)(Ql + g * HDIM + c0);
        ql[kk][1] = *(const uint32_t*)(Ql + (g + 8) * HDIM + c0);
        ql[kk][2] = *(const uint32_t*)(Ql + g * HDIM + c0 + 8);
        ql[kk][3] = *(const uint32_t*)(Ql + (g + 8) * HDIM + c0 + 8);
    }

    const __nv_bfloat16* Kh = g_khi + (size_t)bh * SEQ * HDIM;
    const __nv_bfloat16* Kl = g_klo + (size_t)bh * SEQ * HDIM;
    const __nv_bfloat16* Vh = g_vhi + (size_t)bh * SEQ * HDIM;
    const __nv_bfloat16* Vl = g_vlo + (size_t)bh * SEQ * HDIM;

    float o[8][4];
#pragma unroll
    for (int j = 0; j < 8; j++)
#pragma unroll
        for (int r = 0; r < 4; r++) o[j][r] = 0.f;
    float m0 = -1e30f, m1 = -1e30f, l0 = 0.f, l1 = 0.f, raw = 0.f;

    const int NKV = SEQ / 64;  // 32

#define ATTN_LOAD_STAGE(kv, st) do {                                          \
        const int base_row = (kv) * 64;                                       \
        const uint32_t stb = sbase + (uint32_t)(st) * ASTG_B;                 \
        _Pragma("unroll")                                                     \
        for (int i = 0; i < 2; i++) {                                         \
            const int u = tid + i * 256;                                      \
            const int row = u >> 3, du = u & 7;                               \
            const size_t go = (size_t)(base_row + row) * HDIM + du * 8;       \
            const uint32_t so = stb + (uint32_t)(row * KST + du * 8) * 2;     \
            CP_ASYNC16(so + 0 * ATILE_B, (const void*)(Kh + go));             \
            CP_ASYNC16(so + 1 * ATILE_B, (const void*)(Kl + go));             \
            CP_ASYNC16(so + 2 * ATILE_B, (const void*)(Vh + go));             \
            CP_ASYNC16(so + 3 * ATILE_B, (const void*)(Vl + go));             \
        }                                                                     \
    } while (0)

    ATTN_LOAD_STAGE(0, 0); CP_COMMIT();
    ATTN_LOAD_STAGE(1, 1); CP_COMMIT();

    int st = 0;
    for (int kv = 0; kv < NKV; kv++) {
        CP_WAIT1();
        __syncthreads();
        if (kv + 2 < NKV) {
            const int st2 = (st + 2 >= 3) ? st - 1 : st + 2;
            ATTN_LOAD_STAGE(kv + 2, st2);
        }
        CP_COMMIT();

        const uint32_t kh_b = sbase + (uint32_t)st * ASTG_B;
        const uint32_t kl_b = kh_b + ATILE_B;
        const uint32_t vh_b = kl_b + ATILE_B;
        const uint32_t vl_b = vh_b + ATILE_B;

        // S = Q K^T (split, 3 passes), K fragments via ldmatrix.x4
        float s[8][4];
#pragma unroll
        for (int j = 0; j < 8; j++)
#pragma unroll
            for (int r = 0; r < 4; r++) s[j][r] = 0.f;
#pragma unroll
        for (int kk = 0; kk < 4; kk++) {
            uint32_t kbh[8][2], kbl[8][2];
#pragma unroll
            for (int jp = 0; jp < 4; jp++) {
                const uint32_t off =
                    (uint32_t)(((jp * 16 + b_lrow) * KST + kk * 16 + b_lcol) * 2);
                LDSM_X4(kbh[2 * jp][0], kbh[2 * jp][1],
                        kbh[2 * jp + 1][0], kbh[2 * jp + 1][1], kh_b + off);
                LDSM_X4(kbl[2 * jp][0], kbl[2 * jp][1],
                        kbl[2 * jp + 1][0], kbl[2 * jp + 1][1], kl_b + off);
            }
#pragma unroll
            for (int j = 0; j < 8; j++) {
                mma_bf16(s[j], qh[kk], kbh[j][0], kbh[j][1]);
                mma_bf16(s[j], qh[kk], kbl[j][0], kbl[j][1]);
                mma_bf16(s[j], ql[kk], kbh[j][0], kbh[j][1]);
            }
        }

        // raw absmax (pre-scale), scale, online softmax
        float rm0 = -1e30f, rm1 = -1e30f;
#pragma unroll
        for (int j = 0; j < 8; j++) {
#pragma unroll
            for (int r = 0; r < 4; r++) {
                raw = fmaxf(raw, fabsf(s[j][r]));
                s[j][r] *= 0.125f;
            }
            rm0 = fmaxf(rm0, fmaxf(s[j][0], s[j][1]));
            rm1 = fmaxf(rm1, fmaxf(s[j][2], s[j][3]));
        }
        rm0 = fmaxf(rm0, __shfl_xor_sync(0xffffffffu, rm0, 1));
        rm0 = fmaxf(rm0, __shfl_xor_sync(0xffffffffu, rm0, 2));
        rm1 = fmaxf(rm1, __shfl_xor_sync(0xffffffffu, rm1, 1));
        rm1 = fmaxf(rm1, __shfl_xor_sync(0xffffffffu, rm1, 2));
        const float mn0 = fmaxf(m0, rm0), mn1 = fmaxf(m1, rm1);
        const float f0 = __expf(m0 - mn0), f1 = __expf(m1 - mn1);
        float ps0 = 0.f, ps1 = 0.f;
#pragma unroll
        for (int j = 0; j < 8; j++) {
            s[j][0] = __expf(s[j][0] - mn0);
            s[j][1] = __expf(s[j][1] - mn0);
            s[j][2] = __expf(s[j][2] - mn1);
            s[j][3] = __expf(s[j][3] - mn1);
            ps0 += s[j][0] + s[j][1];
            ps1 += s[j][2] + s[j][3];
        }
        ps0 += __shfl_xor_sync(0xffffffffu, ps0, 1);
        ps0 += __shfl_xor_sync(0xffffffffu, ps0, 2);
        ps1 += __shfl_xor_sync(0xffffffffu, ps1, 1);
        ps1 += __shfl_xor_sync(0xffffffffu, ps1, 2);
        l0 = l0 * f0 + ps0;
        l1 = l1 * f1 + ps1;
        m0 = mn0; m1 = mn1;
#pragma unroll
        for (int j = 0; j < 8; j++) {
            o[j][0] *= f0; o[j][1] *= f0;
            o[j][2] *= f1; o[j][3] *= f1;
        }

        // P -> split bf16 fragments
        uint32_t ph[8][2], pl[8][2];
#pragma unroll
        for (int j = 0; j < 8; j++) {
            uint32_t p0 = packb(s[j][0], s[j][1]);
            uint32_t p1 = packb(s[j][2], s[j][3]);
            __nv_bfloat162 b0 = *(__nv_bfloat162*)&p0;
            __nv_bfloat162 b1 = *(__nv_bfloat162*)&p1;
            ph[j][0] = p0; ph[j][1] = p1;
            pl[j][0] = packb(s[j][0] - __bfloat162float(b0.x),
                             s[j][1] - __bfloat162float(b0.y));
            pl[j][1] = packb(s[j][2] - __bfloat162float(b1.x),
                             s[j][3] - __bfloat162float(b1.y));
        }

        // O += P V (split, 3 passes); V fragments via ldmatrix.x4.trans
#pragma unroll
        for (int kk = 0; kk < 4; kk++) {
            uint32_t pah[4] = {ph[2 * kk][0], ph[2 * kk][1],
                               ph[2 * kk + 1][0], ph[2 * kk + 1][1]};
            uint32_t pal[4] = {pl[2 * kk][0], pl[2 * kk][1],
                               pl[2 * kk + 1][0], pl[2 * kk + 1][1]};
            uint32_t vbh[8][2], vbl[8][2];
#pragma unroll
            for (int jp = 0; jp < 4; jp++) {
                const uint32_t off =
                    (uint32_t)(((kk * 16 + v_lrow) * KST + jp * 16 + v_lcol) * 2);
                LDSM_X4_T(vbh[2 * jp][0], vbh[2 * jp][1],
                          vbh[2 * jp + 1][0], vbh[2 * jp + 1][1], vh_b + off);
                LDSM_X4_T(vbl[2 * jp][0], vbl[2 * jp][1],
                          vbl[2 * jp + 1][0], vbl[2 * jp + 1][1], vl_b + off);
            }
#pragma unroll
            for (int j = 0; j < 8; j++) {
                mma_bf16(o[j], pah, vbh[j][0], vbh[j][1]);
                mma_bf16(o[j], pah, vbl[j][0], vbl[j][1]);
                mma_bf16(o[j], pal, vbh[j][0], vbh[j][1]);
            }
        }
        __syncthreads();
        st = (st + 1 >= 3) ? 0 : st + 1;
    }
#undef ATTN_LOAD_STAGE

    // epilogue
    const float i0 = 1.f / l0, i1 = 1.f / l1;
    const int r0g = q0 + wid * 16 + g;
    const int r1g = r0g + 8;
    const size_t ob0 = ((size_t)b * SEQ + r0g) * DMODEL + h * HDIM;
    const size_t ob1 = ((size_t)b * SEQ + r1g) * DMODEL + h * HDIM;
#pragma unroll
    for (int j = 0; j < 8; j++) {
        const int d = 8 * j + 2 * t;
        float2 w0 = {o[j][0] * i0, o[j][1] * i0};
        float2 w1 = {o[j][2] * i1, o[j][3] * i1};
        *(float2*)(out + ob0 + d) = w0;
        *(float2*)(out + ob1 + d) = w1;
    }
    atomicMax(&s_raw, __float_as_uint(raw));
    atomicMax(&s_aw, __float_as_uint(fmaxf(i0, i1)));
    __syncthreads();
    if (tid == 0) {
        atomicMax(&g_mx[2], s_raw);
        atomicMax(&g_mx[3], s_aw);
    }
}

// ---------------- finalize scalars ----------------
__global__ void finalize_kernel(float* __restrict__ out, int base)
{
    if (threadIdx.x == 0) {
        const float qm  = __uint_as_float(g_mx[0]);
        const float km  = __uint_as_float(g_mx[1]);
        const float qkm = __uint_as_float(g_mx[2]);
        const float awm = __uint_as_float(g_mx[3]);
        const float vm  = __uint_as_float(g_mx[4]);
        out[base + 0] = qm;
        out[base + 1] = km;
        out[base + 2] = qkm;
        out[base + 3] = awm;
        out[base + 4] = vm;
        out[base + 5] = awm;  // v_out_max (faithful source bug)
    }
}

// ---------------- launch ----------------
extern "C" void kernel_launch(void* const* d_in, const int* in_sizes, int n_in,
                              void* d_out, int out_size)
{
    const float* X  = (const float*)d_in[0];
    const float* Wq = (const float*)d_in[1];
    const float* bq = (const float*)d_in[2];
    const float* Wk = (const float*)d_in[3];
    const float* bk = (const float*)d_in[4];
    const float* Wv = (const float*)d_in[5];
    const float* bv = (const float*)d_in[6];
    float* out = (float*)d_out;

    cudaFuncSetAttribute(qkv_gemm_mma,
                         cudaFuncAttributeMaxDynamicSharedMemorySize,
                         GEMM_SMEM_BYTES);
    cudaFuncSetAttribute(attn_mma,
                         cudaFuncAttributeMaxDynamicSharedMemorySize,
                         ATTN_SMEM_BYTES);

    init_kernel<<<1, 32>>>();                                           // 0
    convert_x<<<MROWS * DMODEL / 4 / 256, 256>>>(X);                    // 1
    convert_w<<<dim3(DMODEL * DMODEL / 4 / 256, 1, 3), 256>>>(Wq, Wk, Wv); // 2
    qkv_gemm_mma<<<dim3(DMODEL / 128, MROWS / 128, 3), 256,
                   GEMM_SMEM_BYTES>>>(bq, bk, bv);                      // 3
    spacer_kernel<<<1, 32>>>();                                         // 4
    attn_mma<<<dim3(SEQ / 128, BATCH * HEADS), 256,
               ATTN_SMEM_BYTES>>>(out);                                 // 5
    finalize_kernel<<<1, 32>>>(out, out_size - 6);                      // 6
}

// round 6
// speedup vs baseline: 3.6109x; 1.0006x over previous
#include <cuda_runtime.h>
#include <cuda_bf16.h>
#include <cstdint>

// Problem constants: B=2, S=2048, DM=1024, H=16, DH=64
#define BATCH 2
#define SEQ 2048
#define DMODEL 1024
#define HEADS 16
#define HDIM 64
#define MROWS (BATCH*SEQ)                 // 4096
#define QKV_ELEMS (BATCH*HEADS*SEQ*HDIM)  // 4,194,304

// ---------------- device scratch ----------------
__device__ __nv_bfloat16 g_xhi[MROWS * DMODEL];
__device__ __nv_bfloat16 g_xlo[MROWS * DMODEL];
__device__ __nv_bfloat16 g_whi[3 * DMODEL * DMODEL];
__device__ __nv_bfloat16 g_wlo[3 * DMODEL * DMODEL];
__device__ __nv_bfloat16 g_qhi[QKV_ELEMS], g_qlo[QKV_ELEMS];
__device__ __nv_bfloat16 g_khi[QKV_ELEMS], g_klo[QKV_ELEMS];
__device__ __nv_bfloat16 g_vhi[QKV_ELEMS], g_vlo[QKV_ELEMS];
// absmax slots: 0=q 1=k 2=qk_raw 3=aw 4=v
__device__ unsigned g_mx[5];

__global__ void init_kernel() {
    if (threadIdx.x < 5) g_mx[threadIdx.x] = 0u;
}
__global__ void spacer_kernel() {}   // shifts attn to launch idx 5 for ncu -s 5

// ---------------- helpers ----------------
__device__ __forceinline__ void mma_bf16(float (&c)[4], const uint32_t (&a)[4],
                                         uint32_t b0, uint32_t b1) {
    asm volatile(
        "mma.sync.aligned.m16n8k16.row.col.f32.bf16.bf16.f32 "
        "{%0,%1,%2,%3}, {%4,%5,%6,%7}, {%8,%9}, {%0,%1,%2,%3};"
        : "+f"(c[0]), "+f"(c[1]), "+f"(c[2]), "+f"(c[3])
        : "r"(a[0]), "r"(a[1]), "r"(a[2]), "r"(a[3]), "r"(b0), "r"(b1));
}
__device__ __forceinline__ uint32_t packb(float lo, float hi) {
    uint32_t r;
    asm("cvt.rn.bf16x2.f32 %0, %1, %2;" : "=r"(r) : "f"(hi), "f"(lo));
    return r;
}
__device__ __forceinline__ uint32_t smem_u32(const void* p) {
    uint32_t a;
    asm("{ .reg .u64 t; cvta.to.shared.u64 t, %1; cvt.u32.u64 %0, t; }"
        : "=r"(a) : "l"(p));
    return a;
}
#define LDSM_X4(r0, r1, r2, r3, addr) \
    asm volatile("ldmatrix.sync.aligned.m8n8.x4.shared.b16 {%0,%1,%2,%3}, [%4];" \
                 : "=r"(r0), "=r"(r1), "=r"(r2), "=r"(r3) : "r"(addr))
#define LDSM_X4_T(r0, r1, r2, r3, addr) \
    asm volatile("ldmatrix.sync.aligned.m8n8.x4.trans.shared.b16 {%0,%1,%2,%3}, [%4];" \
                 : "=r"(r0), "=r"(r1), "=r"(r2), "=r"(r3) : "r"(addr))
#define CP_ASYNC16(dst, src) \
    asm volatile("cp.async.cg.shared.global [%0], [%1], 16;" \
                 :: "r"(dst), "l"(src))
#define CP_COMMIT() asm volatile("cp.async.commit_group;" ::: "memory")
#define CP_WAIT1() asm volatile("cp.async.wait_group 1;" ::: "memory")

// ---------------- fp32 -> bf16 hi/lo split conversion ----------------
__global__ __launch_bounds__(256) void convert_x(const float* __restrict__ X) {
    size_t i4 = ((size_t)blockIdx.x * 256 + threadIdx.x) * 4;
    float4 v = *(const float4*)(X + i4);
    float f[4] = {v.x, v.y, v.z, v.w};
    __nv_bfloat16 h[4], l[4];
#pragma unroll
    for (int j = 0; j < 4; j++) {
        h[j] = __float2bfloat16_rn(f[j]);
        l[j] = __float2bfloat16_rn(f[j] - __bfloat162float(h[j]));
    }
    *(__nv_bfloat162*)(g_xhi + i4 + 0) = __nv_bfloat162(h[0], h[1]);
    *(__nv_bfloat162*)(g_xhi + i4 + 2) = __nv_bfloat162(h[2], h[3]);
    *(__nv_bfloat162*)(g_xlo + i4 + 0) = __nv_bfloat162(l[0], l[1]);
    *(__nv_bfloat162*)(g_xlo + i4 + 2) = __nv_bfloat162(l[2], l[3]);
}

__global__ __launch_bounds__(256) void convert_w(
    const float* __restrict__ Wq, const float* __restrict__ Wk,
    const float* __restrict__ Wv) {
    const int z = blockIdx.z;
    const float* W = (z == 0) ? Wq : (z == 1) ? Wk : Wv;
    size_t base = (size_t)z * DMODEL * DMODEL;
    size_t i4 = ((size_t)blockIdx.x * 256 + threadIdx.x) * 4;
    float4 v = *(const float4*)(W + i4);
    float f[4] = {v.x, v.y, v.z, v.w};
    __nv_bfloat16 h[4], l[4];
#pragma unroll
    for (int j = 0; j < 4; j++) {
        h[j] = __float2bfloat16_rn(f[j]);
        l[j] = __float2bfloat16_rn(f[j] - __bfloat162float(h[j]));
    }
    *(__nv_bfloat162*)(g_whi + base + i4 + 0) = __nv_bfloat162(h[0], h[1]);
    *(__nv_bfloat162*)(g_whi + base + i4 + 2) = __nv_bfloat162(h[2], h[3]);
    *(__nv_bfloat162*)(g_wlo + base + i4 + 0) = __nv_bfloat162(l[0], l[1]);
    *(__nv_bfloat162*)(g_wlo + base + i4 + 2) = __nv_bfloat162(l[2], l[3]);
}

// ---------------- split-bf16 QKV GEMM: mma.sync + ldmatrix + cp.async x3 ----
#define GKC 32
#define GST 40                           // smem row stride (bf16), 80B
#define GTILE_B (128 * GST * 2)          // 10240 B per tile
#define GSTG_B (4 * GTILE_B)             // Ah Al Bh Bl = 40960 B per stage
#define GEMM_SMEM_BYTES (3 * GSTG_B)     // 122880

__global__ __launch_bounds__(256, 1) void qkv_gemm_mma(
    const float* __restrict__ bq, const float* __restrict__ bk,
    const float* __restrict__ bv)
{
    extern __shared__ __nv_bfloat16 sm[];
    __shared__ unsigned s_amax;

    const int tid = threadIdx.x;
    const int wid = tid >> 5;
    const int lane = tid & 31;
    const int g = lane >> 2;
    const int t = lane & 3;
    const int wm = wid & 1;           // 0..1 (64 rows)
    const int wn = wid >> 1;          // 0..3 (32 cols)

    const int z = blockIdx.z;
    const int m0 = blockIdx.y * 128;
    const int n0 = blockIdx.x * 128;

    const float* __restrict__ bias = (z == 0) ? bq : (z == 1) ? bk : bv;
    __nv_bfloat16* __restrict__ Ohi = (z == 0) ? g_qhi : (z == 1) ? g_khi : g_vhi;
    __nv_bfloat16* __restrict__ Olo = (z == 0) ? g_qlo : (z == 1) ? g_klo : g_vlo;
    const int mslot = (z == 0) ? 0 : (z == 1) ? 1 : 4;

    const __nv_bfloat16* __restrict__ Ah = g_xhi + (size_t)m0 * DMODEL;
    const __nv_bfloat16* __restrict__ Al = g_xlo + (size_t)m0 * DMODEL;
    const __nv_bfloat16* __restrict__ Bh = g_whi + (size_t)z * DMODEL * DMODEL + (size_t)n0 * DMODEL;
    const __nv_bfloat16* __restrict__ Bl = g_wlo + (size_t)z * DMODEL * DMODEL + (size_t)n0 * DMODEL;

    if (tid == 0) s_amax = 0u;

    const uint32_t sbase = smem_u32(sm);
    const int a_lrow = lane & 15;
    const int a_lcol = ((lane >> 4) & 1) * 8;
    const int b_lrow = (lane & 7) + (lane >> 4) * 8;
    const int b_lcol = ((lane >> 3) & 1) * 8;

    float c[4][4][4];
#pragma unroll
    for (int mt = 0; mt < 4; mt++)
#pragma unroll
        for (int nt = 0; nt < 4; nt++)
#pragma unroll
            for (int r = 0; r < 4; r++) c[mt][nt][r] = 0.f;

    const int NCH = DMODEL / GKC;     // 32

#define GEMM_LOAD_STAGE(ch, st) do {                                          \
        const int k0 = (ch) * GKC;                                            \
        const uint32_t stb = sbase + (uint32_t)(st) * GSTG_B;                 \
        _Pragma("unroll")                                                     \
        for (int i = 0; i < 2; i++) {                                         \
            const int u = tid + i * 256;                                      \
            const int row = u >> 2, cu = u & 3;                               \
            const size_t go = (size_t)row * DMODEL + k0 + cu * 8;             \
            const uint32_t so = stb + (uint32_t)(row * GST + cu * 8) * 2;     \
            CP_ASYNC16(so + 0 * GTILE_B, (const void*)(Ah + go));             \
            CP_ASYNC16(so + 1 * GTILE_B, (const void*)(Al + go));             \
            CP_ASYNC16(so + 2 * GTILE_B, (const void*)(Bh + go));             \
            CP_ASYNC16(so + 3 * GTILE_B, (const void*)(Bl + go));             \
        }                                                                     \
    } while (0)

    GEMM_LOAD_STAGE(0, 0); CP_COMMIT();
    GEMM_LOAD_STAGE(1, 1); CP_COMMIT();

    int st = 0;
    for (int ch = 0; ch < NCH; ch++) {
        CP_WAIT1();
        __syncthreads();
        if (ch + 2 < NCH) {
            const int st2 = (st + 2 >= 3) ? st - 1 : st + 2;
            GEMM_LOAD_STAGE(ch + 2, st2);
        }
        CP_COMMIT();

        const uint32_t bAh = sbase + (uint32_t)st * GSTG_B;
        const uint32_t bAl = bAh + GTILE_B;
        const uint32_t bBh = bAl + GTILE_B;
        const uint32_t bBl = bBh + GTILE_B;
#pragma unroll
        for (int ks = 0; ks < 2; ks++) {
            const int kc = ks * 16;
            uint32_t ah[4][4], al[4][4];
#pragma unroll
            for (int mt = 0; mt < 4; mt++) {
                const uint32_t off =
                    (uint32_t)(((wm * 64 + mt * 16 + a_lrow) * GST + kc + a_lcol) * 2);
                LDSM_X4(ah[mt][0], ah[mt][1], ah[mt][2], ah[mt][3], bAh + off);
                LDSM_X4(al[mt][0], al[mt][1], al[mt][2], al[mt][3], bAl + off);
            }
            uint32_t bhf[4][2], blf[4][2];
#pragma unroll
            for (int ntp = 0; ntp < 2; ntp++) {
                const uint32_t off =
                    (uint32_t)(((wn * 32 + ntp * 16 + b_lrow) * GST + kc + b_lcol) * 2);
                LDSM_X4(bhf[2 * ntp][0], bhf[2 * ntp][1],
                        bhf[2 * ntp + 1][0], bhf[2 * ntp + 1][1], bBh + off);
                LDSM_X4(blf[2 * ntp][0], blf[2 * ntp][1],
                        blf[2 * ntp + 1][0], blf[2 * ntp + 1][1], bBl + off);
            }
            // pass-major order: 16-MMA dependency distance per accumulator
#pragma unroll
            for (int mt = 0; mt < 4; mt++)
#pragma unroll
                for (int nt = 0; nt < 4; nt++)
                    mma_bf16(c[mt][nt], ah[mt], bhf[nt][0], bhf[nt][1]);
#pragma unroll
            for (int mt = 0; mt < 4; mt++)
#pragma unroll
                for (int nt = 0; nt < 4; nt++)
                    mma_bf16(c[mt][nt], ah[mt], blf[nt][0], blf[nt][1]);
#pragma unroll
            for (int mt = 0; mt < 4; mt++)
#pragma unroll
                for (int nt = 0; nt < 4; nt++)
                    mma_bf16(c[mt][nt], al[mt], bhf[nt][0], bhf[nt][1]);
        }
        __syncthreads();
        st = (st + 1 >= 3) ? 0 : st + 1;
    }
#undef GEMM_LOAD_STAGE

    // epilogue: bias, absmax, split -> bf16 hi/lo, layout [BH][S][64]
    float lmax = 0.f;
#pragma unroll
    for (int nt = 0; nt < 4; nt++) {
        const int n = n0 + wn * 32 + nt * 8 + 2 * t;
        const float bn0 = bias[n], bn1 = bias[n + 1];
        const int h = n >> 6, d = n & 63;
#pragma unroll
        for (int mt = 0; mt < 4; mt++) {
            const int mr0 = m0 + wm * 64 + mt * 16 + g;
            const int mr1 = mr0 + 8;
            float v0 = c[mt][nt][0] + bn0;
            float v1 = c[mt][nt][1] + bn1;
            float v2 = c[mt][nt][2] + bn0;
            float v3 = c[mt][nt][3] + bn1;
            lmax = fmaxf(lmax, fmaxf(fmaxf(fabsf(v0), fabsf(v1)),
                                     fmaxf(fabsf(v2), fabsf(v3))));
            const int bb0 = mr0 >> 11, s0 = mr0 & 2047;
            const int bb1 = mr1 >> 11, s1 = mr1 & 2047;
            const size_t o0 = (((size_t)(bb0 * HEADS + h)) * SEQ + s0) * HDIM + d;
            const size_t o1 = (((size_t)(bb1 * HEADS + h)) * SEQ + s1) * HDIM + d;
            uint32_t h0 = packb(v0, v1), h1 = packb(v2, v3);
            __nv_bfloat162 hb0 = *(__nv_bfloat162*)&h0;
            __nv_bfloat162 hb1 = *(__nv_bfloat162*)&h1;
            uint32_t l0 = packb(v0 - __bfloat162float(hb0.x), v1 - __bfloat162float(hb0.y));
            uint32_t l1 = packb(v2 - __bfloat162float(hb1.x), v3 - __bfloat162float(hb1.y));
            *(uint32_t*)(Ohi + o0) = h0;
            *(uint32_t*)(Ohi + o1) = h1;
            *(uint32_t*)(Olo + o0) = l0;
            *(uint32_t*)(Olo + o1) = l1;
        }
    }
    atomicMax(&s_amax, __float_as_uint(lmax));
    __syncthreads();
    if (tid == 0) atomicMax(&g_mx[mslot], s_amax);
}

// ---------- warp-MMA flash attention: split-bf16 + ldmatrix + cp.async x3 ----
#define KST 72                            // K/V smem row stride (bf16), 144B
#define ATILE_B (64 * KST * 2)            // 9216 B per tile
#define ASTG_B (4 * ATILE_B)              // kh kl vh vl = 36864 B per stage
#define ATTN_SMEM_BYTES (3 * ASTG_B)      // 110592

__global__ __launch_bounds__(256, 1) void attn_mma(float* __restrict__ out)
{
    extern __shared__ __nv_bfloat16 asm_buf[];
    __shared__ unsigned s_raw, s_aw;

    const int tid = threadIdx.x;
    const int wid = tid >> 5;
    const int lane = tid & 31;
    const int g = lane >> 2;
    const int t = lane & 3;

    const int bh = blockIdx.y;
    const int b = bh >> 4, h = bh & 15;
    const int q0 = blockIdx.x * 128;

    if (tid == 0) { s_raw = 0u; s_aw = 0u; }

    const uint32_t sbase = smem_u32(asm_buf);
    const int b_lrow = (lane & 7) + (lane >> 4) * 8;
    const int b_lcol = ((lane >> 3) & 1) * 8;
    const int v_lrow = (lane & 7) + ((lane >> 3) & 1) * 8;
    const int v_lcol = (lane >> 4) * 8;

    // Q fragments (hi/lo), loaded once from global
    const size_t qbase = ((size_t)bh * SEQ + q0 + wid * 16) * HDIM;
    const __nv_bfloat16* Qh = g_qhi + qbase;
    const __nv_bfloat16* Ql = g_qlo + qbase;
    uint32_t qh[4][4], ql[4][4];
#pragma unroll
    for (int kk = 0; kk < 4; kk++) {
        const int c0 = kk * 16 + 2 * t;
        qh[kk][0] = *(const uint32_t*)(Qh + g * HDIM + c0);
        qh[kk][1] = *(const uint32_t*)(Qh + (g + 8) * HDIM + c0);
        qh[kk][2] = *(const uint32_t*)(Qh + g * HDIM + c0 + 8);
        qh[kk][3] = *(const uint32_t*)(Qh + (g + 8) * HDIM + c0 + 8);
        ql[kk][0] = *(const uint32_t*)(Ql + g * HDIM + c0);
        ql[kk][1] = *(const uint32_t*)(Ql + (g + 8) * HDIM + c0);
        ql[kk][2] = *(const uint32_t*)(Ql + g * HDIM + c0 + 8);
        ql[kk][3] = *(const uint32_t*)(Ql + (g + 8) * HDIM + c0 + 8);
    }

    const __nv_bfloat16* Kh = g_khi + (size_t)bh * SEQ * HDIM;
    const __nv_bfloat16* Kl = g_klo + (size_t)bh * SEQ * HDIM;
    const __nv_bfloat16* Vh = g_vhi + (size_t)bh * SEQ * HDIM;
    const __nv_bfloat16* Vl = g_vlo + (size_t)bh * SEQ * HDIM;

    float o[8][4];
#pragma unroll
    for (int j = 0; j < 8; j++)
#pragma unroll
        for (int r = 0; r < 4; r++) o[j][r] = 0.f;
    float m0 = -1e30f, m1 = -1e30f, l0 = 0.f, l1 = 0.f, raw = 0.f;

    const int NKV = SEQ / 64;  // 32

#define ATTN_LOAD_STAGE(kv, st) do {                                          \
        const int base_row = (kv) * 64;                                       \
        const uint32_t stb = sbase + (uint32_t)(st) * ASTG_B;                 \
        _Pragma("unroll")                                                     \
        for (int i = 0; i < 2; i++) {                                         \
            const int u = tid + i * 256;                                      \
            const int row = u >> 3, du = u & 7;                               \
            const size_t go = (size_t)(base_row + row) * HDIM + du * 8;       \
            const uint32_t so = stb + (uint32_t)(row * KST + du * 8) * 2;     \
            CP_ASYNC16(so + 0 * ATILE_B, (const void*)(Kh + go));             \
            CP_ASYNC16(so + 1 * ATILE_B, (const void*)(Kl + go));             \
            CP_ASYNC16(so + 2 * ATILE_B, (const void*)(Vh + go));             \
            CP_ASYNC16(so + 3 * ATILE_B, (const void*)(Vl + go));             \
        }                                                                     \
    } while (0)

    ATTN_LOAD_STAGE(0, 0); CP_COMMIT();
    ATTN_LOAD_STAGE(1, 1); CP_COMMIT();

    int st = 0;
    for (int kv = 0; kv < NKV; kv++) {
        CP_WAIT1();
        __syncthreads();
        if (kv + 2 < NKV) {
            const int st2 = (st + 2 >= 3) ? st - 1 : st + 2;
            ATTN_LOAD_STAGE(kv + 2, st2);
        }
        CP_COMMIT();

        const uint32_t kh_b = sbase + (uint32_t)st * ASTG_B;
        const uint32_t kl_b = kh_b + ATILE_B;
        const uint32_t vh_b = kl_b + ATILE_B;
        const uint32_t vl_b = vh_b + ATILE_B;

        // S = Q K^T (split, 3 passes, pass-major for ILP)
        float s[8][4];
#pragma unroll
        for (int j = 0; j < 8; j++)
#pragma unroll
            for (int r = 0; r < 4; r++) s[j][r] = 0.f;
#pragma unroll
        for (int kk = 0; kk < 4; kk++) {
            uint32_t kbh[8][2], kbl[8][2];
#pragma unroll
            for (int jp = 0; jp < 4; jp++) {
                const uint32_t off =
                    (uint32_t)(((jp * 16 + b_lrow) * KST + kk * 16 + b_lcol) * 2);
                LDSM_X4(kbh[2 * jp][0], kbh[2 * jp][1],
                        kbh[2 * jp + 1][0], kbh[2 * jp + 1][1], kh_b + off);
                LDSM_X4(kbl[2 * jp][0], kbl[2 * jp][1],
                        kbl[2 * jp + 1][0], kbl[2 * jp + 1][1], kl_b + off);
            }
#pragma unroll
            for (int j = 0; j < 8; j++)
                mma_bf16(s[j], qh[kk], kbh[j][0], kbh[j][1]);
#pragma unroll
            for (int j = 0; j < 8; j++)
                mma_bf16(s[j], qh[kk], kbl[j][0], kbl[j][1]);
#pragma unroll
            for (int j = 0; j < 8; j++)
                mma_bf16(s[j], ql[kk], kbh[j][0], kbh[j][1]);
        }

        // raw absmax (pre-scale), scale, online softmax
        float rm0 = -1e30f, rm1 = -1e30f;
#pragma unroll
        for (int j = 0; j < 8; j++) {
#pragma unroll
            for (int r = 0; r < 4; r++) {
                raw = fmaxf(raw, fabsf(s[j][r]));
                s[j][r] *= 0.125f;
            }
            rm0 = fmaxf(rm0, fmaxf(s[j][0], s[j][1]));
            rm1 = fmaxf(rm1, fmaxf(s[j][2], s[j][3]));
        }
        rm0 = fmaxf(rm0, __shfl_xor_sync(0xffffffffu, rm0, 1));
        rm0 = fmaxf(rm0, __shfl_xor_sync(0xffffffffu, rm0, 2));
        rm1 = fmaxf(rm1, __shfl_xor_sync(0xffffffffu, rm1, 1));
        rm1 = fmaxf(rm1, __shfl_xor_sync(0xffffffffu, rm1, 2));
        const float mn0 = fmaxf(m0, rm0), mn1 = fmaxf(m1, rm1);
        const float f0 = __expf(m0 - mn0), f1 = __expf(m1 - mn1);
        float ps0 = 0.f, ps1 = 0.f;
#pragma unroll
        for (int j = 0; j < 8; j++) {
            s[j][0] = __expf(s[j][0] - mn0);
            s[j][1] = __expf(s[j][1] - mn0);
            s[j][2] = __expf(s[j][2] - mn1);
            s[j][3] = __expf(s[j][3] - mn1);
            ps0 += s[j][0] + s[j][1];
            ps1 += s[j][2] + s[j][3];
        }
        ps0 += __shfl_xor_sync(0xffffffffu, ps0, 1);
        ps0 += __shfl_xor_sync(0xffffffffu, ps0, 2);
        ps1 += __shfl_xor_sync(0xffffffffu, ps1, 1);
        ps1 += __shfl_xor_sync(0xffffffffu, ps1, 2);
        l0 = l0 * f0 + ps0;
        l1 = l1 * f1 + ps1;
        m0 = mn0; m1 = mn1;
#pragma unroll
        for (int j = 0; j < 8; j++) {
            o[j][0] *= f0; o[j][1] *= f0;
            o[j][2] *= f1; o[j][3] *= f1;
        }

        // P -> split bf16 fragments
        uint32_t ph[8][2], pl[8][2];
#pragma unroll
        for (int j = 0; j < 8; j++) {
            uint32_t p0 = packb(s[j][0], s[j][1]);
            uint32_t p1 = packb(s[j][2], s[j][3]);
            __nv_bfloat162 b0 = *(__nv_bfloat162*)&p0;
            __nv_bfloat162 b1 = *(__nv_bfloat162*)&p1;
            ph[j][0] = p0; ph[j][1] = p1;
            pl[j][0] = packb(s[j][0] - __bfloat162float(b0.x),
                             s[j][1] - __bfloat162float(b0.y));
            pl[j][1] = packb(s[j][2] - __bfloat162float(b1.x),
                             s[j][3] - __bfloat162float(b1.y));
        }

        // O += P V (split, 3 passes, pass-major); V frags via ldmatrix.trans
#pragma unroll
        for (int kk = 0; kk < 4; kk++) {
            uint32_t pah[4] = {ph[2 * kk][0], ph[2 * kk][1],
                               ph[2 * kk + 1][0], ph[2 * kk + 1][1]};
            uint32_t pal[4] = {pl[2 * kk][0], pl[2 * kk][1],
                               pl[2 * kk + 1][0], pl[2 * kk + 1][1]};
            uint32_t vbh[8][2], vbl[8][2];
#pragma unroll
            for (int jp = 0; jp < 4; jp++) {
                const uint32_t off =
                    (uint32_t)(((kk * 16 + v_lrow) * KST + jp * 16 + v_lcol) * 2);
                LDSM_X4_T(vbh[2 * jp][0], vbh[2 * jp][1],
                          vbh[2 * jp + 1][0], vbh[2 * jp + 1][1], vh_b + off);
                LDSM_X4_T(vbl[2 * jp][0], vbl[2 * jp][1],
                          vbl[2 * jp + 1][0], vbl[2 * jp + 1][1], vl_b + off);
            }
#pragma unroll
            for (int j = 0; j < 8; j++)
                mma_bf16(o[j], pah, vbh[j][0], vbh[j][1]);
#pragma unroll
            for (int j = 0; j < 8; j++)
                mma_bf16(o[j], pah, vbl[j][0], vbl[j][1]);
#pragma unroll
            for (int j = 0; j < 8; j++)
                mma_bf16(o[j], pal, vbh[j][0], vbh[j][1]);
        }
        __syncthreads();
        st = (st + 1 >= 3) ? 0 : st + 1;
    }
#undef ATTN_LOAD_STAGE

    // epilogue
    const float i0 = 1.f / l0, i1 = 1.f / l1;
    const int r0g = q0 + wid * 16 + g;
    const int r1g = r0g + 8;
    const size_t ob0 = ((size_t)b * SEQ + r0g) * DMODEL + h * HDIM;
    const size_t ob1 = ((size_t)b * SEQ + r1g) * DMODEL + h * HDIM;
#pragma unroll
    for (int j = 0; j < 8; j++) {
        const int d = 8 * j + 2 * t;
        float2 w0 = {o[j][0] * i0, o[j][1] * i0};
        float2 w1 = {o[j][2] * i1, o[j][3] * i1};
        *(float2*)(out + ob0 + d) = w0;
        *(float2*)(out + ob1 + d) = w1;
    }
    atomicMax(&s_raw, __float_as_uint(raw));
    atomicMax(&s_aw, __float_as_uint(fmaxf(i0, i1)));
    __syncthreads();
    if (tid == 0) {
        atomicMax(&g_mx[2], s_raw);
        atomicMax(&g_mx[3], s_aw);
    }
}

// ---------------- finalize scalars ----------------
__global__ void finalize_kernel(float* __restrict__ out, int base)
{
    if (threadIdx.x == 0) {
        const float qm  = __uint_as_float(g_mx[0]);
        const float km  = __uint_as_float(g_mx[1]);
        const float qkm = __uint_as_float(g_mx[2]);
        const float awm = __uint_as_float(g_mx[3]);
        const float vm  = __uint_as_float(g_mx[4]);
        out[base + 0] = qm;
        out[base + 1] = km;
        out[base + 2] = qkm;
        out[base + 3] = awm;
        out[base + 4] = vm;
        out[base + 5] = awm;  // v_out_max (faithful source bug)
    }
}

// ---------------- launch ----------------
extern "C" void kernel_launch(void* const* d_in, const int* in_sizes, int n_in,
                              void* d_out, int out_size)
{
    const float* X  = (const float*)d_in[0];
    const float* Wq = (const float*)d_in[1];
    const float* bq = (const float*)d_in[2];
    const float* Wk = (const float*)d_in[3];
    const float* bk = (const float*)d_in[4];
    const float* Wv = (const float*)d_in[5];
    const float* bv = (const float*)d_in[6];
    float* out = (float*)d_out;

    cudaFuncSetAttribute(qkv_gemm_mma,
                         cudaFuncAttributeMaxDynamicSharedMemorySize,
                         GEMM_SMEM_BYTES);
    cudaFuncSetAttribute(attn_mma,
                         cudaFuncAttributeMaxDynamicSharedMemorySize,
                         ATTN_SMEM_BYTES);

    init_kernel<<<1, 32>>>();                                           // 0
    convert_x<<<MROWS * DMODEL / 4 / 256, 256>>>(X);                    // 1
    convert_w<<<dim3(DMODEL * DMODEL / 4 / 256, 1, 3), 256>>>(Wq, Wk, Wv); // 2
    qkv_gemm_mma<<<dim3(DMODEL / 128, MROWS / 128, 3), 256,
                   GEMM_SMEM_BYTES>>>(bq, bk, bv);                      // 3
    spacer_kernel<<<1, 32>>>();                                         // 4
    attn_mma<<<dim3(SEQ / 128, BATCH * HEADS), 256,
               ATTN_SMEM_BYTES>>>(out);                                 // 5
    finalize_kernel<<<1, 32>>>(out, out_size - 6);                      // 6
}

// round 7
// speedup vs baseline: 3.6531x; 1.0117x over previous
#include <cuda_runtime.h>
#include <cuda_bf16.h>
#include <cstdint>

// Problem constants: B=2, S=2048, DM=1024, H=16, DH=64
#define BATCH 2
#define SEQ 2048
#define DMODEL 1024
#define HEADS 16
#define HDIM 64
#define MROWS (BATCH*SEQ)                 // 4096
#define QKV_ELEMS (BATCH*HEADS*SEQ*HDIM)  // 4,194,304

// ---------------- device scratch ----------------
__device__ __nv_bfloat16 g_xhi[MROWS * DMODEL];
__device__ __nv_bfloat16 g_xlo[MROWS * DMODEL];
__device__ __nv_bfloat16 g_whi[3 * DMODEL * DMODEL];
__device__ __nv_bfloat16 g_wlo[3 * DMODEL * DMODEL];
__device__ __nv_bfloat16 g_qhi[QKV_ELEMS], g_qlo[QKV_ELEMS];
__device__ __nv_bfloat16 g_khi[QKV_ELEMS], g_klo[QKV_ELEMS];
__device__ __nv_bfloat16 g_vhi[QKV_ELEMS], g_vlo[QKV_ELEMS];
// absmax slots: 0=q 1=k 2=qk_raw 3=aw 4=v
__device__ unsigned g_mx[5];

__global__ void init_kernel() {
    if (threadIdx.x < 5) g_mx[threadIdx.x] = 0u;
}
__global__ void spacer_kernel() {}   // shifts attn to launch idx 5 for ncu -s 5

// ---------------- helpers ----------------
__device__ __forceinline__ void mma_bf16(float (&c)[4], const uint32_t (&a)[4],
                                         uint32_t b0, uint32_t b1) {
    asm volatile(
        "mma.sync.aligned.m16n8k16.row.col.f32.bf16.bf16.f32 "
        "{%0,%1,%2,%3}, {%4,%5,%6,%7}, {%8,%9}, {%0,%1,%2,%3};"
        : "+f"(c[0]), "+f"(c[1]), "+f"(c[2]), "+f"(c[3])
        : "r"(a[0]), "r"(a[1]), "r"(a[2]), "r"(a[3]), "r"(b0), "r"(b1));
}
__device__ __forceinline__ uint32_t packb(float lo, float hi) {
    uint32_t r;
    asm("cvt.rn.bf16x2.f32 %0, %1, %2;" : "=r"(r) : "f"(hi), "f"(lo));
    return r;
}
__device__ __forceinline__ uint32_t smem_u32(const void* p) {
    uint32_t a;
    asm("{ .reg .u64 t; cvta.to.shared.u64 t, %1; cvt.u32.u64 %0, t; }"
        : "=r"(a) : "l"(p));
    return a;
}
#define LDSM_X4(r0, r1, r2, r3, addr) \
    asm volatile("ldmatrix.sync.aligned.m8n8.x4.shared.b16 {%0,%1,%2,%3}, [%4];" \
                 : "=r"(r0), "=r"(r1), "=r"(r2), "=r"(r3) : "r"(addr))
#define LDSM_X4_T(r0, r1, r2, r3, addr) \
    asm volatile("ldmatrix.sync.aligned.m8n8.x4.trans.shared.b16 {%0,%1,%2,%3}, [%4];" \
                 : "=r"(r0), "=r"(r1), "=r"(r2), "=r"(r3) : "r"(addr))
#define CP_ASYNC16(dst, src) \
    asm volatile("cp.async.cg.shared.global [%0], [%1], 16;" \
                 :: "r"(dst), "l"(src))
#define CP_COMMIT() asm volatile("cp.async.commit_group;" ::: "memory")
#define CP_WAIT1() asm volatile("cp.async.wait_group 1;" ::: "memory")

// ---------------- fp32 -> bf16 hi/lo split conversion ----------------
__global__ __launch_bounds__(256) void convert_x(const float* __restrict__ X) {
    size_t i4 = ((size_t)blockIdx.x * 256 + threadIdx.x) * 4;
    float4 v = *(const float4*)(X + i4);
    float f[4] = {v.x, v.y, v.z, v.w};
    __nv_bfloat16 h[4], l[4];
#pragma unroll
    for (int j = 0; j < 4; j++) {
        h[j] = __float2bfloat16_rn(f[j]);
        l[j] = __float2bfloat16_rn(f[j] - __bfloat162float(h[j]));
    }
    *(__nv_bfloat162*)(g_xhi + i4 + 0) = __nv_bfloat162(h[0], h[1]);
    *(__nv_bfloat162*)(g_xhi + i4 + 2) = __nv_bfloat162(h[2], h[3]);
    *(__nv_bfloat162*)(g_xlo + i4 + 0) = __nv_bfloat162(l[0], l[1]);
    *(__nv_bfloat162*)(g_xlo + i4 + 2) = __nv_bfloat162(l[2], l[3]);
}

__global__ __launch_bounds__(256) void convert_w(
    const float* __restrict__ Wq, const float* __restrict__ Wk,
    const float* __restrict__ Wv) {
    const int z = blockIdx.z;
    const float* W = (z == 0) ? Wq : (z == 1) ? Wk : Wv;
    size_t base = (size_t)z * DMODEL * DMODEL;
    size_t i4 = ((size_t)blockIdx.x * 256 + threadIdx.x) * 4;
    float4 v = *(const float4*)(W + i4);
    float f[4] = {v.x, v.y, v.z, v.w};
    __nv_bfloat16 h[4], l[4];
#pragma unroll
    for (int j = 0; j < 4; j++) {
        h[j] = __float2bfloat16_rn(f[j]);
        l[j] = __float2bfloat16_rn(f[j] - __bfloat162float(h[j]));
    }
    *(__nv_bfloat162*)(g_whi + base + i4 + 0) = __nv_bfloat162(h[0], h[1]);
    *(__nv_bfloat162*)(g_whi + base + i4 + 2) = __nv_bfloat162(h[2], h[3]);
    *(__nv_bfloat162*)(g_wlo + base + i4 + 0) = __nv_bfloat162(l[0], l[1]);
    *(__nv_bfloat162*)(g_wlo + base + i4 + 2) = __nv_bfloat162(l[2], l[3]);
}

// ------- split-bf16 QKV GEMM: 512 threads / 16 warps, warp tile 32x32 -------
#define GKC 32
#define GST 40                           // smem row stride (bf16), 80B
#define GTILE_B (128 * GST * 2)          // 10240 B per tile
#define GSTG_B (4 * GTILE_B)             // Ah Al Bh Bl = 40960 B per stage
#define GEMM_SMEM_BYTES (3 * GSTG_B)     // 122880

__global__ __launch_bounds__(512, 1) void qkv_gemm_mma(
    const float* __restrict__ bq, const float* __restrict__ bk,
    const float* __restrict__ bv)
{
    extern __shared__ __nv_bfloat16 sm[];
    __shared__ unsigned s_amax;

    const int tid = threadIdx.x;
    const int wid = tid >> 5;
    const int lane = tid & 31;
    const int g = lane >> 2;
    const int t = lane & 3;
    const int wm = wid & 3;           // 0..3 (32 rows each)
    const int wn = wid >> 2;          // 0..3 (32 cols each)

    const int z = blockIdx.z;
    const int m0 = blockIdx.y * 128;
    const int n0 = blockIdx.x * 128;

    const float* __restrict__ bias = (z == 0) ? bq : (z == 1) ? bk : bv;
    __nv_bfloat16* __restrict__ Ohi = (z == 0) ? g_qhi : (z == 1) ? g_khi : g_vhi;
    __nv_bfloat16* __restrict__ Olo = (z == 0) ? g_qlo : (z == 1) ? g_klo : g_vlo;
    const int mslot = (z == 0) ? 0 : (z == 1) ? 1 : 4;

    const __nv_bfloat16* __restrict__ Ah = g_xhi + (size_t)m0 * DMODEL;
    const __nv_bfloat16* __restrict__ Al = g_xlo + (size_t)m0 * DMODEL;
    const __nv_bfloat16* __restrict__ Bh = g_whi + (size_t)z * DMODEL * DMODEL + (size_t)n0 * DMODEL;
    const __nv_bfloat16* __restrict__ Bl = g_wlo + (size_t)z * DMODEL * DMODEL + (size_t)n0 * DMODEL;

    if (tid == 0) s_amax = 0u;

    const uint32_t sbase = smem_u32(sm);
    const int a_lrow = lane & 15;
    const int a_lcol = ((lane >> 4) & 1) * 8;
    const int b_lrow = (lane & 7) + (lane >> 4) * 8;
    const int b_lcol = ((lane >> 3) & 1) * 8;

    float c[2][4][4];
#pragma unroll
    for (int mt = 0; mt < 2; mt++)
#pragma unroll
        for (int nt = 0; nt < 4; nt++)
#pragma unroll
            for (int r = 0; r < 4; r++) c[mt][nt][r] = 0.f;

    const int NCH = DMODEL / GKC;     // 32

    // 512 threads: one 16B cp.async per tile per thread per stage
#define GEMM_LOAD_STAGE(ch, st) do {                                          \
        const int k0 = (ch) * GKC;                                            \
        const uint32_t stb = sbase + (uint32_t)(st) * GSTG_B;                 \
        const int row = tid >> 2, cu = tid & 3;                               \
        const size_t go = (size_t)row * DMODEL + k0 + cu * 8;                 \
        const uint32_t so = stb + (uint32_t)(row * GST + cu * 8) * 2;         \
        CP_ASYNC16(so + 0 * GTILE_B, (const void*)(Ah + go));                 \
        CP_ASYNC16(so + 1 * GTILE_B, (const void*)(Al + go));                 \
        CP_ASYNC16(so + 2 * GTILE_B, (const void*)(Bh + go));                 \
        CP_ASYNC16(so + 3 * GTILE_B, (const void*)(Bl + go));                 \
    } while (0)

    GEMM_LOAD_STAGE(0, 0); CP_COMMIT();
    GEMM_LOAD_STAGE(1, 1); CP_COMMIT();

    int st = 0;
    for (int ch = 0; ch < NCH; ch++) {
        CP_WAIT1();
        __syncthreads();
        if (ch + 2 < NCH) {
            const int st2 = (st + 2 >= 3) ? st - 1 : st + 2;
            GEMM_LOAD_STAGE(ch + 2, st2);
        }
        CP_COMMIT();

        const uint32_t bAh = sbase + (uint32_t)st * GSTG_B;
        const uint32_t bAl = bAh + GTILE_B;
        const uint32_t bBh = bAl + GTILE_B;
        const uint32_t bBl = bBh + GTILE_B;
#pragma unroll
        for (int ks = 0; ks < 2; ks++) {
            const int kc = ks * 16;
            uint32_t ah[2][4], al[2][4];
#pragma unroll
            for (int mt = 0; mt < 2; mt++) {
                const uint32_t off =
                    (uint32_t)(((wm * 32 + mt * 16 + a_lrow) * GST + kc + a_lcol) * 2);
                LDSM_X4(ah[mt][0], ah[mt][1], ah[mt][2], ah[mt][3], bAh + off);
                LDSM_X4(al[mt][0], al[mt][1], al[mt][2], al[mt][3], bAl + off);
            }
            uint32_t bhf[4][2], blf[4][2];
#pragma unroll
            for (int ntp = 0; ntp < 2; ntp++) {
                const uint32_t off =
                    (uint32_t)(((wn * 32 + ntp * 16 + b_lrow) * GST + kc + b_lcol) * 2);
                LDSM_X4(bhf[2 * ntp][0], bhf[2 * ntp][1],
                        bhf[2 * ntp + 1][0], bhf[2 * ntp + 1][1], bBh + off);
                LDSM_X4(blf[2 * ntp][0], blf[2 * ntp][1],
                        blf[2 * ntp + 1][0], blf[2 * ntp + 1][1], bBl + off);
            }
#pragma unroll
            for (int mt = 0; mt < 2; mt++)
#pragma unroll
                for (int nt = 0; nt < 4; nt++)
                    mma_bf16(c[mt][nt], ah[mt], bhf[nt][0], bhf[nt][1]);
#pragma unroll
            for (int mt = 0; mt < 2; mt++)
#pragma unroll
                for (int nt = 0; nt < 4; nt++)
                    mma_bf16(c[mt][nt], ah[mt], blf[nt][0], blf[nt][1]);
#pragma unroll
            for (int mt = 0; mt < 2; mt++)
#pragma unroll
                for (int nt = 0; nt < 4; nt++)
                    mma_bf16(c[mt][nt], al[mt], bhf[nt][0], bhf[nt][1]);
        }
        __syncthreads();
        st = (st + 1 >= 3) ? 0 : st + 1;
    }
#undef GEMM_LOAD_STAGE

    // epilogue: bias, absmax, split -> bf16 hi/lo, layout [BH][S][64]
    float lmax = 0.f;
#pragma unroll
    for (int nt = 0; nt < 4; nt++) {
        const int n = n0 + wn * 32 + nt * 8 + 2 * t;
        const float bn0 = bias[n], bn1 = bias[n + 1];
        const int h = n >> 6, d = n & 63;
#pragma unroll
        for (int mt = 0; mt < 2; mt++) {
            const int mr0 = m0 + wm * 32 + mt * 16 + g;
            const int mr1 = mr0 + 8;
            float v0 = c[mt][nt][0] + bn0;
            float v1 = c[mt][nt][1] + bn1;
            float v2 = c[mt][nt][2] + bn0;
            float v3 = c[mt][nt][3] + bn1;
            lmax = fmaxf(lmax, fmaxf(fmaxf(fabsf(v0), fabsf(v1)),
                                     fmaxf(fabsf(v2), fabsf(v3))));
            const int bb0 = mr0 >> 11, s0 = mr0 & 2047;
            const int bb1 = mr1 >> 11, s1 = mr1 & 2047;
            const size_t o0 = (((size_t)(bb0 * HEADS + h)) * SEQ + s0) * HDIM + d;
            const size_t o1 = (((size_t)(bb1 * HEADS + h)) * SEQ + s1) * HDIM + d;
            uint32_t h0 = packb(v0, v1), h1 = packb(v2, v3);
            __nv_bfloat162 hb0 = *(__nv_bfloat162*)&h0;
            __nv_bfloat162 hb1 = *(__nv_bfloat162*)&h1;
            uint32_t l0 = packb(v0 - __bfloat162float(hb0.x), v1 - __bfloat162float(hb0.y));
            uint32_t l1 = packb(v2 - __bfloat162float(hb1.x), v3 - __bfloat162float(hb1.y));
            *(uint32_t*)(Ohi + o0) = h0;
            *(uint32_t*)(Ohi + o1) = h1;
            *(uint32_t*)(Olo + o0) = l0;
            *(uint32_t*)(Olo + o1) = l1;
        }
    }
    atomicMax(&s_amax, __float_as_uint(lmax));
    __syncthreads();
    if (tid == 0) atomicMax(&g_mx[mslot], s_amax);
}

// ------ flash attention: KV tile 32, 3-stage cp.async, 2 CTAs/SM ------------
#define AKV 32                            // kv rows per tile
#define KST 72                            // smem row stride (bf16), 144B
#define ATILE_B (AKV * KST * 2)           // 4608 B per tile
#define ASTG_B (4 * ATILE_B)              // kh kl vh vl = 18432 B per stage
#define ATTN_SMEM_BYTES (3 * ASTG_B)      // 55296

__global__ __launch_bounds__(256, 2) void attn_mma(float* __restrict__ out)
{
    extern __shared__ __nv_bfloat16 asm_buf[];
    __shared__ unsigned s_raw, s_aw;

    const int tid = threadIdx.x;
    const int wid = tid >> 5;
    const int lane = tid & 31;
    const int g = lane >> 2;
    const int t = lane & 3;

    const int bh = blockIdx.y;
    const int b = bh >> 4, h = bh & 15;
    const int q0 = blockIdx.x * 128;

    if (tid == 0) { s_raw = 0u; s_aw = 0u; }

    const uint32_t sbase = smem_u32(asm_buf);
    const int b_lrow = (lane & 7) + (lane >> 4) * 8;
    const int b_lcol = ((lane >> 3) & 1) * 8;
    const int v_lrow = (lane & 7) + ((lane >> 3) & 1) * 8;
    const int v_lcol = (lane >> 4) * 8;

    // Q fragments (hi/lo), loaded once from global
    const size_t qbase = ((size_t)bh * SEQ + q0 + wid * 16) * HDIM;
    const __nv_bfloat16* Qh = g_qhi + qbase;
    const __nv_bfloat16* Ql = g_qlo + qbase;
    uint32_t qh[4][4], ql[4][4];
#pragma unroll
    for (int kk = 0; kk < 4; kk++) {
        const int c0 = kk * 16 + 2 * t;
        qh[kk][0] = *(const uint32_t*)(Qh + g * HDIM + c0);
        qh[kk][1] = *(const uint32_t*)(Qh + (g + 8) * HDIM + c0);
        qh[kk][2] = *(const uint32_t*)(Qh + g * HDIM + c0 + 8);
        qh[kk][3] = *(const uint32_t*)(Qh + (g + 8) * HDIM + c0 + 8);
        ql[kk][0] = *(const uint32_t*)(Ql + g * HDIM + c0);
        ql[kk][1] = *(const uint32_t*)(Ql + (g + 8) * HDIM + c0);
        ql[kk][2] = *(const uint32_t*)(Ql + g * HDIM + c0 + 8);
        ql[kk][3] = *(const uint32_t*)(Ql + (g + 8) * HDIM + c0 + 8);
    }

    const __nv_bfloat16* Kh = g_khi + (size_t)bh * SEQ * HDIM;
    const __nv_bfloat16* Kl = g_klo + (size_t)bh * SEQ * HDIM;
    const __nv_bfloat16* Vh = g_vhi + (size_t)bh * SEQ * HDIM;
    const __nv_bfloat16* Vl = g_vlo + (size_t)bh * SEQ * HDIM;

    float o[8][4];
#pragma unroll
    for (int j = 0; j < 8; j++)
#pragma unroll
        for (int r = 0; r < 4; r++) o[j][r] = 0.f;
    float m0 = -1e30f, m1 = -1e30f, l0 = 0.f, l1 = 0.f, raw = 0.f;

    const int NKV = SEQ / AKV;  // 64

    // 256 threads: one 16B cp.async per tile per thread per stage
#define ATTN_LOAD_STAGE(kv, st) do {                                          \
        const int base_row = (kv) * AKV;                                      \
        const uint32_t stb = sbase + (uint32_t)(st) * ASTG_B;                 \
        const int row = tid >> 3, du = tid & 7;                               \
        const size_t go = (size_t)(base_row + row) * HDIM + du * 8;           \
        const uint32_t so = stb + (uint32_t)(row * KST + du * 8) * 2;         \
        CP_ASYNC16(so + 0 * ATILE_B, (const void*)(Kh + go));                 \
        CP_ASYNC16(so + 1 * ATILE_B, (const void*)(Kl + go));                 \
        CP_ASYNC16(so + 2 * ATILE_B, (const void*)(Vh + go));                 \
        CP_ASYNC16(so + 3 * ATILE_B, (const void*)(Vl + go));                 \
    } while (0)

    ATTN_LOAD_STAGE(0, 0); CP_COMMIT();
    ATTN_LOAD_STAGE(1, 1); CP_COMMIT();

    int st = 0;
    for (int kv = 0; kv < NKV; kv++) {
        CP_WAIT1();
        __syncthreads();
        if (kv + 2 < NKV) {
            const int st2 = (st + 2 >= 3) ? st - 1 : st + 2;
            ATTN_LOAD_STAGE(kv + 2, st2);
        }
        CP_COMMIT();

        const uint32_t kh_b = sbase + (uint32_t)st * ASTG_B;
        const uint32_t kl_b = kh_b + ATILE_B;
        const uint32_t vh_b = kl_b + ATILE_B;
        const uint32_t vl_b = vh_b + ATILE_B;

        // S = Q K^T over 32 kv cols (split, 3 passes, pass-major)
        float s[4][4];
#pragma unroll
        for (int j = 0; j < 4; j++)
#pragma unroll
            for (int r = 0; r < 4; r++) s[j][r] = 0.f;
#pragma unroll
        for (int kk = 0; kk < 4; kk++) {
            uint32_t kbh[4][2], kbl[4][2];
#pragma unroll
            for (int jp = 0; jp < 2; jp++) {
                const uint32_t off =
                    (uint32_t)(((jp * 16 + b_lrow) * KST + kk * 16 + b_lcol) * 2);
                LDSM_X4(kbh[2 * jp][0], kbh[2 * jp][1],
                        kbh[2 * jp + 1][0], kbh[2 * jp + 1][1], kh_b + off);
                LDSM_X4(kbl[2 * jp][0], kbl[2 * jp][1],
                        kbl[2 * jp + 1][0], kbl[2 * jp + 1][1], kl_b + off);
            }
#pragma unroll
            for (int j = 0; j < 4; j++)
                mma_bf16(s[j], qh[kk], kbh[j][0], kbh[j][1]);
#pragma unroll
            for (int j = 0; j < 4; j++)
                mma_bf16(s[j], qh[kk], kbl[j][0], kbl[j][1]);
#pragma unroll
            for (int j = 0; j < 4; j++)
                mma_bf16(s[j], ql[kk], kbh[j][0], kbh[j][1]);
        }

        // raw absmax (pre-scale), scale, online softmax
        float rm0 = -1e30f, rm1 = -1e30f;
#pragma unroll
        for (int j = 0; j < 4; j++) {
#pragma unroll
            for (int r = 0; r < 4; r++) {
                raw = fmaxf(raw, fabsf(s[j][r]));
                s[j][r] *= 0.125f;
            }
            rm0 = fmaxf(rm0, fmaxf(s[j][0], s[j][1]));
            rm1 = fmaxf(rm1, fmaxf(s[j][2], s[j][3]));
        }
        rm0 = fmaxf(rm0, __shfl_xor_sync(0xffffffffu, rm0, 1));
        rm0 = fmaxf(rm0, __shfl_xor_sync(0xffffffffu, rm0, 2));
        rm1 = fmaxf(rm1, __shfl_xor_sync(0xffffffffu, rm1, 1));
        rm1 = fmaxf(rm1, __shfl_xor_sync(0xffffffffu, rm1, 2));
        const float mn0 = fmaxf(m0, rm0), mn1 = fmaxf(m1, rm1);
        const float f0 = __expf(m0 - mn0), f1 = __expf(m1 - mn1);
        float ps0 = 0.f, ps1 = 0.f;
#pragma unroll
        for (int j = 0; j < 4; j++) {
            s[j][0] = __expf(s[j][0] - mn0);
            s[j][1] = __expf(s[j][1] - mn0);
            s[j][2] = __expf(s[j][2] - mn1);
            s[j][3] = __expf(s[j][3] - mn1);
            ps0 += s[j][0] + s[j][1];
            ps1 += s[j][2] + s[j][3];
        }
        ps0 += __shfl_xor_sync(0xffffffffu, ps0, 1);
        ps0 += __shfl_xor_sync(0xffffffffu, ps0, 2);
        ps1 += __shfl_xor_sync(0xffffffffu, ps1, 1);
        ps1 += __shfl_xor_sync(0xffffffffu, ps1, 2);
        l0 = l0 * f0 + ps0;
        l1 = l1 * f1 + ps1;
        m0 = mn0; m1 = mn1;
#pragma unroll
        for (int j = 0; j < 8; j++) {
            o[j][0] *= f0; o[j][1] *= f0;
            o[j][2] *= f1; o[j][3] *= f1;
        }

        // P -> split bf16 fragments (16x32 P)
        uint32_t ph[4][2], pl[4][2];
#pragma unroll
        for (int j = 0; j < 4; j++) {
            uint32_t p0 = packb(s[j][0], s[j][1]);
            uint32_t p1 = packb(s[j][2], s[j][3]);
            __nv_bfloat162 b0 = *(__nv_bfloat162*)&p0;
            __nv_bfloat162 b1 = *(__nv_bfloat162*)&p1;
            ph[j][0] = p0; ph[j][1] = p1;
            pl[j][0] = packb(s[j][0] - __bfloat162float(b0.x),
                             s[j][1] - __bfloat162float(b0.y));
            pl[j][1] = packb(s[j][2] - __bfloat162float(b1.x),
                             s[j][3] - __bfloat162float(b1.y));
        }

        // O += P V (split, 3 passes, pass-major); V frags via ldmatrix.trans
#pragma unroll
        for (int kk = 0; kk < 2; kk++) {
            uint32_t pah[4] = {ph[2 * kk][0], ph[2 * kk][1],
                               ph[2 * kk + 1][0], ph[2 * kk + 1][1]};
            uint32_t pal[4] = {pl[2 * kk][0], pl[2 * kk][1],
                               pl[2 * kk + 1][0], pl[2 * kk + 1][1]};
            uint32_t vbh[8][2], vbl[8][2];
#pragma unroll
            for (int jp = 0; jp < 4; jp++) {
                const uint32_t off =
                    (uint32_t)(((kk * 16 + v_lrow) * KST + jp * 16 + v_lcol) * 2);
                LDSM_X4_T(vbh[2 * jp][0], vbh[2 * jp][1],
                          vbh[2 * jp + 1][0], vbh[2 * jp + 1][1], vh_b + off);
                LDSM_X4_T(vbl[2 * jp][0], vbl[2 * jp][1],
                          vbl[2 * jp + 1][0], vbl[2 * jp + 1][1], vl_b + off);
            }
#pragma unroll
            for (int j = 0; j < 8; j++)
                mma_bf16(o[j], pah, vbh[j][0], vbh[j][1]);
#pragma unroll
            for (int j = 0; j < 8; j++)
                mma_bf16(o[j], pah, vbl[j][0], vbl[j][1]);
#pragma unroll
            for (int j = 0; j < 8; j++)
                mma_bf16(o[j], pal, vbh[j][0], vbh[j][1]);
        }
        __syncthreads();
        st = (st + 1 >= 3) ? 0 : st + 1;
    }
#undef ATTN_LOAD_STAGE

    // epilogue
    const float i0 = 1.f / l0, i1 = 1.f / l1;
    const int r0g = q0 + wid * 16 + g;
    const int r1g = r0g + 8;
    const size_t ob0 = ((size_t)b * SEQ + r0g) * DMODEL + h * HDIM;
    const size_t ob1 = ((size_t)b * SEQ + r1g) * DMODEL + h * HDIM;
#pragma unroll
    for (int j = 0; j < 8; j++) {
        const int d = 8 * j + 2 * t;
        float2 w0 = {o[j][0] * i0, o[j][1] * i0};
        float2 w1 = {o[j][2] * i1, o[j][3] * i1};
        *(float2*)(out + ob0 + d) = w0;
        *(float2*)(out + ob1 + d) = w1;
    }
    atomicMax(&s_raw, __float_as_uint(raw));
    atomicMax(&s_aw, __float_as_uint(fmaxf(i0, i1)));
    __syncthreads();
    if (tid == 0) {
        atomicMax(&g_mx[2], s_raw);
        atomicMax(&g_mx[3], s_aw);
    }
}

// ---------------- finalize scalars ----------------
__global__ void finalize_kernel(float* __restrict__ out, int base)
{
    if (threadIdx.x == 0) {
        const float qm  = __uint_as_float(g_mx[0]);
        const float km  = __uint_as_float(g_mx[1]);
        const float qkm = __uint_as_float(g_mx[2]);
        const float awm = __uint_as_float(g_mx[3]);
        const float vm  = __uint_as_float(g_mx[4]);
        out[base + 0] = qm;
        out[base + 1] = km;
        out[base + 2] = qkm;
        out[base + 3] = awm;
        out[base + 4] = vm;
        out[base + 5] = awm;  // v_out_max (faithful source bug)
    }
}

// ---------------- launch ----------------
extern "C" void kernel_launch(void* const* d_in, const int* in_sizes, int n_in,
                              void* d_out, int out_size)
{
    const float* X  = (const float*)d_in[0];
    const float* Wq = (const float*)d_in[1];
    const float* bq = (const float*)d_in[2];
    const float* Wk = (const float*)d_in[3];
    const float* bk = (const float*)d_in[4];
    const float* Wv = (const float*)d_in[5];
    const float* bv = (const float*)d_in[6];
    float* out = (float*)d_out;

    cudaFuncSetAttribute(qkv_gemm_mma,
                         cudaFuncAttributeMaxDynamicSharedMemorySize,
                         GEMM_SMEM_BYTES);
    cudaFuncSetAttribute(attn_mma,
                         cudaFuncAttributeMaxDynamicSharedMemorySize,
                         ATTN_SMEM_BYTES);

    init_kernel<<<1, 32>>>();                                           // 0
    convert_x<<<MROWS * DMODEL / 4 / 256, 256>>>(X);                    // 1
    convert_w<<<dim3(DMODEL * DMODEL / 4 / 256, 1, 3), 256>>>(Wq, Wk, Wv); // 2
    qkv_gemm_mma<<<dim3(DMODEL / 128, MROWS / 128, 3), 512,
                   GEMM_SMEM_BYTES>>>(bq, bk, bv);                      // 3
    spacer_kernel<<<1, 32>>>();                                         // 4
    attn_mma<<<dim3(SEQ / 128, BATCH * HEADS), 256,
               ATTN_SMEM_BYTES>>>(out);                                 // 5
    finalize_kernel<<<1, 32>>>(out, out_size - 6);                      // 6
}

// round 8
// speedup vs baseline: 5.1362x; 1.4060x over previous
#include <cuda_runtime.h>
#include <cuda_fp16.h>
#include <cstdint>

// Problem constants: B=2, S=2048, DM=1024, H=16, DH=64
#define BATCH 2
#define SEQ 2048
#define DMODEL 1024
#define HEADS 16
#define HDIM 64
#define MROWS (BATCH*SEQ)                 // 4096
#define QKV_ELEMS (BATCH*HEADS*SEQ*HDIM)  // 4,194,304

// ---------------- device scratch (fp16) ----------------
__device__ __half g_x16[MROWS * DMODEL];
__device__ __half g_whi[3 * DMODEL * DMODEL];
__device__ __half g_wlo[3 * DMODEL * DMODEL];
__device__ __half g_q16[QKV_ELEMS];
__device__ __half g_khi[QKV_ELEMS], g_klo[QKV_ELEMS];
__device__ __half g_vhi[QKV_ELEMS], g_vlo[QKV_ELEMS];
// absmax slots: 0=q 1=k 2=qk_raw 3=aw 4=v
__device__ unsigned g_mx[5];

__global__ void init_kernel() {
    if (threadIdx.x < 5) g_mx[threadIdx.x] = 0u;
}
__global__ void spacer_kernel() {}   // shifts attn to launch idx 5 for ncu -s 5

// ---------------- helpers ----------------
__device__ __forceinline__ void mma_f16(float (&c)[4], const uint32_t (&a)[4],
                                        uint32_t b0, uint32_t b1) {
    asm volatile(
        "mma.sync.aligned.m16n8k16.row.col.f32.f16.f16.f32 "
        "{%0,%1,%2,%3}, {%4,%5,%6,%7}, {%8,%9}, {%0,%1,%2,%3};"
        : "+f"(c[0]), "+f"(c[1]), "+f"(c[2]), "+f"(c[3])
        : "r"(a[0]), "r"(a[1]), "r"(a[2]), "r"(a[3]), "r"(b0), "r"(b1));
}
__device__ __forceinline__ uint32_t packh(float lo, float hi) {
    uint32_t r;
    asm("cvt.rn.f16x2.f32 %0, %1, %2;" : "=r"(r) : "f"(hi), "f"(lo));
    return r;
}
__device__ __forceinline__ uint32_t smem_u32(const void* p) {
    uint32_t a;
    asm("{ .reg .u64 t; cvta.to.shared.u64 t, %1; cvt.u32.u64 %0, t; }"
        : "=r"(a) : "l"(p));
    return a;
}
#define LDSM_X4(r0, r1, r2, r3, addr) \
    asm volatile("ldmatrix.sync.aligned.m8n8.x4.shared.b16 {%0,%1,%2,%3}, [%4];" \
                 : "=r"(r0), "=r"(r1), "=r"(r2), "=r"(r3) : "r"(addr))
#define LDSM_X4_T(r0, r1, r2, r3, addr) \
    asm volatile("ldmatrix.sync.aligned.m8n8.x4.trans.shared.b16 {%0,%1,%2,%3}, [%4];" \
                 : "=r"(r0), "=r"(r1), "=r"(r2), "=r"(r3) : "r"(addr))
#define CP_ASYNC16(dst, src) \
    asm volatile("cp.async.cg.shared.global [%0], [%1], 16;" \
                 :: "r"(dst), "l"(src))
#define CP_COMMIT() asm volatile("cp.async.commit_group;" ::: "memory")
#define CP_WAIT1() asm volatile("cp.async.wait_group 1;" ::: "memory")

// ---------------- fp32 -> fp16 conversion ----------------
__global__ __launch_bounds__(256) void convert_x(const float* __restrict__ X) {
    size_t i4 = ((size_t)blockIdx.x * 256 + threadIdx.x) * 4;
    float4 v = *(const float4*)(X + i4);
    *(__half2*)(g_x16 + i4 + 0) = __floats2half2_rn(v.x, v.y);
    *(__half2*)(g_x16 + i4 + 2) = __floats2half2_rn(v.z, v.w);
}

__global__ __launch_bounds__(256) void convert_w(
    const float* __restrict__ Wq, const float* __restrict__ Wk,
    const float* __restrict__ Wv) {
    const int z = blockIdx.z;
    const float* W = (z == 0) ? Wq : (z == 1) ? Wk : Wv;
    size_t base = (size_t)z * DMODEL * DMODEL;
    size_t i4 = ((size_t)blockIdx.x * 256 + threadIdx.x) * 4;
    float4 v = *(const float4*)(W + i4);
    float f[4] = {v.x, v.y, v.z, v.w};
    __half h[4], l[4];
#pragma unroll
    for (int j = 0; j < 4; j++) {
        h[j] = __float2half_rn(f[j]);
        l[j] = __float2half_rn(f[j] - __half2float(h[j]));
    }
    *(__half2*)(g_whi + base + i4 + 0) = __half2(h[0], h[1]);
    *(__half2*)(g_whi + base + i4 + 2) = __half2(h[2], h[3]);
    *(__half2*)(g_wlo + base + i4 + 0) = __half2(l[0], l[1]);
    *(__half2*)(g_wlo + base + i4 + 2) = __half2(l[2], l[3]);
}

// ------- fp16 2-pass QKV GEMM: C = X16·(Whi+Wlo), 512 thr, warp tile 32x32 --
#define GKC 32
#define GST 40                           // smem row stride (fp16), 80B
#define GTILE_B (128 * GST * 2)          // 10240 B per tile
#define GSTG_B (3 * GTILE_B)             // A Bh Bl = 30720 B per stage
#define GEMM_SMEM_BYTES (3 * GSTG_B)     // 92160

__global__ __launch_bounds__(512, 1) void qkv_gemm_mma(
    const float* __restrict__ bq, const float* __restrict__ bk,
    const float* __restrict__ bv)
{
    extern __shared__ __half sm[];
    __shared__ unsigned s_amax;

    const int tid = threadIdx.x;
    const int wid = tid >> 5;
    const int lane = tid & 31;
    const int g = lane >> 2;
    const int t = lane & 3;
    const int wm = wid & 3;           // 0..3 (32 rows each)
    const int wn = wid >> 2;          // 0..3 (32 cols each)

    const int z = blockIdx.z;
    const int m0 = blockIdx.y * 128;
    const int n0 = blockIdx.x * 128;

    const float* __restrict__ bias = (z == 0) ? bq : (z == 1) ? bk : bv;
    __half* __restrict__ Ohi = (z == 0) ? g_q16 : (z == 1) ? g_khi : g_vhi;
    __half* __restrict__ Olo = (z == 0) ? (__half*)nullptr
                                        : (z == 1) ? g_klo : g_vlo;
    const int mslot = (z == 0) ? 0 : (z == 1) ? 1 : 4;

    const __half* __restrict__ A  = g_x16 + (size_t)m0 * DMODEL;
    const __half* __restrict__ Bh = g_whi + (size_t)z * DMODEL * DMODEL + (size_t)n0 * DMODEL;
    const __half* __restrict__ Bl = g_wlo + (size_t)z * DMODEL * DMODEL + (size_t)n0 * DMODEL;

    if (tid == 0) s_amax = 0u;

    const uint32_t sbase = smem_u32(sm);
    const int a_lrow = lane & 15;
    const int a_lcol = ((lane >> 4) & 1) * 8;
    const int b_lrow = (lane & 7) + (lane >> 4) * 8;
    const int b_lcol = ((lane >> 3) & 1) * 8;

    float c[2][4][4];
#pragma unroll
    for (int mt = 0; mt < 2; mt++)
#pragma unroll
        for (int nt = 0; nt < 4; nt++)
#pragma unroll
            for (int r = 0; r < 4; r++) c[mt][nt][r] = 0.f;

    const int NCH = DMODEL / GKC;     // 32

#define GEMM_LOAD_STAGE(ch, st) do {                                          \
        const int k0 = (ch) * GKC;                                            \
        const uint32_t stb = sbase + (uint32_t)(st) * GSTG_B;                 \
        const int row = tid >> 2, cu = tid & 3;                               \
        const size_t go = (size_t)row * DMODEL + k0 + cu * 8;                 \
        const uint32_t so = stb + (uint32_t)(row * GST + cu * 8) * 2;         \
        CP_ASYNC16(so + 0 * GTILE_B, (const void*)(A + go));                  \
        CP_ASYNC16(so + 1 * GTILE_B, (const void*)(Bh + go));                 \
        CP_ASYNC16(so + 2 * GTILE_B, (const void*)(Bl + go));                 \
    } while (0)

    GEMM_LOAD_STAGE(0, 0); CP_COMMIT();
    GEMM_LOAD_STAGE(1, 1); CP_COMMIT();

    int st = 0;
    for (int ch = 0; ch < NCH; ch++) {
        CP_WAIT1();
        __syncthreads();
        if (ch + 2 < NCH) {
            const int st2 = (st + 2 >= 3) ? st - 1 : st + 2;
            GEMM_LOAD_STAGE(ch + 2, st2);
        }
        CP_COMMIT();

        const uint32_t bA  = sbase + (uint32_t)st * GSTG_B;
        const uint32_t bBh = bA + GTILE_B;
        const uint32_t bBl = bBh + GTILE_B;
#pragma unroll
        for (int ks = 0; ks < 2; ks++) {
            const int kc = ks * 16;
            uint32_t ah[2][4];
#pragma unroll
            for (int mt = 0; mt < 2; mt++) {
                const uint32_t off =
                    (uint32_t)(((wm * 32 + mt * 16 + a_lrow) * GST + kc + a_lcol) * 2);
                LDSM_X4(ah[mt][0], ah[mt][1], ah[mt][2], ah[mt][3], bA + off);
            }
            uint32_t bhf[4][2], blf[4][2];
#pragma unroll
            for (int ntp = 0; ntp < 2; ntp++) {
                const uint32_t off =
                    (uint32_t)(((wn * 32 + ntp * 16 + b_lrow) * GST + kc + b_lcol) * 2);
                LDSM_X4(bhf[2 * ntp][0], bhf[2 * ntp][1],
                        bhf[2 * ntp + 1][0], bhf[2 * ntp + 1][1], bBh + off);
                LDSM_X4(blf[2 * ntp][0], blf[2 * ntp][1],
                        blf[2 * ntp + 1][0], blf[2 * ntp + 1][1], bBl + off);
            }
#pragma unroll
            for (int mt = 0; mt < 2; mt++)
#pragma unroll
                for (int nt = 0; nt < 4; nt++)
                    mma_f16(c[mt][nt], ah[mt], bhf[nt][0], bhf[nt][1]);
#pragma unroll
            for (int mt = 0; mt < 2; mt++)
#pragma unroll
                for (int nt = 0; nt < 4; nt++)
                    mma_f16(c[mt][nt], ah[mt], blf[nt][0], blf[nt][1]);
        }
        __syncthreads();
        st = (st + 1 >= 3) ? 0 : st + 1;
    }
#undef GEMM_LOAD_STAGE

    // epilogue: bias, absmax, fp16 hi(+lo for K/V), layout [BH][S][64]
    float lmax = 0.f;
#pragma unroll
    for (int nt = 0; nt < 4; nt++) {
        const int n = n0 + wn * 32 + nt * 8 + 2 * t;
        const float bn0 = bias[n], bn1 = bias[n + 1];
        const int h = n >> 6, d = n & 63;
#pragma unroll
        for (int mt = 0; mt < 2; mt++) {
            const int mr0 = m0 + wm * 32 + mt * 16 + g;
            const int mr1 = mr0 + 8;
            float v0 = c[mt][nt][0] + bn0;
            float v1 = c[mt][nt][1] + bn1;
            float v2 = c[mt][nt][2] + bn0;
            float v3 = c[mt][nt][3] + bn1;
            lmax = fmaxf(lmax, fmaxf(fmaxf(fabsf(v0), fabsf(v1)),
                                     fmaxf(fabsf(v2), fabsf(v3))));
            const int bb0 = mr0 >> 11, s0 = mr0 & 2047;
            const int bb1 = mr1 >> 11, s1 = mr1 & 2047;
            const size_t o0 = (((size_t)(bb0 * HEADS + h)) * SEQ + s0) * HDIM + d;
            const size_t o1 = (((size_t)(bb1 * HEADS + h)) * SEQ + s1) * HDIM + d;
            uint32_t h0 = packh(v0, v1), h1 = packh(v2, v3);
            *(uint32_t*)(Ohi + o0) = h0;
            *(uint32_t*)(Ohi + o1) = h1;
            if (z != 0) {
                __half2 hb0 = *(__half2*)&h0;
                __half2 hb1 = *(__half2*)&h1;
                uint32_t l0 = packh(v0 - __half2float(hb0.x),
                                    v1 - __half2float(hb0.y));
                uint32_t l1 = packh(v2 - __half2float(hb1.x),
                                    v3 - __half2float(hb1.y));
                *(uint32_t*)(Olo + o0) = l0;
                *(uint32_t*)(Olo + o1) = l1;
            }
        }
    }
    atomicMax(&s_amax, __float_as_uint(lmax));
    __syncthreads();
    if (tid == 0) atomicMax(&g_mx[mslot], s_amax);
}

// ------ flash attention: fp16 2-pass, KV tile 32, 3-stage cp.async ---------
#define AKV 32                            // kv rows per tile
#define KST 72                            // smem row stride (fp16), 144B
#define ATILE_B (AKV * KST * 2)           // 4608 B per tile
#define ASTG_B (4 * ATILE_B)              // kh kl vh vl = 18432 B per stage
#define ATTN_SMEM_BYTES (3 * ASTG_B)      // 55296

__global__ __launch_bounds__(256, 2) void attn_mma(float* __restrict__ out)
{
    extern __shared__ __half asm_buf[];
    __shared__ unsigned s_raw, s_aw;

    const int tid = threadIdx.x;
    const int wid = tid >> 5;
    const int lane = tid & 31;
    const int g = lane >> 2;
    const int t = lane & 3;

    const int bh = blockIdx.y;
    const int b = bh >> 4, h = bh & 15;
    const int q0 = blockIdx.x * 128;

    if (tid == 0) { s_raw = 0u; s_aw = 0u; }

    const uint32_t sbase = smem_u32(asm_buf);
    const int b_lrow = (lane & 7) + (lane >> 4) * 8;
    const int b_lcol = ((lane >> 3) & 1) * 8;
    const int v_lrow = (lane & 7) + ((lane >> 3) & 1) * 8;
    const int v_lcol = (lane >> 4) * 8;

    // Q fragments (fp16, single precision level), loaded once
    const size_t qbase = ((size_t)bh * SEQ + q0 + wid * 16) * HDIM;
    const __half* Qh = g_q16 + qbase;
    uint32_t qh[4][4];
#pragma unroll
    for (int kk = 0; kk < 4; kk++) {
        const int c0 = kk * 16 + 2 * t;
        qh[kk][0] = *(const uint32_t*)(Qh + g * HDIM + c0);
        qh[kk][1] = *(const uint32_t*)(Qh + (g + 8) * HDIM + c0);
        qh[kk][2] = *(const uint32_t*)(Qh + g * HDIM + c0 + 8);
        qh[kk][3] = *(const uint32_t*)(Qh + (g + 8) * HDIM + c0 + 8);
    }

    const __half* Kh = g_khi + (size_t)bh * SEQ * HDIM;
    const __half* Kl = g_klo + (size_t)bh * SEQ * HDIM;
    const __half* Vh = g_vhi + (size_t)bh * SEQ * HDIM;
    const __half* Vl = g_vlo + (size_t)bh * SEQ * HDIM;

    float o[8][4];
#pragma unroll
    for (int j = 0; j < 8; j++)
#pragma unroll
        for (int r = 0; r < 4; r++) o[j][r] = 0.f;
    float m0 = -1e30f, m1 = -1e30f, l0 = 0.f, l1 = 0.f, raw = 0.f;

    const int NKV = SEQ / AKV;  // 64

#define ATTN_LOAD_STAGE(kv, st) do {                                          \
        const int base_row = (kv) * AKV;                                      \
        const uint32_t stb = sbase + (uint32_t)(st) * ASTG_B;                 \
        const int row = tid >> 3, du = tid & 7;                               \
        const size_t go = (size_t)(base_row + row) * HDIM + du * 8;           \
        const uint32_t so = stb + (uint32_t)(row * KST + du * 8) * 2;         \
        CP_ASYNC16(so + 0 * ATILE_B, (const void*)(Kh + go));                 \
        CP_ASYNC16(so + 1 * ATILE_B, (const void*)(Kl + go));                 \
        CP_ASYNC16(so + 2 * ATILE_B, (const void*)(Vh + go));                 \
        CP_ASYNC16(so + 3 * ATILE_B, (const void*)(Vl + go));                 \
    } while (0)

    ATTN_LOAD_STAGE(0, 0); CP_COMMIT();
    ATTN_LOAD_STAGE(1, 1); CP_COMMIT();

    int st = 0;
    for (int kv = 0; kv < NKV; kv++) {
        CP_WAIT1();
        __syncthreads();
        if (kv + 2 < NKV) {
            const int st2 = (st + 2 >= 3) ? st - 1 : st + 2;
            ATTN_LOAD_STAGE(kv + 2, st2);
        }
        CP_COMMIT();

        const uint32_t kh_b = sbase + (uint32_t)st * ASTG_B;
        const uint32_t kl_b = kh_b + ATILE_B;
        const uint32_t vh_b = kl_b + ATILE_B;
        const uint32_t vl_b = vh_b + ATILE_B;

        // S = Q·(Kh+Kl)^T  (2 passes, pass-major)
        float s[4][4];
#pragma unroll
        for (int j = 0; j < 4; j++)
#pragma unroll
            for (int r = 0; r < 4; r++) s[j][r] = 0.f;
#pragma unroll
        for (int kk = 0; kk < 4; kk++) {
            uint32_t kbh[4][2], kbl[4][2];
#pragma unroll
            for (int jp = 0; jp < 2; jp++) {
                const uint32_t off =
                    (uint32_t)(((jp * 16 + b_lrow) * KST + kk * 16 + b_lcol) * 2);
                LDSM_X4(kbh[2 * jp][0], kbh[2 * jp][1],
                        kbh[2 * jp + 1][0], kbh[2 * jp + 1][1], kh_b + off);
                LDSM_X4(kbl[2 * jp][0], kbl[2 * jp][1],
                        kbl[2 * jp + 1][0], kbl[2 * jp + 1][1], kl_b + off);
            }
#pragma unroll
            for (int j = 0; j < 4; j++)
                mma_f16(s[j], qh[kk], kbh[j][0], kbh[j][1]);
#pragma unroll
            for (int j = 0; j < 4; j++)
                mma_f16(s[j], qh[kk], kbl[j][0], kbl[j][1]);
        }

        // raw absmax (pre-scale), scale, online softmax
        float rm0 = -1e30f, rm1 = -1e30f;
#pragma unroll
        for (int j = 0; j < 4; j++) {
#pragma unroll
            for (int r = 0; r < 4; r++) {
                raw = fmaxf(raw, fabsf(s[j][r]));
                s[j][r] *= 0.125f;
            }
            rm0 = fmaxf(rm0, fmaxf(s[j][0], s[j][1]));
            rm1 = fmaxf(rm1, fmaxf(s[j][2], s[j][3]));
        }
        rm0 = fmaxf(rm0, __shfl_xor_sync(0xffffffffu, rm0, 1));
        rm0 = fmaxf(rm0, __shfl_xor_sync(0xffffffffu, rm0, 2));
        rm1 = fmaxf(rm1, __shfl_xor_sync(0xffffffffu, rm1, 1));
        rm1 = fmaxf(rm1, __shfl_xor_sync(0xffffffffu, rm1, 2));
        const float mn0 = fmaxf(m0, rm0), mn1 = fmaxf(m1, rm1);
        const float f0 = __expf(m0 - mn0), f1 = __expf(m1 - mn1);
        float ps0 = 0.f, ps1 = 0.f;
#pragma unroll
        for (int j = 0; j < 4; j++) {
            s[j][0] = __expf(s[j][0] - mn0);
            s[j][1] = __expf(s[j][1] - mn0);
            s[j][2] = __expf(s[j][2] - mn1);
            s[j][3] = __expf(s[j][3] - mn1);
            ps0 += s[j][0] + s[j][1];
            ps1 += s[j][2] + s[j][3];
        }
        ps0 += __shfl_xor_sync(0xffffffffu, ps0, 1);
        ps0 += __shfl_xor_sync(0xffffffffu, ps0, 2);
        ps1 += __shfl_xor_sync(0xffffffffu, ps1, 1);
        ps1 += __shfl_xor_sync(0xffffffffu, ps1, 2);
        l0 = l0 * f0 + ps0;
        l1 = l1 * f1 + ps1;
        m0 = mn0; m1 = mn1;
#pragma unroll
        for (int j = 0; j < 8; j++) {
            o[j][0] *= f0; o[j][1] *= f0;
            o[j][2] *= f1; o[j][3] *= f1;
        }

        // P -> fp16 fragments (single precision level)
        uint32_t ph[4][2];
#pragma unroll
        for (int j = 0; j < 4; j++) {
            ph[j][0] = packh(s[j][0], s[j][1]);
            ph[j][1] = packh(s[j][2], s[j][3]);
        }

        // O += P·(Vh+Vl)  (2 passes, pass-major); V frags via ldmatrix.trans
#pragma unroll
        for (int kk = 0; kk < 2; kk++) {
            uint32_t pah[4] = {ph[2 * kk][0], ph[2 * kk][1],
                               ph[2 * kk + 1][0], ph[2 * kk + 1][1]};
            uint32_t vbh[8][2], vbl[8][2];
#pragma unroll
            for (int jp = 0; jp < 4; jp++) {
                const uint32_t off =
                    (uint32_t)(((kk * 16 + v_lrow) * KST + jp * 16 + v_lcol) * 2);
                LDSM_X4_T(vbh[2 * jp][0], vbh[2 * jp][1],
                          vbh[2 * jp + 1][0], vbh[2 * jp + 1][1], vh_b + off);
                LDSM_X4_T(vbl[2 * jp][0], vbl[2 * jp][1],
                          vbl[2 * jp + 1][0], vbl[2 * jp + 1][1], vl_b + off);
            }
#pragma unroll
            for (int j = 0; j < 8; j++)
                mma_f16(o[j], pah, vbh[j][0], vbh[j][1]);
#pragma unroll
            for (int j = 0; j < 8; j++)
                mma_f16(o[j], pah, vbl[j][0], vbl[j][1]);
        }
        __syncthreads();
        st = (st + 1 >= 3) ? 0 : st + 1;
    }
#undef ATTN_LOAD_STAGE

    // epilogue
    const float i0 = 1.f / l0, i1 = 1.f / l1;
    const int r0g = q0 + wid * 16 + g;
    const int r1g = r0g + 8;
    const size_t ob0 = ((size_t)b * SEQ + r0g) * DMODEL + h * HDIM;
    const size_t ob1 = ((size_t)b * SEQ + r1g) * DMODEL + h * HDIM;
#pragma unroll
    for (int j = 0; j < 8; j++) {
        const int d = 8 * j + 2 * t;
        float2 w0 = {o[j][0] * i0, o[j][1] * i0};
        float2 w1 = {o[j][2] * i1, o[j][3] * i1};
        *(float2*)(out + ob0 + d) = w0;
        *(float2*)(out + ob1 + d) = w1;
    }
    atomicMax(&s_raw, __float_as_uint(raw));
    atomicMax(&s_aw, __float_as_uint(fmaxf(i0, i1)));
    __syncthreads();
    if (tid == 0) {
        atomicMax(&g_mx[2], s_raw);
        atomicMax(&g_mx[3], s_aw);
    }
}

// ---------------- finalize scalars ----------------
__global__ void finalize_kernel(float* __restrict__ out, int base)
{
    if (threadIdx.x == 0) {
        const float qm  = __uint_as_float(g_mx[0]);
        const float km  = __uint_as_float(g_mx[1]);
        const float qkm = __uint_as_float(g_mx[2]);
        const float awm = __uint_as_float(g_mx[3]);
        const float vm  = __uint_as_float(g_mx[4]);
        out[base + 0] = qm;
        out[base + 1] = km;
        out[base + 2] = qkm;
        out[base + 3] = awm;
        out[base + 4] = vm;
        out[base + 5] = awm;  // v_out_max (faithful source bug)
    }
}

// ---------------- launch ----------------
extern "C" void kernel_launch(void* const* d_in, const int* in_sizes, int n_in,
                              void* d_out, int out_size)
{
    const float* X  = (const float*)d_in[0];
    const float* Wq = (const float*)d_in[1];
    const float* bq = (const float*)d_in[2];
    const float* Wk = (const float*)d_in[3];
    const float* bk = (const float*)d_in[4];
    const float* Wv = (const float*)d_in[5];
    const float* bv = (const float*)d_in[6];
    float* out = (float*)d_out;

    cudaFuncSetAttribute(qkv_gemm_mma,
                         cudaFuncAttributeMaxDynamicSharedMemorySize,
                         GEMM_SMEM_BYTES);
    cudaFuncSetAttribute(attn_mma,
                         cudaFuncAttributeMaxDynamicSharedMemorySize,
                         ATTN_SMEM_BYTES);

    init_kernel<<<1, 32>>>();                                           // 0
    convert_x<<<MROWS * DMODEL / 4 / 256, 256>>>(X);                    // 1
    convert_w<<<dim3(DMODEL * DMODEL / 4 / 256, 1, 3), 256>>>(Wq, Wk, Wv); // 2
    qkv_gemm_mma<<<dim3(DMODEL / 128, MROWS / 128, 3), 512,
                   GEMM_SMEM_BYTES>>>(bq, bk, bv);                      // 3
    spacer_kernel<<<1, 32>>>();                                         // 4
    attn_mma<<<dim3(SEQ / 128, BATCH * HEADS), 256,
               ATTN_SMEM_BYTES>>>(out);                                 // 5
    finalize_kernel<<<1, 32>>>(out, out_size - 6);                      // 6
}

// round 9
// speedup vs baseline: 5.6697x; 1.1039x over previous
#include <cuda_runtime.h>
#include <cuda_fp16.h>
#include <cstdint>

// Problem constants: B=2, S=2048, DM=1024, H=16, DH=64
#define BATCH 2
#define SEQ 2048
#define DMODEL 1024
#define HEADS 16
#define HDIM 64
#define MROWS (BATCH*SEQ)                 // 4096
#define QKV_ELEMS (BATCH*HEADS*SEQ*HDIM)  // 4,194,304

// ---------------- device scratch (fp16) ----------------
__device__ __half g_x16[MROWS * DMODEL];
__device__ __half g_whi[3 * DMODEL * DMODEL];
__device__ __half g_wlo[3 * DMODEL * DMODEL];
__device__ __half g_q16[QKV_ELEMS];
__device__ __half g_khi[QKV_ELEMS], g_klo[QKV_ELEMS];
__device__ __half g_vhi[QKV_ELEMS], g_vlo[QKV_ELEMS];
// absmax slots: 0=q 1=k 2=qk_raw 3=aw 4=v
__device__ unsigned g_mx[5];

__global__ void init_kernel() {
    if (threadIdx.x < 5) g_mx[threadIdx.x] = 0u;
}
__global__ void spacer_kernel() {}   // shifts attn to launch idx 5 for ncu -s 5

// ---------------- helpers ----------------
__device__ __forceinline__ void mma_f16(float (&c)[4], const uint32_t (&a)[4],
                                        uint32_t b0, uint32_t b1) {
    asm volatile(
        "mma.sync.aligned.m16n8k16.row.col.f32.f16.f16.f32 "
        "{%0,%1,%2,%3}, {%4,%5,%6,%7}, {%8,%9}, {%0,%1,%2,%3};"
        : "+f"(c[0]), "+f"(c[1]), "+f"(c[2]), "+f"(c[3])
        : "r"(a[0]), "r"(a[1]), "r"(a[2]), "r"(a[3]), "r"(b0), "r"(b1));
}
__device__ __forceinline__ uint32_t packh(float lo, float hi) {
    uint32_t r;
    asm("cvt.rn.f16x2.f32 %0, %1, %2;" : "=r"(r) : "f"(hi), "f"(lo));
    return r;
}
__device__ __forceinline__ uint32_t smem_u32(const void* p) {
    uint32_t a;
    asm("{ .reg .u64 t; cvta.to.shared.u64 t, %1; cvt.u32.u64 %0, t; }"
        : "=r"(a) : "l"(p));
    return a;
}
#define LDSM_X4(r0, r1, r2, r3, addr) \
    asm volatile("ldmatrix.sync.aligned.m8n8.x4.shared.b16 {%0,%1,%2,%3}, [%4];" \
                 : "=r"(r0), "=r"(r1), "=r"(r2), "=r"(r3) : "r"(addr))
#define LDSM_X4_T(r0, r1, r2, r3, addr) \
    asm volatile("ldmatrix.sync.aligned.m8n8.x4.trans.shared.b16 {%0,%1,%2,%3}, [%4];" \
                 : "=r"(r0), "=r"(r1), "=r"(r2), "=r"(r3) : "r"(addr))
#define CP_ASYNC16(dst, src) \
    asm volatile("cp.async.cg.shared.global [%0], [%1], 16;" \
                 :: "r"(dst), "l"(src))
#define CP_COMMIT() asm volatile("cp.async.commit_group;" ::: "memory")
#define CP_WAIT1() asm volatile("cp.async.wait_group 1;" ::: "memory")

// ---------------- fp32 -> fp16 conversion ----------------
__global__ __launch_bounds__(256) void convert_x(const float* __restrict__ X) {
    size_t i4 = ((size_t)blockIdx.x * 256 + threadIdx.x) * 4;
    float4 v = *(const float4*)(X + i4);
    *(__half2*)(g_x16 + i4 + 0) = __floats2half2_rn(v.x, v.y);
    *(__half2*)(g_x16 + i4 + 2) = __floats2half2_rn(v.z, v.w);
}

__global__ __launch_bounds__(256) void convert_w(
    const float* __restrict__ Wq, const float* __restrict__ Wk,
    const float* __restrict__ Wv) {
    const int z = blockIdx.z;
    const float* W = (z == 0) ? Wq : (z == 1) ? Wk : Wv;
    size_t base = (size_t)z * DMODEL * DMODEL;
    size_t i4 = ((size_t)blockIdx.x * 256 + threadIdx.x) * 4;
    float4 v = *(const float4*)(W + i4);
    float f[4] = {v.x, v.y, v.z, v.w};
    __half h[4], l[4];
#pragma unroll
    for (int j = 0; j < 4; j++) {
        h[j] = __float2half_rn(f[j]);
        l[j] = __float2half_rn(f[j] - __half2float(h[j]));
    }
    *(__half2*)(g_whi + base + i4 + 0) = __half2(h[0], h[1]);
    *(__half2*)(g_whi + base + i4 + 2) = __half2(h[2], h[3]);
    *(__half2*)(g_wlo + base + i4 + 0) = __half2(l[0], l[1]);
    *(__half2*)(g_wlo + base + i4 + 2) = __half2(l[2], l[3]);
}

// ---- fp16 2-pass QKV GEMM: 256 thr, 2 CTA/SM, warp tile 64x32 -------------
#define GKC 32
#define GST 40                           // smem row stride (fp16), 80B
#define GTILE_B (128 * GST * 2)          // 10240 B per tile
#define GSTG_B (3 * GTILE_B)             // A Bh Bl = 30720 B per stage
#define GEMM_SMEM_BYTES (3 * GSTG_B)     // 92160

__global__ __launch_bounds__(256, 2) void qkv_gemm_mma(
    const float* __restrict__ bq, const float* __restrict__ bk,
    const float* __restrict__ bv)
{
    extern __shared__ __half sm[];
    __shared__ unsigned s_amax;

    const int tid = threadIdx.x;
    const int wid = tid >> 5;
    const int lane = tid & 31;
    const int g = lane >> 2;
    const int t = lane & 3;
    const int wm = wid & 1;           // 0..1 (64 rows each)
    const int wn = wid >> 1;          // 0..3 (32 cols each)

    const int z = blockIdx.z;
    const int m0 = blockIdx.y * 128;
    const int n0 = blockIdx.x * 128;

    const float* __restrict__ bias = (z == 0) ? bq : (z == 1) ? bk : bv;
    __half* __restrict__ Ohi = (z == 0) ? g_q16 : (z == 1) ? g_khi : g_vhi;
    __half* __restrict__ Olo = (z == 0) ? (__half*)nullptr
                                        : (z == 1) ? g_klo : g_vlo;
    const int mslot = (z == 0) ? 0 : (z == 1) ? 1 : 4;

    const __half* __restrict__ A  = g_x16 + (size_t)m0 * DMODEL;
    const __half* __restrict__ Bh = g_whi + (size_t)z * DMODEL * DMODEL + (size_t)n0 * DMODEL;
    const __half* __restrict__ Bl = g_wlo + (size_t)z * DMODEL * DMODEL + (size_t)n0 * DMODEL;

    if (tid == 0) s_amax = 0u;

    const uint32_t sbase = smem_u32(sm);
    const int a_lrow = lane & 15;
    const int a_lcol = ((lane >> 4) & 1) * 8;
    const int b_lrow = (lane & 7) + (lane >> 4) * 8;
    const int b_lcol = ((lane >> 3) & 1) * 8;

    float c[4][4][4];
#pragma unroll
    for (int mt = 0; mt < 4; mt++)
#pragma unroll
        for (int nt = 0; nt < 4; nt++)
#pragma unroll
            for (int r = 0; r < 4; r++) c[mt][nt][r] = 0.f;

    const int NCH = DMODEL / GKC;     // 32

    // 256 thr: 2 x 16B cp.async per tile per thread per stage
#define GEMM_LOAD_STAGE(ch, st) do {                                          \
        const int k0 = (ch) * GKC;                                            \
        const uint32_t stb = sbase + (uint32_t)(st) * GSTG_B;                 \
        _Pragma("unroll")                                                     \
        for (int i = 0; i < 2; i++) {                                         \
            const int cid = tid + i * 256;                                    \
            const int row = cid >> 2, cu = cid & 3;                           \
            const size_t go = (size_t)row * DMODEL + k0 + cu * 8;             \
            const uint32_t so = stb + (uint32_t)(row * GST + cu * 8) * 2;     \
            CP_ASYNC16(so + 0 * GTILE_B, (const void*)(A + go));              \
            CP_ASYNC16(so + 1 * GTILE_B, (const void*)(Bh + go));             \
            CP_ASYNC16(so + 2 * GTILE_B, (const void*)(Bl + go));             \
        }                                                                     \
    } while (0)

    GEMM_LOAD_STAGE(0, 0); CP_COMMIT();
    GEMM_LOAD_STAGE(1, 1); CP_COMMIT();

    int st = 0;
    for (int ch = 0; ch < NCH; ch++) {
        CP_WAIT1();
        __syncthreads();
        if (ch + 2 < NCH) {
            const int st2 = (st + 2 >= 3) ? st - 1 : st + 2;
            GEMM_LOAD_STAGE(ch + 2, st2);
        }
        CP_COMMIT();

        const uint32_t bA  = sbase + (uint32_t)st * GSTG_B;
        const uint32_t bBh = bA + GTILE_B;
        const uint32_t bBl = bBh + GTILE_B;
#pragma unroll
        for (int ks = 0; ks < 2; ks++) {
            const int kc = ks * 16;
            uint32_t ah[4][4];
#pragma unroll
            for (int mt = 0; mt < 4; mt++) {
                const uint32_t off =
                    (uint32_t)(((wm * 64 + mt * 16 + a_lrow) * GST + kc + a_lcol) * 2);
                LDSM_X4(ah[mt][0], ah[mt][1], ah[mt][2], ah[mt][3], bA + off);
            }
            uint32_t bhf[4][2], blf[4][2];
#pragma unroll
            for (int ntp = 0; ntp < 2; ntp++) {
                const uint32_t off =
                    (uint32_t)(((wn * 32 + ntp * 16 + b_lrow) * GST + kc + b_lcol) * 2);
                LDSM_X4(bhf[2 * ntp][0], bhf[2 * ntp][1],
                        bhf[2 * ntp + 1][0], bhf[2 * ntp + 1][1], bBh + off);
                LDSM_X4(blf[2 * ntp][0], blf[2 * ntp][1],
                        blf[2 * ntp + 1][0], blf[2 * ntp + 1][1], bBl + off);
            }
#pragma unroll
            for (int mt = 0; mt < 4; mt++)
#pragma unroll
                for (int nt = 0; nt < 4; nt++)
                    mma_f16(c[mt][nt], ah[mt], bhf[nt][0], bhf[nt][1]);
#pragma unroll
            for (int mt = 0; mt < 4; mt++)
#pragma unroll
                for (int nt = 0; nt < 4; nt++)
                    mma_f16(c[mt][nt], ah[mt], blf[nt][0], blf[nt][1]);
        }
        __syncthreads();
        st = (st + 1 >= 3) ? 0 : st + 1;
    }
#undef GEMM_LOAD_STAGE

    // epilogue: bias, absmax, fp16 hi(+lo for K/V), layout [BH][S][64]
    float lmax = 0.f;
#pragma unroll
    for (int nt = 0; nt < 4; nt++) {
        const int n = n0 + wn * 32 + nt * 8 + 2 * t;
        const float bn0 = bias[n], bn1 = bias[n + 1];
        const int h = n >> 6, d = n & 63;
#pragma unroll
        for (int mt = 0; mt < 4; mt++) {
            const int mr0 = m0 + wm * 64 + mt * 16 + g;
            const int mr1 = mr0 + 8;
            float v0 = c[mt][nt][0] + bn0;
            float v1 = c[mt][nt][1] + bn1;
            float v2 = c[mt][nt][2] + bn0;
            float v3 = c[mt][nt][3] + bn1;
            lmax = fmaxf(lmax, fmaxf(fmaxf(fabsf(v0), fabsf(v1)),
                                     fmaxf(fabsf(v2), fabsf(v3))));
            const int bb0 = mr0 >> 11, s0 = mr0 & 2047;
            const int bb1 = mr1 >> 11, s1 = mr1 & 2047;
            const size_t o0 = (((size_t)(bb0 * HEADS + h)) * SEQ + s0) * HDIM + d;
            const size_t o1 = (((size_t)(bb1 * HEADS + h)) * SEQ + s1) * HDIM + d;
            uint32_t h0 = packh(v0, v1), h1 = packh(v2, v3);
            *(uint32_t*)(Ohi + o0) = h0;
            *(uint32_t*)(Ohi + o1) = h1;
            if (z != 0) {
                __half2 hb0 = *(__half2*)&h0;
                __half2 hb1 = *(__half2*)&h1;
                uint32_t l0 = packh(v0 - __half2float(hb0.x),
                                    v1 - __half2float(hb0.y));
                uint32_t l1 = packh(v2 - __half2float(hb1.x),
                                    v3 - __half2float(hb1.y));
                *(uint32_t*)(Olo + o0) = l0;
                *(uint32_t*)(Olo + o1) = l1;
            }
        }
    }
    atomicMax(&s_amax, __float_as_uint(lmax));
    __syncthreads();
    if (tid == 0) atomicMax(&g_mx[mslot], s_amax);
}

// ------ flash attention: fp16 2-pass, KV tile 32, 3-stage cp.async ---------
#define AKV 32                            // kv rows per tile
#define KST 72                            // smem row stride (fp16), 144B
#define ATILE_B (AKV * KST * 2)           // 4608 B per tile
#define ASTG_B (4 * ATILE_B)              // kh kl vh vl = 18432 B per stage
#define ATTN_SMEM_BYTES (3 * ASTG_B)      // 55296

__global__ __launch_bounds__(256, 2) void attn_mma(float* __restrict__ out)
{
    extern __shared__ __half asm_buf[];
    __shared__ unsigned s_raw, s_aw;

    const int tid = threadIdx.x;
    const int wid = tid >> 5;
    const int lane = tid & 31;
    const int g = lane >> 2;
    const int t = lane & 3;

    const int bh = blockIdx.y;
    const int b = bh >> 4, h = bh & 15;
    const int q0 = blockIdx.x * 128;

    if (tid == 0) { s_raw = 0u; s_aw = 0u; }

    const uint32_t sbase = smem_u32(asm_buf);
    const int b_lrow = (lane & 7) + (lane >> 4) * 8;
    const int b_lcol = ((lane >> 3) & 1) * 8;
    const int v_lrow = (lane & 7) + ((lane >> 3) & 1) * 8;
    const int v_lcol = (lane >> 4) * 8;

    // Q fragments (fp16, single precision level), loaded once
    const size_t qbase = ((size_t)bh * SEQ + q0 + wid * 16) * HDIM;
    const __half* Qh = g_q16 + qbase;
    uint32_t qh[4][4];
#pragma unroll
    for (int kk = 0; kk < 4; kk++) {
        const int c0 = kk * 16 + 2 * t;
        qh[kk][0] = *(const uint32_t*)(Qh + g * HDIM + c0);
        qh[kk][1] = *(const uint32_t*)(Qh + (g + 8) * HDIM + c0);
        qh[kk][2] = *(const uint32_t*)(Qh + g * HDIM + c0 + 8);
        qh[kk][3] = *(const uint32_t*)(Qh + (g + 8) * HDIM + c0 + 8);
    }

    const __half* Kh = g_khi + (size_t)bh * SEQ * HDIM;
    const __half* Kl = g_klo + (size_t)bh * SEQ * HDIM;
    const __half* Vh = g_vhi + (size_t)bh * SEQ * HDIM;
    const __half* Vl = g_vlo + (size_t)bh * SEQ * HDIM;

    float o[8][4];
#pragma unroll
    for (int j = 0; j < 8; j++)
#pragma unroll
        for (int r = 0; r < 4; r++) o[j][r] = 0.f;
    float m0 = -1e30f, m1 = -1e30f, l0 = 0.f, l1 = 0.f, raw = 0.f;

    const int NKV = SEQ / AKV;  // 64

#define ATTN_LOAD_STAGE(kv, st) do {                                          \
        const int base_row = (kv) * AKV;                                      \
        const uint32_t stb = sbase + (uint32_t)(st) * ASTG_B;                 \
        const int row = tid >> 3, du = tid & 7;                               \
        const size_t go = (size_t)(base_row + row) * HDIM + du * 8;           \
        const uint32_t so = stb + (uint32_t)(row * KST + du * 8) * 2;         \
        CP_ASYNC16(so + 0 * ATILE_B, (const void*)(Kh + go));                 \
        CP_ASYNC16(so + 1 * ATILE_B, (const void*)(Kl + go));                 \
        CP_ASYNC16(so + 2 * ATILE_B, (const void*)(Vh + go));                 \
        CP_ASYNC16(so + 3 * ATILE_B, (const void*)(Vl + go));                 \
    } while (0)

    ATTN_LOAD_STAGE(0, 0); CP_COMMIT();
    ATTN_LOAD_STAGE(1, 1); CP_COMMIT();

    int st = 0;
    for (int kv = 0; kv < NKV; kv++) {
        CP_WAIT1();
        __syncthreads();
        if (kv + 2 < NKV) {
            const int st2 = (st + 2 >= 3) ? st - 1 : st + 2;
            ATTN_LOAD_STAGE(kv + 2, st2);
        }
        CP_COMMIT();

        const uint32_t kh_b = sbase + (uint32_t)st * ASTG_B;
        const uint32_t kl_b = kh_b + ATILE_B;
        const uint32_t vh_b = kl_b + ATILE_B;
        const uint32_t vl_b = vh_b + ATILE_B;

        // S = Q·(Kh+Kl)^T  (2 passes, pass-major)
        float s[4][4];
#pragma unroll
        for (int j = 0; j < 4; j++)
#pragma unroll
            for (int r = 0; r < 4; r++) s[j][r] = 0.f;
#pragma unroll
        for (int kk = 0; kk < 4; kk++) {
            uint32_t kbh[4][2], kbl[4][2];
#pragma unroll
            for (int jp = 0; jp < 2; jp++) {
                const uint32_t off =
                    (uint32_t)(((jp * 16 + b_lrow) * KST + kk * 16 + b_lcol) * 2);
                LDSM_X4(kbh[2 * jp][0], kbh[2 * jp][1],
                        kbh[2 * jp + 1][0], kbh[2 * jp + 1][1], kh_b + off);
                LDSM_X4(kbl[2 * jp][0], kbl[2 * jp][1],
                        kbl[2 * jp + 1][0], kbl[2 * jp + 1][1], kl_b + off);
            }
#pragma unroll
            for (int j = 0; j < 4; j++)
                mma_f16(s[j], qh[kk], kbh[j][0], kbh[j][1]);
#pragma unroll
            for (int j = 0; j < 4; j++)
                mma_f16(s[j], qh[kk], kbl[j][0], kbl[j][1]);
        }

        // raw absmax (pre-scale), scale, online softmax
        float rm0 = -1e30f, rm1 = -1e30f;
#pragma unroll
        for (int j = 0; j < 4; j++) {
#pragma unroll
            for (int r = 0; r < 4; r++) {
                raw = fmaxf(raw, fabsf(s[j][r]));
                s[j][r] *= 0.125f;
            }
            rm0 = fmaxf(rm0, fmaxf(s[j][0], s[j][1]));
            rm1 = fmaxf(rm1, fmaxf(s[j][2], s[j][3]));
        }
        rm0 = fmaxf(rm0, __shfl_xor_sync(0xffffffffu, rm0, 1));
        rm0 = fmaxf(rm0, __shfl_xor_sync(0xffffffffu, rm0, 2));
        rm1 = fmaxf(rm1, __shfl_xor_sync(0xffffffffu, rm1, 1));
        rm1 = fmaxf(rm1, __shfl_xor_sync(0xffffffffu, rm1, 2));
        const float mn0 = fmaxf(m0, rm0), mn1 = fmaxf(m1, rm1);
        const float f0 = __expf(m0 - mn0), f1 = __expf(m1 - mn1);
        float ps0 = 0.f, ps1 = 0.f;
#pragma unroll
        for (int j = 0; j < 4; j++) {
            s[j][0] = __expf(s[j][0] - mn0);
            s[j][1] = __expf(s[j][1] - mn0);
            s[j][2] = __expf(s[j][2] - mn1);
            s[j][3] = __expf(s[j][3] - mn1);
            ps0 += s[j][0] + s[j][1];
            ps1 += s[j][2] + s[j][3];
        }
        ps0 += __shfl_xor_sync(0xffffffffu, ps0, 1);
        ps0 += __shfl_xor_sync(0xffffffffu, ps0, 2);
        ps1 += __shfl_xor_sync(0xffffffffu, ps1, 1);
        ps1 += __shfl_xor_sync(0xffffffffu, ps1, 2);
        l0 = l0 * f0 + ps0;
        l1 = l1 * f1 + ps1;
        m0 = mn0; m1 = mn1;
#pragma unroll
        for (int j = 0; j < 8; j++) {
            o[j][0] *= f0; o[j][1] *= f0;
            o[j][2] *= f1; o[j][3] *= f1;
        }

        // P -> fp16 fragments
        uint32_t ph[4][2];
#pragma unroll
        for (int j = 0; j < 4; j++) {
            ph[j][0] = packh(s[j][0], s[j][1]);
            ph[j][1] = packh(s[j][2], s[j][3]);
        }

        // O += P·(Vh+Vl)  (2 passes, pass-major); V frags via ldmatrix.trans
#pragma unroll
        for (int kk = 0; kk < 2; kk++) {
            uint32_t pah[4] = {ph[2 * kk][0], ph[2 * kk][1],
                               ph[2 * kk + 1][0], ph[2 * kk + 1][1]};
            uint32_t vbh[8][2], vbl[8][2];
#pragma unroll
            for (int jp = 0; jp < 4; jp++) {
                const uint32_t off =
                    (uint32_t)(((kk * 16 + v_lrow) * KST + jp * 16 + v_lcol) * 2);
                LDSM_X4_T(vbh[2 * jp][0], vbh[2 * jp][1],
                          vbh[2 * jp + 1][0], vbh[2 * jp + 1][1], vh_b + off);
                LDSM_X4_T(vbl[2 * jp][0], vbl[2 * jp][1],
                          vbl[2 * jp + 1][0], vbl[2 * jp + 1][1], vl_b + off);
            }
#pragma unroll
            for (int j = 0; j < 8; j++)
                mma_f16(o[j], pah, vbh[j][0], vbh[j][1]);
#pragma unroll
            for (int j = 0; j < 8; j++)
                mma_f16(o[j], pah, vbl[j][0], vbl[j][1]);
        }
        __syncthreads();
        st = (st + 1 >= 3) ? 0 : st + 1;
    }
#undef ATTN_LOAD_STAGE

    // epilogue
    const float i0 = 1.f / l0, i1 = 1.f / l1;
    const int r0g = q0 + wid * 16 + g;
    const int r1g = r0g + 8;
    const size_t ob0 = ((size_t)b * SEQ + r0g) * DMODEL + h * HDIM;
    const size_t ob1 = ((size_t)b * SEQ + r1g) * DMODEL + h * HDIM;
#pragma unroll
    for (int j = 0; j < 8; j++) {
        const int d = 8 * j + 2 * t;
        float2 w0 = {o[j][0] * i0, o[j][1] * i0};
        float2 w1 = {o[j][2] * i1, o[j][3] * i1};
        *(float2*)(out + ob0 + d) = w0;
        *(float2*)(out + ob1 + d) = w1;
    }
    atomicMax(&s_raw, __float_as_uint(raw));
    atomicMax(&s_aw, __float_as_uint(fmaxf(i0, i1)));
    __syncthreads();
    if (tid == 0) {
        atomicMax(&g_mx[2], s_raw);
        atomicMax(&g_mx[3], s_aw);
    }
}

// ---------------- finalize scalars ----------------
__global__ void finalize_kernel(float* __restrict__ out, int base)
{
    if (threadIdx.x == 0) {
        const float qm  = __uint_as_float(g_mx[0]);
        const float km  = __uint_as_float(g_mx[1]);
        const float qkm = __uint_as_float(g_mx[2]);
        const float awm = __uint_as_float(g_mx[3]);
        const float vm  = __uint_as_float(g_mx[4]);
        out[base + 0] = qm;
        out[base + 1] = km;
        out[base + 2] = qkm;
        out[base + 3] = awm;
        out[base + 4] = vm;
        out[base + 5] = awm;  // v_out_max (faithful source bug)
    }
}

// ---------------- launch ----------------
extern "C" void kernel_launch(void* const* d_in, const int* in_sizes, int n_in,
                              void* d_out, int out_size)
{
    const float* X  = (const float*)d_in[0];
    const float* Wq = (const float*)d_in[1];
    const float* bq = (const float*)d_in[2];
    const float* Wk = (const float*)d_in[3];
    const float* bk = (const float*)d_in[4];
    const float* Wv = (const float*)d_in[5];
    const float* bv = (const float*)d_in[6];
    float* out = (float*)d_out;

    cudaFuncSetAttribute(qkv_gemm_mma,
                         cudaFuncAttributeMaxDynamicSharedMemorySize,
                         GEMM_SMEM_BYTES);
    cudaFuncSetAttribute(attn_mma,
                         cudaFuncAttributeMaxDynamicSharedMemorySize,
                         ATTN_SMEM_BYTES);

    init_kernel<<<1, 32>>>();                                           // 0
    convert_x<<<MROWS * DMODEL / 4 / 256, 256>>>(X);                    // 1
    convert_w<<<dim3(DMODEL * DMODEL / 4 / 256, 1, 3), 256>>>(Wq, Wk, Wv); // 2
    qkv_gemm_mma<<<dim3(DMODEL / 128, MROWS / 128, 3), 256,
                   GEMM_SMEM_BYTES>>>(bq, bk, bv);                      // 3
    spacer_kernel<<<1, 32>>>();                                         // 4
    attn_mma<<<dim3(SEQ / 128, BATCH * HEADS), 256,
               ATTN_SMEM_BYTES>>>(out);                                 // 5
    finalize_kernel<<<1, 32>>>(out, out_size - 6);                      // 6
}

// round 10
// speedup vs baseline: 5.9612x; 1.0514x over previous
#include <cuda_runtime.h>
#include <cuda_fp16.h>
#include <cstdint>

// Problem constants: B=2, S=2048, DM=1024, H=16, DH=64
#define BATCH 2
#define SEQ 2048
#define DMODEL 1024
#define HEADS 16
#define HDIM 64
#define MROWS (BATCH*SEQ)                 // 4096
#define QKV_ELEMS (BATCH*HEADS*SEQ*HDIM)  // 4,194,304

// ---------------- device scratch (fp16) ----------------
__device__ __half g_x16[MROWS * DMODEL];
__device__ __half g_whi[3 * DMODEL * DMODEL];
__device__ __half g_wlo[3 * DMODEL * DMODEL];
__device__ __half g_q16[QKV_ELEMS];
__device__ __half g_khi[QKV_ELEMS], g_klo[QKV_ELEMS];
__device__ __half g_vhi[QKV_ELEMS];
// absmax slots: 0=q 1=k 2=qk_raw 3=aw 4=v
__device__ unsigned g_mx[5];

__global__ void init_kernel() {
    if (threadIdx.x < 5) g_mx[threadIdx.x] = 0u;
}
__global__ void spacer_kernel() {}   // shifts attn to launch idx 5 for ncu -s 5

// ---------------- helpers ----------------
__device__ __forceinline__ void mma_f16(float (&c)[4], const uint32_t (&a)[4],
                                        uint32_t b0, uint32_t b1) {
    asm volatile(
        "mma.sync.aligned.m16n8k16.row.col.f32.f16.f16.f32 "
        "{%0,%1,%2,%3}, {%4,%5,%6,%7}, {%8,%9}, {%0,%1,%2,%3};"
        : "+f"(c[0]), "+f"(c[1]), "+f"(c[2]), "+f"(c[3])
        : "r"(a[0]), "r"(a[1]), "r"(a[2]), "r"(a[3]), "r"(b0), "r"(b1));
}
__device__ __forceinline__ uint32_t packh(float lo, float hi) {
    uint32_t r;
    asm("cvt.rn.f16x2.f32 %0, %1, %2;" : "=r"(r) : "f"(hi), "f"(lo));
    return r;
}
__device__ __forceinline__ uint32_t smem_u32(const void* p) {
    uint32_t a;
    asm("{ .reg .u64 t; cvta.to.shared.u64 t, %1; cvt.u32.u64 %0, t; }"
        : "=r"(a) : "l"(p));
    return a;
}
#define LDSM_X4(r0, r1, r2, r3, addr) \
    asm volatile("ldmatrix.sync.aligned.m8n8.x4.shared.b16 {%0,%1,%2,%3}, [%4];" \
                 : "=r"(r0), "=r"(r1), "=r"(r2), "=r"(r3) : "r"(addr))
#define LDSM_X4_T(r0, r1, r2, r3, addr) \
    asm volatile("ldmatrix.sync.aligned.m8n8.x4.trans.shared.b16 {%0,%1,%2,%3}, [%4];" \
                 : "=r"(r0), "=r"(r1), "=r"(r2), "=r"(r3) : "r"(addr))
#define CP_ASYNC16(dst, src) \
    asm volatile("cp.async.cg.shared.global [%0], [%1], 16;" \
                 :: "r"(dst), "l"(src))
#define CP_COMMIT() asm volatile("cp.async.commit_group;" ::: "memory")
#define CP_WAIT1() asm volatile("cp.async.wait_group 1;" ::: "memory")

// ---------------- fp32 -> fp16 conversion ----------------
__global__ __launch_bounds__(256) void convert_x(const float* __restrict__ X) {
    size_t i4 = ((size_t)blockIdx.x * 256 + threadIdx.x) * 4;
    float4 v = *(const float4*)(X + i4);
    *(__half2*)(g_x16 + i4 + 0) = __floats2half2_rn(v.x, v.y);
    *(__half2*)(g_x16 + i4 + 2) = __floats2half2_rn(v.z, v.w);
}

__global__ __launch_bounds__(256) void convert_w(
    const float* __restrict__ Wq, const float* __restrict__ Wk,
    const float* __restrict__ Wv) {
    const int z = blockIdx.z;
    const float* W = (z == 0) ? Wq : (z == 1) ? Wk : Wv;
    size_t base = (size_t)z * DMODEL * DMODEL;
    size_t i4 = ((size_t)blockIdx.x * 256 + threadIdx.x) * 4;
    float4 v = *(const float4*)(W + i4);
    float f[4] = {v.x, v.y, v.z, v.w};
    __half h[4], l[4];
#pragma unroll
    for (int j = 0; j < 4; j++) {
        h[j] = __float2half_rn(f[j]);
        l[j] = __float2half_rn(f[j] - __half2float(h[j]));
    }
    *(__half2*)(g_whi + base + i4 + 0) = __half2(h[0], h[1]);
    *(__half2*)(g_whi + base + i4 + 2) = __half2(h[2], h[3]);
    *(__half2*)(g_wlo + base + i4 + 0) = __half2(l[0], l[1]);
    *(__half2*)(g_wlo + base + i4 + 2) = __half2(l[2], l[3]);
}

// ---- fp16 2-pass QKV GEMM: 256 thr, 2 CTA/SM, warp tile 64x32 -------------
#define GKC 32
#define GST 40                           // smem row stride (fp16), 80B
#define GTILE_B (128 * GST * 2)          // 10240 B per tile
#define GSTG_B (3 * GTILE_B)             // A Bh Bl = 30720 B per stage
#define GEMM_SMEM_BYTES (3 * GSTG_B)     // 92160

__global__ __launch_bounds__(256, 2) void qkv_gemm_mma(
    const float* __restrict__ bq, const float* __restrict__ bk,
    const float* __restrict__ bv)
{
    extern __shared__ __half sm[];
    __shared__ unsigned s_amax;

    const int tid = threadIdx.x;
    const int wid = tid >> 5;
    const int lane = tid & 31;
    const int g = lane >> 2;
    const int t = lane & 3;
    const int wm = wid & 1;           // 0..1 (64 rows each)
    const int wn = wid >> 1;          // 0..3 (32 cols each)

    const int z = blockIdx.z;
    const int m0 = blockIdx.y * 128;
    const int n0 = blockIdx.x * 128;

    const float* __restrict__ bias = (z == 0) ? bq : (z == 1) ? bk : bv;
    __half* __restrict__ Ohi = (z == 0) ? g_q16 : (z == 1) ? g_khi : g_vhi;
    __half* __restrict__ Olo = (z == 1) ? g_klo : (__half*)nullptr;
    const int mslot = (z == 0) ? 0 : (z == 1) ? 1 : 4;

    const __half* __restrict__ A  = g_x16 + (size_t)m0 * DMODEL;
    const __half* __restrict__ Bh = g_whi + (size_t)z * DMODEL * DMODEL + (size_t)n0 * DMODEL;
    const __half* __restrict__ Bl = g_wlo + (size_t)z * DMODEL * DMODEL + (size_t)n0 * DMODEL;

    if (tid == 0) s_amax = 0u;

    const uint32_t sbase = smem_u32(sm);
    const int a_lrow = lane & 15;
    const int a_lcol = ((lane >> 4) & 1) * 8;
    const int b_lrow = (lane & 7) + (lane >> 4) * 8;
    const int b_lcol = ((lane >> 3) & 1) * 8;

    float c[4][4][4];
#pragma unroll
    for (int mt = 0; mt < 4; mt++)
#pragma unroll
        for (int nt = 0; nt < 4; nt++)
#pragma unroll
            for (int r = 0; r < 4; r++) c[mt][nt][r] = 0.f;

    const int NCH = DMODEL / GKC;     // 32

#define GEMM_LOAD_STAGE(ch, st) do {                                          \
        const int k0 = (ch) * GKC;                                            \
        const uint32_t stb = sbase + (uint32_t)(st) * GSTG_B;                 \
        _Pragma("unroll")                                                     \
        for (int i = 0; i < 2; i++) {                                         \
            const int cid = tid + i * 256;                                    \
            const int row = cid >> 2, cu = cid & 3;                           \
            const size_t go = (size_t)row * DMODEL + k0 + cu * 8;             \
            const uint32_t so = stb + (uint32_t)(row * GST + cu * 8) * 2;     \
            CP_ASYNC16(so + 0 * GTILE_B, (const void*)(A + go));              \
            CP_ASYNC16(so + 1 * GTILE_B, (const void*)(Bh + go));             \
            CP_ASYNC16(so + 2 * GTILE_B, (const void*)(Bl + go));             \
        }                                                                     \
    } while (0)

    GEMM_LOAD_STAGE(0, 0); CP_COMMIT();
    GEMM_LOAD_STAGE(1, 1); CP_COMMIT();

    int st = 0;
    for (int ch = 0; ch < NCH; ch++) {
        CP_WAIT1();
        __syncthreads();
        if (ch + 2 < NCH) {
            const int st2 = (st + 2 >= 3) ? st - 1 : st + 2;
            GEMM_LOAD_STAGE(ch + 2, st2);
        }
        CP_COMMIT();

        const uint32_t bA  = sbase + (uint32_t)st * GSTG_B;
        const uint32_t bBh = bA + GTILE_B;
        const uint32_t bBl = bBh + GTILE_B;
#pragma unroll
        for (int ks = 0; ks < 2; ks++) {
            const int kc = ks * 16;
            uint32_t ah[4][4];
#pragma unroll
            for (int mt = 0; mt < 4; mt++) {
                const uint32_t off =
                    (uint32_t)(((wm * 64 + mt * 16 + a_lrow) * GST + kc + a_lcol) * 2);
                LDSM_X4(ah[mt][0], ah[mt][1], ah[mt][2], ah[mt][3], bA + off);
            }
            uint32_t bhf[4][2], blf[4][2];
#pragma unroll
            for (int ntp = 0; ntp < 2; ntp++) {
                const uint32_t off =
                    (uint32_t)(((wn * 32 + ntp * 16 + b_lrow) * GST + kc + b_lcol) * 2);
                LDSM_X4(bhf[2 * ntp][0], bhf[2 * ntp][1],
                        bhf[2 * ntp + 1][0], bhf[2 * ntp + 1][1], bBh + off);
                LDSM_X4(blf[2 * ntp][0], blf[2 * ntp][1],
                        blf[2 * ntp + 1][0], blf[2 * ntp + 1][1], bBl + off);
            }
#pragma unroll
            for (int mt = 0; mt < 4; mt++)
#pragma unroll
                for (int nt = 0; nt < 4; nt++)
                    mma_f16(c[mt][nt], ah[mt], bhf[nt][0], bhf[nt][1]);
#pragma unroll
            for (int mt = 0; mt < 4; mt++)
#pragma unroll
                for (int nt = 0; nt < 4; nt++)
                    mma_f16(c[mt][nt], ah[mt], blf[nt][0], blf[nt][1]);
        }
        __syncthreads();
        st = (st + 1 >= 3) ? 0 : st + 1;
    }
#undef GEMM_LOAD_STAGE

    // epilogue: bias, absmax, fp16 hi (+lo for K only), layout [BH][S][64]
    float lmax = 0.f;
#pragma unroll
    for (int nt = 0; nt < 4; nt++) {
        const int n = n0 + wn * 32 + nt * 8 + 2 * t;
        const float bn0 = bias[n], bn1 = bias[n + 1];
        const int h = n >> 6, d = n & 63;
#pragma unroll
        for (int mt = 0; mt < 4; mt++) {
            const int mr0 = m0 + wm * 64 + mt * 16 + g;
            const int mr1 = mr0 + 8;
            float v0 = c[mt][nt][0] + bn0;
            float v1 = c[mt][nt][1] + bn1;
            float v2 = c[mt][nt][2] + bn0;
            float v3 = c[mt][nt][3] + bn1;
            lmax = fmaxf(lmax, fmaxf(fmaxf(fabsf(v0), fabsf(v1)),
                                     fmaxf(fabsf(v2), fabsf(v3))));
            const int bb0 = mr0 >> 11, s0 = mr0 & 2047;
            const int bb1 = mr1 >> 11, s1 = mr1 & 2047;
            const size_t o0 = (((size_t)(bb0 * HEADS + h)) * SEQ + s0) * HDIM + d;
            const size_t o1 = (((size_t)(bb1 * HEADS + h)) * SEQ + s1) * HDIM + d;
            uint32_t h0 = packh(v0, v1), h1 = packh(v2, v3);
            *(uint32_t*)(Ohi + o0) = h0;
            *(uint32_t*)(Ohi + o1) = h1;
            if (z == 1) {
                __half2 hb0 = *(__half2*)&h0;
                __half2 hb1 = *(__half2*)&h1;
                uint32_t l0 = packh(v0 - __half2float(hb0.x),
                                    v1 - __half2float(hb0.y));
                uint32_t l1 = packh(v2 - __half2float(hb1.x),
                                    v3 - __half2float(hb1.y));
                *(uint32_t*)(Olo + o0) = l0;
                *(uint32_t*)(Olo + o1) = l1;
            }
        }
    }
    atomicMax(&s_amax, __float_as_uint(lmax));
    __syncthreads();
    if (tid == 0) atomicMax(&g_mx[mslot], s_amax);
}

// ------ flash attention: S 2-pass, PV 1-pass, KV tile 32, 3-stage ----------
#define AKV 32                            // kv rows per tile
#define KST 72                            // smem row stride (fp16), 144B
#define ATILE_B (AKV * KST * 2)           // 4608 B per tile
#define ASTG_B (3 * ATILE_B)              // kh kl vh = 13824 B per stage
#define ATTN_SMEM_BYTES (3 * ASTG_B)      // 41472

__global__ __launch_bounds__(256, 2) void attn_mma(float* __restrict__ out)
{
    extern __shared__ __half asm_buf[];
    __shared__ unsigned s_raw, s_aw;

    const int tid = threadIdx.x;
    const int wid = tid >> 5;
    const int lane = tid & 31;
    const int g = lane >> 2;
    const int t = lane & 3;

    const int bh = blockIdx.y;
    const int b = bh >> 4, h = bh & 15;
    const int q0 = blockIdx.x * 128;

    if (tid == 0) { s_raw = 0u; s_aw = 0u; }

    const uint32_t sbase = smem_u32(asm_buf);
    const int b_lrow = (lane & 7) + (lane >> 4) * 8;
    const int b_lcol = ((lane >> 3) & 1) * 8;
    const int v_lrow = (lane & 7) + ((lane >> 3) & 1) * 8;
    const int v_lcol = (lane >> 4) * 8;

    // Q fragments (fp16), loaded once
    const size_t qbase = ((size_t)bh * SEQ + q0 + wid * 16) * HDIM;
    const __half* Qh = g_q16 + qbase;
    uint32_t qh[4][4];
#pragma unroll
    for (int kk = 0; kk < 4; kk++) {
        const int c0 = kk * 16 + 2 * t;
        qh[kk][0] = *(const uint32_t*)(Qh + g * HDIM + c0);
        qh[kk][1] = *(const uint32_t*)(Qh + (g + 8) * HDIM + c0);
        qh[kk][2] = *(const uint32_t*)(Qh + g * HDIM + c0 + 8);
        qh[kk][3] = *(const uint32_t*)(Qh + (g + 8) * HDIM + c0 + 8);
    }

    const __half* Kh = g_khi + (size_t)bh * SEQ * HDIM;
    const __half* Kl = g_klo + (size_t)bh * SEQ * HDIM;
    const __half* Vh = g_vhi + (size_t)bh * SEQ * HDIM;

    float o[8][4];
#pragma unroll
    for (int j = 0; j < 8; j++)
#pragma unroll
        for (int r = 0; r < 4; r++) o[j][r] = 0.f;
    float m0 = -1e30f, m1 = -1e30f, l0 = 0.f, l1 = 0.f, raw = 0.f;

    const int NKV = SEQ / AKV;  // 64

#define ATTN_LOAD_STAGE(kv, st) do {                                          \
        const int base_row = (kv) * AKV;                                      \
        const uint32_t stb = sbase + (uint32_t)(st) * ASTG_B;                 \
        const int row = tid >> 3, du = tid & 7;                               \
        const size_t go = (size_t)(base_row + row) * HDIM + du * 8;           \
        const uint32_t so = stb + (uint32_t)(row * KST + du * 8) * 2;         \
        CP_ASYNC16(so + 0 * ATILE_B, (const void*)(Kh + go));                 \
        CP_ASYNC16(so + 1 * ATILE_B, (const void*)(Kl + go));                 \
        CP_ASYNC16(so + 2 * ATILE_B, (const void*)(Vh + go));                 \
    } while (0)

    ATTN_LOAD_STAGE(0, 0); CP_COMMIT();
    ATTN_LOAD_STAGE(1, 1); CP_COMMIT();

    int st = 0;
    for (int kv = 0; kv < NKV; kv++) {
        CP_WAIT1();
        __syncthreads();
        if (kv + 2 < NKV) {
            const int st2 = (st + 2 >= 3) ? st - 1 : st + 2;
            ATTN_LOAD_STAGE(kv + 2, st2);
        }
        CP_COMMIT();

        const uint32_t kh_b = sbase + (uint32_t)st * ASTG_B;
        const uint32_t kl_b = kh_b + ATILE_B;
        const uint32_t vh_b = kl_b + ATILE_B;

        // S = Q·(Kh+Kl)^T  (2 passes, pass-major)
        float s[4][4];
#pragma unroll
        for (int j = 0; j < 4; j++)
#pragma unroll
            for (int r = 0; r < 4; r++) s[j][r] = 0.f;
#pragma unroll
        for (int kk = 0; kk < 4; kk++) {
            uint32_t kbh[4][2], kbl[4][2];
#pragma unroll
            for (int jp = 0; jp < 2; jp++) {
                const uint32_t off =
                    (uint32_t)(((jp * 16 + b_lrow) * KST + kk * 16 + b_lcol) * 2);
                LDSM_X4(kbh[2 * jp][0], kbh[2 * jp][1],
                        kbh[2 * jp + 1][0], kbh[2 * jp + 1][1], kh_b + off);
                LDSM_X4(kbl[2 * jp][0], kbl[2 * jp][1],
                        kbl[2 * jp + 1][0], kbl[2 * jp + 1][1], kl_b + off);
            }
#pragma unroll
            for (int j = 0; j < 4; j++)
                mma_f16(s[j], qh[kk], kbh[j][0], kbh[j][1]);
#pragma unroll
            for (int j = 0; j < 4; j++)
                mma_f16(s[j], qh[kk], kbl[j][0], kbl[j][1]);
        }

        // raw absmax (pre-scale), scale, online softmax
        float rm0 = -1e30f, rm1 = -1e30f;
#pragma unroll
        for (int j = 0; j < 4; j++) {
#pragma unroll
            for (int r = 0; r < 4; r++) {
                raw = fmaxf(raw, fabsf(s[j][r]));
                s[j][r] *= 0.125f;
            }
            rm0 = fmaxf(rm0, fmaxf(s[j][0], s[j][1]));
            rm1 = fmaxf(rm1, fmaxf(s[j][2], s[j][3]));
        }
        rm0 = fmaxf(rm0, __shfl_xor_sync(0xffffffffu, rm0, 1));
        rm0 = fmaxf(rm0, __shfl_xor_sync(0xffffffffu, rm0, 2));
        rm1 = fmaxf(rm1, __shfl_xor_sync(0xffffffffu, rm1, 1));
        rm1 = fmaxf(rm1, __shfl_xor_sync(0xffffffffu, rm1, 2));
        const float mn0 = fmaxf(m0, rm0), mn1 = fmaxf(m1, rm1);
        const float f0 = __expf(m0 - mn0), f1 = __expf(m1 - mn1);
        float ps0 = 0.f, ps1 = 0.f;
#pragma unroll
        for (int j = 0; j < 4; j++) {
            s[j][0] = __expf(s[j][0] - mn0);
            s[j][1] = __expf(s[j][1] - mn0);
            s[j][2] = __expf(s[j][2] - mn1);
            s[j][3] = __expf(s[j][3] - mn1);
            ps0 += s[j][0] + s[j][1];
            ps1 += s[j][2] + s[j][3];
        }
        ps0 += __shfl_xor_sync(0xffffffffu, ps0, 1);
        ps0 += __shfl_xor_sync(0xffffffffu, ps0, 2);
        ps1 += __shfl_xor_sync(0xffffffffu, ps1, 1);
        ps1 += __shfl_xor_sync(0xffffffffu, ps1, 2);
        l0 = l0 * f0 + ps0;
        l1 = l1 * f1 + ps1;
        m0 = mn0; m1 = mn1;
#pragma unroll
        for (int j = 0; j < 8; j++) {
            o[j][0] *= f0; o[j][1] *= f0;
            o[j][2] *= f1; o[j][3] *= f1;
        }

        // P -> fp16 fragments
        uint32_t ph[4][2];
#pragma unroll
        for (int j = 0; j < 4; j++) {
            ph[j][0] = packh(s[j][0], s[j][1]);
            ph[j][1] = packh(s[j][2], s[j][3]);
        }

        // O += P·Vh  (single pass); V frags via ldmatrix.trans
#pragma unroll
        for (int kk = 0; kk < 2; kk++) {
            uint32_t pah[4] = {ph[2 * kk][0], ph[2 * kk][1],
                               ph[2 * kk + 1][0], ph[2 * kk + 1][1]};
            uint32_t vbh[8][2];
#pragma unroll
            for (int jp = 0; jp < 4; jp++) {
                const uint32_t off =
                    (uint32_t)(((kk * 16 + v_lrow) * KST + jp * 16 + v_lcol) * 2);
                LDSM_X4_T(vbh[2 * jp][0], vbh[2 * jp][1],
                          vbh[2 * jp + 1][0], vbh[2 * jp + 1][1], vh_b + off);
            }
#pragma unroll
            for (int j = 0; j < 8; j++)
                mma_f16(o[j], pah, vbh[j][0], vbh[j][1]);
        }
        __syncthreads();
        st = (st + 1 >= 3) ? 0 : st + 1;
    }
#undef ATTN_LOAD_STAGE

    // epilogue
    const float i0 = 1.f / l0, i1 = 1.f / l1;
    const int r0g = q0 + wid * 16 + g;
    const int r1g = r0g + 8;
    const size_t ob0 = ((size_t)b * SEQ + r0g) * DMODEL + h * HDIM;
    const size_t ob1 = ((size_t)b * SEQ + r1g) * DMODEL + h * HDIM;
#pragma unroll
    for (int j = 0; j < 8; j++) {
        const int d = 8 * j + 2 * t;
        float2 w0 = {o[j][0] * i0, o[j][1] * i0};
        float2 w1 = {o[j][2] * i1, o[j][3] * i1};
        *(float2*)(out + ob0 + d) = w0;
        *(float2*)(out + ob1 + d) = w1;
    }
    atomicMax(&s_raw, __float_as_uint(raw));
    atomicMax(&s_aw, __float_as_uint(fmaxf(i0, i1)));
    __syncthreads();
    if (tid == 0) {
        atomicMax(&g_mx[2], s_raw);
        atomicMax(&g_mx[3], s_aw);
    }
}

// ---------------- finalize scalars ----------------
__global__ void finalize_kernel(float* __restrict__ out, int base)
{
    if (threadIdx.x == 0) {
        const float qm  = __uint_as_float(g_mx[0]);
        const float km  = __uint_as_float(g_mx[1]);
        const float qkm = __uint_as_float(g_mx[2]);
        const float awm = __uint_as_float(g_mx[3]);
        const float vm  = __uint_as_float(g_mx[4]);
        out[base + 0] = qm;
        out[base + 1] = km;
        out[base + 2] = qkm;
        out[base + 3] = awm;
        out[base + 4] = vm;
        out[base + 5] = awm;  // v_out_max (faithful source bug)
    }
}

// ---------------- launch ----------------
extern "C" void kernel_launch(void* const* d_in, const int* in_sizes, int n_in,
                              void* d_out, int out_size)
{
    const float* X  = (const float*)d_in[0];
    const float* Wq = (const float*)d_in[1];
    const float* bq = (const float*)d_in[2];
    const float* Wk = (const float*)d_in[3];
    const float* bk = (const float*)d_in[4];
    const float* Wv = (const float*)d_in[5];
    const float* bv = (const float*)d_in[6];
    float* out = (float*)d_out;

    cudaFuncSetAttribute(qkv_gemm_mma,
                         cudaFuncAttributeMaxDynamicSharedMemorySize,
                         GEMM_SMEM_BYTES);
    cudaFuncSetAttribute(attn_mma,
                         cudaFuncAttributeMaxDynamicSharedMemorySize,
                         ATTN_SMEM_BYTES);

    init_kernel<<<1, 32>>>();                                           // 0
    convert_x<<<MROWS * DMODEL / 4 / 256, 256>>>(X);                    // 1
    convert_w<<<dim3(DMODEL * DMODEL / 4 / 256, 1, 3), 256>>>(Wq, Wk, Wv); // 2
    qkv_gemm_mma<<<dim3(DMODEL / 128, MROWS / 128, 3), 256,
                   GEMM_SMEM_BYTES>>>(bq, bk, bv);                      // 3
    spacer_kernel<<<1, 32>>>();                                         // 4
    attn_mma<<<dim3(SEQ / 128, BATCH * HEADS), 256,
               ATTN_SMEM_BYTES>>>(out);                                 // 5
    finalize_kernel<<<1, 32>>>(out, out_size - 6);                      // 6
}

// round 11
// speedup vs baseline: 8.5268x; 1.4304x over previous
#include <cuda_runtime.h>
#include <cuda_fp16.h>
#include <cstdint>

// Problem constants: B=2, S=2048, DM=1024, H=16, DH=64
#define BATCH 2
#define SEQ 2048
#define DMODEL 1024
#define HEADS 16
#define HDIM 64
#define MROWS (BATCH*SEQ)                 // 4096
#define QKV_ELEMS (BATCH*HEADS*SEQ*HDIM)  // 4,194,304

// ---------------- device scratch (fp16) ----------------
__device__ __half g_x16[MROWS * DMODEL];
__device__ __half g_w16[3 * DMODEL * DMODEL];
__device__ __half g_q16[QKV_ELEMS];
__device__ __half g_k16[QKV_ELEMS];
__device__ __half g_v16[QKV_ELEMS];
// absmax slots: 0=q 1=k 2=qk_raw 3=aw 4=v
__device__ unsigned g_mx[5];

__global__ void init_kernel() {
    if (threadIdx.x < 5) g_mx[threadIdx.x] = 0u;
}
__global__ void spacer_kernel() {}   // shifts attn to launch idx 5 for ncu -s 5

// ---------------- helpers ----------------
__device__ __forceinline__ void mma_f16(float (&c)[4], const uint32_t (&a)[4],
                                        uint32_t b0, uint32_t b1) {
    asm volatile(
        "mma.sync.aligned.m16n8k16.row.col.f32.f16.f16.f32 "
        "{%0,%1,%2,%3}, {%4,%5,%6,%7}, {%8,%9}, {%0,%1,%2,%3};"
        : "+f"(c[0]), "+f"(c[1]), "+f"(c[2]), "+f"(c[3])
        : "r"(a[0]), "r"(a[1]), "r"(a[2]), "r"(a[3]), "r"(b0), "r"(b1));
}
__device__ __forceinline__ uint32_t packh(float lo, float hi) {
    uint32_t r;
    asm("cvt.rn.f16x2.f32 %0, %1, %2;" : "=r"(r) : "f"(hi), "f"(lo));
    return r;
}
__device__ __forceinline__ uint32_t smem_u32(const void* p) {
    uint32_t a;
    asm("{ .reg .u64 t; cvta.to.shared.u64 t, %1; cvt.u32.u64 %0, t; }"
        : "=r"(a) : "l"(p));
    return a;
}
#define LDSM_X4(r0, r1, r2, r3, addr) \
    asm volatile("ldmatrix.sync.aligned.m8n8.x4.shared.b16 {%0,%1,%2,%3}, [%4];" \
                 : "=r"(r0), "=r"(r1), "=r"(r2), "=r"(r3) : "r"(addr))
#define LDSM_X4_T(r0, r1, r2, r3, addr) \
    asm volatile("ldmatrix.sync.aligned.m8n8.x4.trans.shared.b16 {%0,%1,%2,%3}, [%4];" \
                 : "=r"(r0), "=r"(r1), "=r"(r2), "=r"(r3) : "r"(addr))
#define CP_ASYNC16(dst, src) \
    asm volatile("cp.async.cg.shared.global [%0], [%1], 16;" \
                 :: "r"(dst), "l"(src))
#define CP_COMMIT() asm volatile("cp.async.commit_group;" ::: "memory")
#define CP_WAIT1() asm volatile("cp.async.wait_group 1;" ::: "memory")

// ---------------- fp32 -> fp16 conversion ----------------
__global__ __launch_bounds__(256) void convert_x(const float* __restrict__ X) {
    size_t i4 = ((size_t)blockIdx.x * 256 + threadIdx.x) * 4;
    float4 v = *(const float4*)(X + i4);
    *(__half2*)(g_x16 + i4 + 0) = __floats2half2_rn(v.x, v.y);
    *(__half2*)(g_x16 + i4 + 2) = __floats2half2_rn(v.z, v.w);
}

__global__ __launch_bounds__(256) void convert_w(
    const float* __restrict__ Wq, const float* __restrict__ Wk,
    const float* __restrict__ Wv) {
    const int z = blockIdx.z;
    const float* W = (z == 0) ? Wq : (z == 1) ? Wk : Wv;
    size_t base = (size_t)z * DMODEL * DMODEL;
    size_t i4 = ((size_t)blockIdx.x * 256 + threadIdx.x) * 4;
    float4 v = *(const float4*)(W + i4);
    *(__half2*)(g_w16 + base + i4 + 0) = __floats2half2_rn(v.x, v.y);
    *(__half2*)(g_w16 + base + i4 + 2) = __floats2half2_rn(v.z, v.w);
}

// ---- fp16 1-pass QKV GEMM: 256 thr, 2 CTA/SM, warp tile 64x32 -------------
#define GKC 32
#define GST 40                           // smem row stride (fp16), 80B
#define GTILE_B (128 * GST * 2)          // 10240 B per tile
#define GSTG_B (2 * GTILE_B)             // A B = 20480 B per stage
#define GEMM_SMEM_BYTES (3 * GSTG_B)     // 61440

__global__ __launch_bounds__(256, 2) void qkv_gemm_mma(
    const float* __restrict__ bq, const float* __restrict__ bk,
    const float* __restrict__ bv)
{
    extern __shared__ __half sm[];
    __shared__ unsigned s_amax;

    const int tid = threadIdx.x;
    const int wid = tid >> 5;
    const int lane = tid & 31;
    const int g = lane >> 2;
    const int t = lane & 3;
    const int wm = wid & 1;           // 0..1 (64 rows each)
    const int wn = wid >> 1;          // 0..3 (32 cols each)

    const int z = blockIdx.z;
    const int m0 = blockIdx.y * 128;
    const int n0 = blockIdx.x * 128;

    const float* __restrict__ bias = (z == 0) ? bq : (z == 1) ? bk : bv;
    __half* __restrict__ O = (z == 0) ? g_q16 : (z == 1) ? g_k16 : g_v16;
    const int mslot = (z == 0) ? 0 : (z == 1) ? 1 : 4;

    const __half* __restrict__ A = g_x16 + (size_t)m0 * DMODEL;
    const __half* __restrict__ B = g_w16 + (size_t)z * DMODEL * DMODEL + (size_t)n0 * DMODEL;

    if (tid == 0) s_amax = 0u;

    const uint32_t sbase = smem_u32(sm);
    const int a_lrow = lane & 15;
    const int a_lcol = ((lane >> 4) & 1) * 8;
    const int b_lrow = (lane & 7) + (lane >> 4) * 8;
    const int b_lcol = ((lane >> 3) & 1) * 8;

    float c[4][4][4];
#pragma unroll
    for (int mt = 0; mt < 4; mt++)
#pragma unroll
        for (int nt = 0; nt < 4; nt++)
#pragma unroll
            for (int r = 0; r < 4; r++) c[mt][nt][r] = 0.f;

    const int NCH = DMODEL / GKC;     // 32

#define GEMM_LOAD_STAGE(ch, st) do {                                          \
        const int k0 = (ch) * GKC;                                            \
        const uint32_t stb = sbase + (uint32_t)(st) * GSTG_B;                 \
        _Pragma("unroll")                                                     \
        for (int i = 0; i < 2; i++) {                                         \
            const int cid = tid + i * 256;                                    \
            const int row = cid >> 2, cu = cid & 3;                           \
            const size_t go = (size_t)row * DMODEL + k0 + cu * 8;             \
            const uint32_t so = stb + (uint32_t)(row * GST + cu * 8) * 2;     \
            CP_ASYNC16(so + 0 * GTILE_B, (const void*)(A + go));              \
            CP_ASYNC16(so + 1 * GTILE_B, (const void*)(B + go));              \
        }                                                                     \
    } while (0)

    GEMM_LOAD_STAGE(0, 0); CP_COMMIT();
    GEMM_LOAD_STAGE(1, 1); CP_COMMIT();

    int st = 0;
    for (int ch = 0; ch < NCH; ch++) {
        CP_WAIT1();
        __syncthreads();
        if (ch + 2 < NCH) {
            const int st2 = (st + 2 >= 3) ? st - 1 : st + 2;
            GEMM_LOAD_STAGE(ch + 2, st2);
        }
        CP_COMMIT();

        const uint32_t bA = sbase + (uint32_t)st * GSTG_B;
        const uint32_t bB = bA + GTILE_B;
#pragma unroll
        for (int ks = 0; ks < 2; ks++) {
            const int kc = ks * 16;
            uint32_t ah[4][4];
#pragma unroll
            for (int mt = 0; mt < 4; mt++) {
                const uint32_t off =
                    (uint32_t)(((wm * 64 + mt * 16 + a_lrow) * GST + kc + a_lcol) * 2);
                LDSM_X4(ah[mt][0], ah[mt][1], ah[mt][2], ah[mt][3], bA + off);
            }
            uint32_t bf[4][2];
#pragma unroll
            for (int ntp = 0; ntp < 2; ntp++) {
                const uint32_t off =
                    (uint32_t)(((wn * 32 + ntp * 16 + b_lrow) * GST + kc + b_lcol) * 2);
                LDSM_X4(bf[2 * ntp][0], bf[2 * ntp][1],
                        bf[2 * ntp + 1][0], bf[2 * ntp + 1][1], bB + off);
            }
#pragma unroll
            for (int mt = 0; mt < 4; mt++)
#pragma unroll
                for (int nt = 0; nt < 4; nt++)
                    mma_f16(c[mt][nt], ah[mt], bf[nt][0], bf[nt][1]);
        }
        __syncthreads();
        st = (st + 1 >= 3) ? 0 : st + 1;
    }
#undef GEMM_LOAD_STAGE

    // epilogue: bias, absmax, fp16 store, layout [BH][S][64]
    float lmax = 0.f;
#pragma unroll
    for (int nt = 0; nt < 4; nt++) {
        const int n = n0 + wn * 32 + nt * 8 + 2 * t;
        const float bn0 = bias[n], bn1 = bias[n + 1];
        const int h = n >> 6, d = n & 63;
#pragma unroll
        for (int mt = 0; mt < 4; mt++) {
            const int mr0 = m0 + wm * 64 + mt * 16 + g;
            const int mr1 = mr0 + 8;
            float v0 = c[mt][nt][0] + bn0;
            float v1 = c[mt][nt][1] + bn1;
            float v2 = c[mt][nt][2] + bn0;
            float v3 = c[mt][nt][3] + bn1;
            lmax = fmaxf(lmax, fmaxf(fmaxf(fabsf(v0), fabsf(v1)),
                                     fmaxf(fabsf(v2), fabsf(v3))));
            const int bb0 = mr0 >> 11, s0 = mr0 & 2047;
            const int bb1 = mr1 >> 11, s1 = mr1 & 2047;
            const size_t o0 = (((size_t)(bb0 * HEADS + h)) * SEQ + s0) * HDIM + d;
            const size_t o1 = (((size_t)(bb1 * HEADS + h)) * SEQ + s1) * HDIM + d;
            *(uint32_t*)(O + o0) = packh(v0, v1);
            *(uint32_t*)(O + o1) = packh(v2, v3);
        }
    }
    atomicMax(&s_amax, __float_as_uint(lmax));
    __syncthreads();
    if (tid == 0) atomicMax(&g_mx[mslot], s_amax);
}

// ------ flash attention: S 1-pass, PV 1-pass, KV tile 32, 3-stage ----------
#define AKV 32                            // kv rows per tile
#define KST 72                            // smem row stride (fp16), 144B
#define ATILE_B (AKV * KST * 2)           // 4608 B per tile
#define ASTG_B (2 * ATILE_B)              // k v = 9216 B per stage
#define ATTN_SMEM_BYTES (3 * ASTG_B)      // 27648

__global__ __launch_bounds__(256, 2) void attn_mma(float* __restrict__ out)
{
    extern __shared__ __half asm_buf[];
    __shared__ unsigned s_raw, s_aw;

    const int tid = threadIdx.x;
    const int wid = tid >> 5;
    const int lane = tid & 31;
    const int g = lane >> 2;
    const int t = lane & 3;

    const int bh = blockIdx.y;
    const int b = bh >> 4, h = bh & 15;
    const int q0 = blockIdx.x * 128;

    if (tid == 0) { s_raw = 0u; s_aw = 0u; }

    const uint32_t sbase = smem_u32(asm_buf);
    const int b_lrow = (lane & 7) + (lane >> 4) * 8;
    const int b_lcol = ((lane >> 3) & 1) * 8;
    const int v_lrow = (lane & 7) + ((lane >> 3) & 1) * 8;
    const int v_lcol = (lane >> 4) * 8;

    // Q fragments (fp16), loaded once
    const size_t qbase = ((size_t)bh * SEQ + q0 + wid * 16) * HDIM;
    const __half* Qh = g_q16 + qbase;
    uint32_t qh[4][4];
#pragma unroll
    for (int kk = 0; kk < 4; kk++) {
        const int c0 = kk * 16 + 2 * t;
        qh[kk][0] = *(const uint32_t*)(Qh + g * HDIM + c0);
        qh[kk][1] = *(const uint32_t*)(Qh + (g + 8) * HDIM + c0);
        qh[kk][2] = *(const uint32_t*)(Qh + g * HDIM + c0 + 8);
        qh[kk][3] = *(const uint32_t*)(Qh + (g + 8) * HDIM + c0 + 8);
    }

    const __half* K = g_k16 + (size_t)bh * SEQ * HDIM;
    const __half* V = g_v16 + (size_t)bh * SEQ * HDIM;

    float o[8][4];
#pragma unroll
    for (int j = 0; j < 8; j++)
#pragma unroll
        for (int r = 0; r < 4; r++) o[j][r] = 0.f;
    float m0 = -1e30f, m1 = -1e30f, l0 = 0.f, l1 = 0.f, raw = 0.f;

    const int NKV = SEQ / AKV;  // 64

#define ATTN_LOAD_STAGE(kv, st) do {                                          \
        const int base_row = (kv) * AKV;                                      \
        const uint32_t stb = sbase + (uint32_t)(st) * ASTG_B;                 \
        const int row = tid >> 3, du = tid & 7;                               \
        const size_t go = (size_t)(base_row + row) * HDIM + du * 8;           \
        const uint32_t so = stb + (uint32_t)(row * KST + du * 8) * 2;         \
        CP_ASYNC16(so + 0 * ATILE_B, (const void*)(K + go));                  \
        CP_ASYNC16(so + 1 * ATILE_B, (const void*)(V + go));                  \
    } while (0)

    ATTN_LOAD_STAGE(0, 0); CP_COMMIT();
    ATTN_LOAD_STAGE(1, 1); CP_COMMIT();

    int st = 0;
    for (int kv = 0; kv < NKV; kv++) {
        CP_WAIT1();
        __syncthreads();
        if (kv + 2 < NKV) {
            const int st2 = (st + 2 >= 3) ? st - 1 : st + 2;
            ATTN_LOAD_STAGE(kv + 2, st2);
        }
        CP_COMMIT();

        const uint32_t k_b = sbase + (uint32_t)st * ASTG_B;
        const uint32_t v_b = k_b + ATILE_B;

        // S = Q·K^T (single pass)
        float s[4][4];
#pragma unroll
        for (int j = 0; j < 4; j++)
#pragma unroll
            for (int r = 0; r < 4; r++) s[j][r] = 0.f;
#pragma unroll
        for (int kk = 0; kk < 4; kk++) {
            uint32_t kb[4][2];
#pragma unroll
            for (int jp = 0; jp < 2; jp++) {
                const uint32_t off =
                    (uint32_t)(((jp * 16 + b_lrow) * KST + kk * 16 + b_lcol) * 2);
                LDSM_X4(kb[2 * jp][0], kb[2 * jp][1],
                        kb[2 * jp + 1][0], kb[2 * jp + 1][1], k_b + off);
            }
#pragma unroll
            for (int j = 0; j < 4; j++)
                mma_f16(s[j], qh[kk], kb[j][0], kb[j][1]);
        }

        // raw absmax (pre-scale), scale, online softmax
        float rm0 = -1e30f, rm1 = -1e30f;
#pragma unroll
        for (int j = 0; j < 4; j++) {
#pragma unroll
            for (int r = 0; r < 4; r++) {
                raw = fmaxf(raw, fabsf(s[j][r]));
                s[j][r] *= 0.125f;
            }
            rm0 = fmaxf(rm0, fmaxf(s[j][0], s[j][1]));
            rm1 = fmaxf(rm1, fmaxf(s[j][2], s[j][3]));
        }
        rm0 = fmaxf(rm0, __shfl_xor_sync(0xffffffffu, rm0, 1));
        rm0 = fmaxf(rm0, __shfl_xor_sync(0xffffffffu, rm0, 2));
        rm1 = fmaxf(rm1, __shfl_xor_sync(0xffffffffu, rm1, 1));
        rm1 = fmaxf(rm1, __shfl_xor_sync(0xffffffffu, rm1, 2));
        const float mn0 = fmaxf(m0, rm0), mn1 = fmaxf(m1, rm1);
        const float f0 = __expf(m0 - mn0), f1 = __expf(m1 - mn1);
        float ps0 = 0.f, ps1 = 0.f;
#pragma unroll
        for (int j = 0; j < 4; j++) {
            s[j][0] = __expf(s[j][0] - mn0);
            s[j][1] = __expf(s[j][1] - mn0);
            s[j][2] = __expf(s[j][2] - mn1);
            s[j][3] = __expf(s[j][3] - mn1);
            ps0 += s[j][0] + s[j][1];
            ps1 += s[j][2] + s[j][3];
        }
        ps0 += __shfl_xor_sync(0xffffffffu, ps0, 1);
        ps0 += __shfl_xor_sync(0xffffffffu, ps0, 2);
        ps1 += __shfl_xor_sync(0xffffffffu, ps1, 1);
        ps1 += __shfl_xor_sync(0xffffffffu, ps1, 2);
        l0 = l0 * f0 + ps0;
        l1 = l1 * f1 + ps1;
        m0 = mn0; m1 = mn1;
#pragma unroll
        for (int j = 0; j < 8; j++) {
            o[j][0] *= f0; o[j][1] *= f0;
            o[j][2] *= f1; o[j][3] *= f1;
        }

        // P -> fp16 fragments
        uint32_t ph[4][2];
#pragma unroll
        for (int j = 0; j < 4; j++) {
            ph[j][0] = packh(s[j][0], s[j][1]);
            ph[j][1] = packh(s[j][2], s[j][3]);
        }

        // O += P·V (single pass); V frags via ldmatrix.trans
#pragma unroll
        for (int kk = 0; kk < 2; kk++) {
            uint32_t pah[4] = {ph[2 * kk][0], ph[2 * kk][1],
                               ph[2 * kk + 1][0], ph[2 * kk + 1][1]};
            uint32_t vb[8][2];
#pragma unroll
            for (int jp = 0; jp < 4; jp++) {
                const uint32_t off =
                    (uint32_t)(((kk * 16 + v_lrow) * KST + jp * 16 + v_lcol) * 2);
                LDSM_X4_T(vb[2 * jp][0], vb[2 * jp][1],
                          vb[2 * jp + 1][0], vb[2 * jp + 1][1], v_b + off);
            }
#pragma unroll
            for (int j = 0; j < 8; j++)
                mma_f16(o[j], pah, vb[j][0], vb[j][1]);
        }
        __syncthreads();
        st = (st + 1 >= 3) ? 0 : st + 1;
    }
#undef ATTN_LOAD_STAGE

    // epilogue
    const float i0 = 1.f / l0, i1 = 1.f / l1;
    const int r0g = q0 + wid * 16 + g;
    const int r1g = r0g + 8;
    const size_t ob0 = ((size_t)b * SEQ + r0g) * DMODEL + h * HDIM;
    const size_t ob1 = ((size_t)b * SEQ + r1g) * DMODEL + h * HDIM;
#pragma unroll
    for (int j = 0; j < 8; j++) {
        const int d = 8 * j + 2 * t;
        float2 w0 = {o[j][0] * i0, o[j][1] * i0};
        float2 w1 = {o[j][2] * i1, o[j][3] * i1};
        *(float2*)(out + ob0 + d) = w0;
        *(float2*)(out + ob1 + d) = w1;
    }
    atomicMax(&s_raw, __float_as_uint(raw));
    atomicMax(&s_aw, __float_as_uint(fmaxf(i0, i1)));
    __syncthreads();
    if (tid == 0) {
        atomicMax(&g_mx[2], s_raw);
        atomicMax(&g_mx[3], s_aw);
    }
}

// ---------------- finalize scalars ----------------
__global__ void finalize_kernel(float* __restrict__ out, int base)
{
    if (threadIdx.x == 0) {
        const float qm  = __uint_as_float(g_mx[0]);
        const float km  = __uint_as_float(g_mx[1]);
        const float qkm = __uint_as_float(g_mx[2]);
        const float awm = __uint_as_float(g_mx[3]);
        const float vm  = __uint_as_float(g_mx[4]);
        out[base + 0] = qm;
        out[base + 1] = km;
        out[base + 2] = qkm;
        out[base + 3] = awm;
        out[base + 4] = vm;
        out[base + 5] = awm;  // v_out_max (faithful source bug)
    }
}

// ---------------- launch ----------------
extern "C" void kernel_launch(void* const* d_in, const int* in_sizes, int n_in,
                              void* d_out, int out_size)
{
    const float* X  = (const float*)d_in[0];
    const float* Wq = (const float*)d_in[1];
    const float* bq = (const float*)d_in[2];
    const float* Wk = (const float*)d_in[3];
    const float* bk = (const float*)d_in[4];
    const float* Wv = (const float*)d_in[5];
    const float* bv = (const float*)d_in[6];
    float* out = (float*)d_out;

    cudaFuncSetAttribute(qkv_gemm_mma,
                         cudaFuncAttributeMaxDynamicSharedMemorySize,
                         GEMM_SMEM_BYTES);
    cudaFuncSetAttribute(attn_mma,
                         cudaFuncAttributeMaxDynamicSharedMemorySize,
                         ATTN_SMEM_BYTES);

    init_kernel<<<1, 32>>>();                                           // 0
    convert_x<<<MROWS * DMODEL / 4 / 256, 256>>>(X);                    // 1
    convert_w<<<dim3(DMODEL * DMODEL / 4 / 256, 1, 3), 256>>>(Wq, Wk, Wv); // 2
    qkv_gemm_mma<<<dim3(DMODEL / 128, MROWS / 128, 3), 256,
                   GEMM_SMEM_BYTES>>>(bq, bk, bv);                      // 3
    spacer_kernel<<<1, 32>>>();                                         // 4
    attn_mma<<<dim3(SEQ / 128, BATCH * HEADS), 256,
               ATTN_SMEM_BYTES>>>(out);                                 // 5
    finalize_kernel<<<1, 32>>>(out, out_size - 6);                      // 6
}

// round 12
// speedup vs baseline: 9.3261x; 1.0937x over previous
#include <cuda_runtime.h>
#include <cuda_fp16.h>
#include <cstdint>

// Problem constants: B=2, S=2048, DM=1024, H=16, DH=64
#define BATCH 2
#define SEQ 2048
#define DMODEL 1024
#define HEADS 16
#define HDIM 64
#define MROWS (BATCH*SEQ)                 // 4096
#define QKV_ELEMS (BATCH*HEADS*SEQ*HDIM)  // 4,194,304

// ---------------- device scratch (fp16) ----------------
__device__ __half g_x16[MROWS * DMODEL];
__device__ __half g_w16[3 * DMODEL * DMODEL];
__device__ __half g_q16[QKV_ELEMS];
__device__ __half g_k16[QKV_ELEMS];
__device__ __half g_v16[QKV_ELEMS];
// absmax slots: 0=q 1=k 2=qk_raw 3=aw 4=v
__device__ unsigned g_mx[5];

// ---------------- helpers ----------------
__device__ __forceinline__ void mma_f16(float (&c)[4], const uint32_t (&a)[4],
                                        uint32_t b0, uint32_t b1) {
    asm volatile(
        "mma.sync.aligned.m16n8k16.row.col.f32.f16.f16.f32 "
        "{%0,%1,%2,%3}, {%4,%5,%6,%7}, {%8,%9}, {%0,%1,%2,%3};"
        : "+f"(c[0]), "+f"(c[1]), "+f"(c[2]), "+f"(c[3])
        : "r"(a[0]), "r"(a[1]), "r"(a[2]), "r"(a[3]), "r"(b0), "r"(b1));
}
__device__ __forceinline__ uint32_t packh(float lo, float hi) {
    uint32_t r;
    asm("cvt.rn.f16x2.f32 %0, %1, %2;" : "=r"(r) : "f"(hi), "f"(lo));
    return r;
}
__device__ __forceinline__ uint32_t smem_u32(const void* p) {
    uint32_t a;
    asm("{ .reg .u64 t; cvta.to.shared.u64 t, %1; cvt.u32.u64 %0, t; }"
        : "=r"(a) : "l"(p));
    return a;
}
#define LDSM_X4(r0, r1, r2, r3, addr) \
    asm volatile("ldmatrix.sync.aligned.m8n8.x4.shared.b16 {%0,%1,%2,%3}, [%4];" \
                 : "=r"(r0), "=r"(r1), "=r"(r2), "=r"(r3) : "r"(addr))
#define LDSM_X4_T(r0, r1, r2, r3, addr) \
    asm volatile("ldmatrix.sync.aligned.m8n8.x4.trans.shared.b16 {%0,%1,%2,%3}, [%4];" \
                 : "=r"(r0), "=r"(r1), "=r"(r2), "=r"(r3) : "r"(addr))
#define CP_ASYNC16(dst, src) \
    asm volatile("cp.async.cg.shared.global [%0], [%1], 16;" \
                 :: "r"(dst), "l"(src))
#define CP_COMMIT() asm volatile("cp.async.commit_group;" ::: "memory")
#define CP_WAIT1() asm volatile("cp.async.wait_group 1;" ::: "memory")
#define ONES_F16X2 0x3C003C00u

// ---------------- fp32 -> fp16 conversion (init fused) ----------------
__global__ __launch_bounds__(256) void convert_x(const float* __restrict__ X) {
    if (blockIdx.x == 0 && threadIdx.x < 5) g_mx[threadIdx.x] = 0u;
    size_t i4 = ((size_t)blockIdx.x * 256 + threadIdx.x) * 4;
    float4 v = *(const float4*)(X + i4);
    *(__half2*)(g_x16 + i4 + 0) = __floats2half2_rn(v.x, v.y);
    *(__half2*)(g_x16 + i4 + 2) = __floats2half2_rn(v.z, v.w);
}

__global__ __launch_bounds__(256) void convert_w(
    const float* __restrict__ Wq, const float* __restrict__ Wk,
    const float* __restrict__ Wv) {
    const int z = blockIdx.z;
    const float* W = (z == 0) ? Wq : (z == 1) ? Wk : Wv;
    size_t base = (size_t)z * DMODEL * DMODEL;
    size_t i4 = ((size_t)blockIdx.x * 256 + threadIdx.x) * 4;
    float4 v = *(const float4*)(W + i4);
    *(__half2*)(g_w16 + base + i4 + 0) = __floats2half2_rn(v.x, v.y);
    *(__half2*)(g_w16 + base + i4 + 2) = __floats2half2_rn(v.z, v.w);
}

// ---- fp16 1-pass QKV GEMM: 256 thr, 2 CTA/SM, K-chunk 64, 2-stage ---------
#define GKC 64
#define GST 72                           // smem row stride (fp16), 144B
#define GTILE_B (128 * GST * 2)          // 18432 B per tile
#define GSTG_B (2 * GTILE_B)             // A B = 36864 B per stage
#define GEMM_SMEM_BYTES (2 * GSTG_B)     // 73728

__global__ __launch_bounds__(256, 2) void qkv_gemm_mma(
    const float* __restrict__ bq, const float* __restrict__ bk,
    const float* __restrict__ bv)
{
    extern __shared__ __half sm[];
    __shared__ unsigned s_amax;

    const int tid = threadIdx.x;
    const int wid = tid >> 5;
    const int lane = tid & 31;
    const int g = lane >> 2;
    const int t = lane & 3;
    const int wm = wid & 1;           // 0..1 (64 rows each)
    const int wn = wid >> 1;          // 0..3 (32 cols each)

    const int z = blockIdx.z;
    const int m0 = blockIdx.y * 128;
    const int n0 = blockIdx.x * 128;

    const float* __restrict__ bias = (z == 0) ? bq : (z == 1) ? bk : bv;
    __half* __restrict__ O = (z == 0) ? g_q16 : (z == 1) ? g_k16 : g_v16;
    const int mslot = (z == 0) ? 0 : (z == 1) ? 1 : 4;

    const __half* __restrict__ A = g_x16 + (size_t)m0 * DMODEL;
    const __half* __restrict__ B = g_w16 + (size_t)z * DMODEL * DMODEL + (size_t)n0 * DMODEL;

    if (tid == 0) s_amax = 0u;

    const uint32_t sbase = smem_u32(sm);
    const int a_lrow = lane & 15;
    const int a_lcol = ((lane >> 4) & 1) * 8;
    const int b_lrow = (lane & 7) + (lane >> 4) * 8;
    const int b_lcol = ((lane >> 3) & 1) * 8;

    float c[4][4][4];
#pragma unroll
    for (int mt = 0; mt < 4; mt++)
#pragma unroll
        for (int nt = 0; nt < 4; nt++)
#pragma unroll
            for (int r = 0; r < 4; r++) c[mt][nt][r] = 0.f;

    const int NCH = DMODEL / GKC;     // 16

    // 128 rows x 128B per matrix: 4 x 16B cp.async per matrix per thread
#define GEMM_LOAD_STAGE(ch, st) do {                                          \
        const int k0 = (ch) * GKC;                                            \
        const uint32_t stb = sbase + (uint32_t)(st) * GSTG_B;                 \
        _Pragma("unroll")                                                     \
        for (int i = 0; i < 4; i++) {                                         \
            const int cid = tid + i * 256;                                    \
            const int row = cid >> 3, du = cid & 7;                           \
            const size_t go = (size_t)row * DMODEL + k0 + du * 8;             \
            const uint32_t so = stb + (uint32_t)(row * GST + du * 8) * 2;     \
            CP_ASYNC16(so + 0 * GTILE_B, (const void*)(A + go));              \
            CP_ASYNC16(so + 1 * GTILE_B, (const void*)(B + go));              \
        }                                                                     \
    } while (0)

    GEMM_LOAD_STAGE(0, 0); CP_COMMIT();
    GEMM_LOAD_STAGE(1, 1); CP_COMMIT();

    for (int ch = 0; ch < NCH; ch++) {
        CP_WAIT1();
        __syncthreads();
        const int st = ch & 1;
        const uint32_t bA = sbase + (uint32_t)st * GSTG_B;
        const uint32_t bB = bA + GTILE_B;
#pragma unroll
        for (int ks = 0; ks < 4; ks++) {
            const int kc = ks * 16;
            uint32_t ah[4][4];
#pragma unroll
            for (int mt = 0; mt < 4; mt++) {
                const uint32_t off =
                    (uint32_t)(((wm * 64 + mt * 16 + a_lrow) * GST + kc + a_lcol) * 2);
                LDSM_X4(ah[mt][0], ah[mt][1], ah[mt][2], ah[mt][3], bA + off);
            }
            uint32_t bf[4][2];
#pragma unroll
            for (int ntp = 0; ntp < 2; ntp++) {
                const uint32_t off =
                    (uint32_t)(((wn * 32 + ntp * 16 + b_lrow) * GST + kc + b_lcol) * 2);
                LDSM_X4(bf[2 * ntp][0], bf[2 * ntp][1],
                        bf[2 * ntp + 1][0], bf[2 * ntp + 1][1], bB + off);
            }
#pragma unroll
            for (int mt = 0; mt < 4; mt++)
#pragma unroll
                for (int nt = 0; nt < 4; nt++)
                    mma_f16(c[mt][nt], ah[mt], bf[nt][0], bf[nt][1]);
        }
        __syncthreads();
        if (ch + 2 < NCH) {
            GEMM_LOAD_STAGE(ch + 2, st);
            CP_COMMIT();
        }
    }
#undef GEMM_LOAD_STAGE

    // epilogue: bias, absmax, fp16 store, layout [BH][S][64]
    float lmax = 0.f;
#pragma unroll
    for (int nt = 0; nt < 4; nt++) {
        const int n = n0 + wn * 32 + nt * 8 + 2 * t;
        const float bn0 = bias[n], bn1 = bias[n + 1];
        const int h = n >> 6, d = n & 63;
#pragma unroll
        for (int mt = 0; mt < 4; mt++) {
            const int mr0 = m0 + wm * 64 + mt * 16 + g;
            const int mr1 = mr0 + 8;
            float v0 = c[mt][nt][0] + bn0;
            float v1 = c[mt][nt][1] + bn1;
            float v2 = c[mt][nt][2] + bn0;
            float v3 = c[mt][nt][3] + bn1;
            lmax = fmaxf(lmax, fmaxf(fmaxf(fabsf(v0), fabsf(v1)),
                                     fmaxf(fabsf(v2), fabsf(v3))));
            const int bb0 = mr0 >> 11, s0 = mr0 & 2047;
            const int bb1 = mr1 >> 11, s1 = mr1 & 2047;
            const size_t o0 = (((size_t)(bb0 * HEADS + h)) * SEQ + s0) * HDIM + d;
            const size_t o1 = (((size_t)(bb1 * HEADS + h)) * SEQ + s1) * HDIM + d;
            *(uint32_t*)(O + o0) = packh(v0, v1);
            *(uint32_t*)(O + o1) = packh(v2, v3);
        }
    }
    atomicMax(&s_amax, __float_as_uint(lmax));
    __syncthreads();
    if (tid == 0) atomicMax(&g_mx[mslot], s_amax);
}

// ------ flash attention: fp16, MMA row-sum for l, KV tile 32, 3-stage ------
#define AKV 32                            // kv rows per tile
#define KST 72                            // smem row stride (fp16), 144B
#define ATILE_B (AKV * KST * 2)           // 4608 B per tile
#define ASTG_B (2 * ATILE_B)              // k v = 9216 B per stage
#define ATTN_SMEM_BYTES (3 * ASTG_B)      // 27648

__global__ __launch_bounds__(256, 2) void attn_mma(float* __restrict__ out)
{
    extern __shared__ __half asm_buf[];
    __shared__ unsigned s_raw, s_aw;

    const int tid = threadIdx.x;
    const int wid = tid >> 5;
    const int lane = tid & 31;
    const int g = lane >> 2;
    const int t = lane & 3;

    const int bh = blockIdx.y;
    const int b = bh >> 4, h = bh & 15;
    const int q0 = blockIdx.x * 128;

    if (tid == 0) { s_raw = 0u; s_aw = 0u; }

    const uint32_t sbase = smem_u32(asm_buf);
    const int b_lrow = (lane & 7) + (lane >> 4) * 8;
    const int b_lcol = ((lane >> 3) & 1) * 8;
    const int v_lrow = (lane & 7) + ((lane >> 3) & 1) * 8;
    const int v_lcol = (lane >> 4) * 8;

    // Q fragments (fp16), loaded once
    const size_t qbase = ((size_t)bh * SEQ + q0 + wid * 16) * HDIM;
    const __half* Qh = g_q16 + qbase;
    uint32_t qh[4][4];
#pragma unroll
    for (int kk = 0; kk < 4; kk++) {
        const int c0 = kk * 16 + 2 * t;
        qh[kk][0] = *(const uint32_t*)(Qh + g * HDIM + c0);
        qh[kk][1] = *(const uint32_t*)(Qh + (g + 8) * HDIM + c0);
        qh[kk][2] = *(const uint32_t*)(Qh + g * HDIM + c0 + 8);
        qh[kk][3] = *(const uint32_t*)(Qh + (g + 8) * HDIM + c0 + 8);
    }

    const __half* K = g_k16 + (size_t)bh * SEQ * HDIM;
    const __half* V = g_v16 + (size_t)bh * SEQ * HDIM;

    float o[8][4];
#pragma unroll
    for (int j = 0; j < 8; j++)
#pragma unroll
        for (int r = 0; r < 4; r++) o[j][r] = 0.f;
    float lac[4] = {0.f, 0.f, 0.f, 0.f};   // row-sum accumulator (l via MMA)
    float m0 = -1e30f, m1 = -1e30f, raw = 0.f;

    const int NKV = SEQ / AKV;  // 64

#define ATTN_LOAD_STAGE(kv, st) do {                                          \
        const int base_row = (kv) * AKV;                                      \
        const uint32_t stb = sbase + (uint32_t)(st) * ASTG_B;                 \
        const int row = tid >> 3, du = tid & 7;                               \
        const size_t go = (size_t)(base_row + row) * HDIM + du * 8;           \
        const uint32_t so = stb + (uint32_t)(row * KST + du * 8) * 2;         \
        CP_ASYNC16(so + 0 * ATILE_B, (const void*)(K + go));                  \
        CP_ASYNC16(so + 1 * ATILE_B, (const void*)(V + go));                  \
    } while (0)

    ATTN_LOAD_STAGE(0, 0); CP_COMMIT();
    ATTN_LOAD_STAGE(1, 1); CP_COMMIT();

    int st = 0;
    for (int kv = 0; kv < NKV; kv++) {
        CP_WAIT1();
        __syncthreads();
        if (kv + 2 < NKV) {
            const int st2 = (st + 2 >= 3) ? st - 1 : st + 2;
            ATTN_LOAD_STAGE(kv + 2, st2);
        }
        CP_COMMIT();

        const uint32_t k_b = sbase + (uint32_t)st * ASTG_B;
        const uint32_t v_b = k_b + ATILE_B;

        // S = Q·K^T (single pass)
        float s[4][4];
#pragma unroll
        for (int j = 0; j < 4; j++)
#pragma unroll
            for (int r = 0; r < 4; r++) s[j][r] = 0.f;
#pragma unroll
        for (int kk = 0; kk < 4; kk++) {
            uint32_t kb[4][2];
#pragma unroll
            for (int jp = 0; jp < 2; jp++) {
                const uint32_t off =
                    (uint32_t)(((jp * 16 + b_lrow) * KST + kk * 16 + b_lcol) * 2);
                LDSM_X4(kb[2 * jp][0], kb[2 * jp][1],
                        kb[2 * jp + 1][0], kb[2 * jp + 1][1], k_b + off);
            }
#pragma unroll
            for (int j = 0; j < 4; j++)
                mma_f16(s[j], qh[kk], kb[j][0], kb[j][1]);
        }

        // raw absmax (pre-scale), scale, online max (shuffle over t)
        float rm0 = -1e30f, rm1 = -1e30f;
#pragma unroll
        for (int j = 0; j < 4; j++) {
#pragma unroll
            for (int r = 0; r < 4; r++) {
                raw = fmaxf(raw, fabsf(s[j][r]));
                s[j][r] *= 0.125f;
            }
            rm0 = fmaxf(rm0, fmaxf(s[j][0], s[j][1]));
            rm1 = fmaxf(rm1, fmaxf(s[j][2], s[j][3]));
        }
        rm0 = fmaxf(rm0, __shfl_xor_sync(0xffffffffu, rm0, 1));
        rm0 = fmaxf(rm0, __shfl_xor_sync(0xffffffffu, rm0, 2));
        rm1 = fmaxf(rm1, __shfl_xor_sync(0xffffffffu, rm1, 1));
        rm1 = fmaxf(rm1, __shfl_xor_sync(0xffffffffu, rm1, 2));
        const float mn0 = fmaxf(m0, rm0), mn1 = fmaxf(m1, rm1);
        const float f0 = __expf(m0 - mn0), f1 = __expf(m1 - mn1);
        m0 = mn0; m1 = mn1;
#pragma unroll
        for (int j = 0; j < 4; j++) {
            s[j][0] = __expf(s[j][0] - mn0);
            s[j][1] = __expf(s[j][1] - mn0);
            s[j][2] = __expf(s[j][2] - mn1);
            s[j][3] = __expf(s[j][3] - mn1);
        }
        // rescale O and l-accumulator by the online factors
#pragma unroll
        for (int j = 0; j < 8; j++) {
            o[j][0] *= f0; o[j][1] *= f0;
            o[j][2] *= f1; o[j][3] *= f1;
        }
        lac[0] *= f0; lac[1] *= f0;
        lac[2] *= f1; lac[3] *= f1;

        // P -> fp16 fragments
        uint32_t ph[4][2];
#pragma unroll
        for (int j = 0; j < 4; j++) {
            ph[j][0] = packh(s[j][0], s[j][1]);
            ph[j][1] = packh(s[j][2], s[j][3]);
        }

        // O += P·V (single pass) + l += P·1 via extra MMA
#pragma unroll
        for (int kk = 0; kk < 2; kk++) {
            uint32_t pah[4] = {ph[2 * kk][0], ph[2 * kk][1],
                               ph[2 * kk + 1][0], ph[2 * kk + 1][1]};
            uint32_t vb[8][2];
#pragma unroll
            for (int jp = 0; jp < 4; jp++) {
                const uint32_t off =
                    (uint32_t)(((kk * 16 + v_lrow) * KST + jp * 16 + v_lcol) * 2);
                LDSM_X4_T(vb[2 * jp][0], vb[2 * jp][1],
                          vb[2 * jp + 1][0], vb[2 * jp + 1][1], v_b + off);
            }
#pragma unroll
            for (int j = 0; j < 8; j++)
                mma_f16(o[j], pah, vb[j][0], vb[j][1]);
            mma_f16(lac, pah, ONES_F16X2, ONES_F16X2);  // row sums -> l
        }
        __syncthreads();
        st = (st + 1 >= 3) ? 0 : st + 1;
    }
#undef ATTN_LOAD_STAGE

    // epilogue: l lives in lac[0] (rows g) and lac[2] (rows g+8)
    const float i0 = 1.f / lac[0], i1 = 1.f / lac[2];
    const int r0g = q0 + wid * 16 + g;
    const int r1g = r0g + 8;
    const size_t ob0 = ((size_t)b * SEQ + r0g) * DMODEL + h * HDIM;
    const size_t ob1 = ((size_t)b * SEQ + r1g) * DMODEL + h * HDIM;
#pragma unroll
    for (int j = 0; j < 8; j++) {
        const int d = 8 * j + 2 * t;
        float2 w0 = {o[j][0] * i0, o[j][1] * i0};
        float2 w1 = {o[j][2] * i1, o[j][3] * i1};
        *(float2*)(out + ob0 + d) = w0;
        *(float2*)(out + ob1 + d) = w1;
    }
    atomicMax(&s_raw, __float_as_uint(raw));
    atomicMax(&s_aw, __float_as_uint(fmaxf(i0, i1)));
    __syncthreads();
    if (tid == 0) {
        atomicMax(&g_mx[2], s_raw);
        atomicMax(&g_mx[3], s_aw);
    }
}

// ---------------- finalize scalars ----------------
__global__ void finalize_kernel(float* __restrict__ out, int base)
{
    if (threadIdx.x == 0) {
        const float qm  = __uint_as_float(g_mx[0]);
        const float km  = __uint_as_float(g_mx[1]);
        const float qkm = __uint_as_float(g_mx[2]);
        const float awm = __uint_as_float(g_mx[3]);
        const float vm  = __uint_as_float(g_mx[4]);
        out[base + 0] = qm;
        out[base + 1] = km;
        out[base + 2] = qkm;
        out[base + 3] = awm;
        out[base + 4] = vm;
        out[base + 5] = awm;  // v_out_max (faithful source bug)
    }
}

// ---------------- launch ----------------
extern "C" void kernel_launch(void* const* d_in, const int* in_sizes, int n_in,
                              void* d_out, int out_size)
{
    const float* X  = (const float*)d_in[0];
    const float* Wq = (const float*)d_in[1];
    const float* bq = (const float*)d_in[2];
    const float* Wk = (const float*)d_in[3];
    const float* bk = (const float*)d_in[4];
    const float* Wv = (const float*)d_in[5];
    const float* bv = (const float*)d_in[6];
    float* out = (float*)d_out;

    cudaFuncSetAttribute(qkv_gemm_mma,
                         cudaFuncAttributeMaxDynamicSharedMemorySize,
                         GEMM_SMEM_BYTES);
    cudaFuncSetAttribute(attn_mma,
                         cudaFuncAttributeMaxDynamicSharedMemorySize,
                         ATTN_SMEM_BYTES);

    convert_x<<<MROWS * DMODEL / 4 / 256, 256>>>(X);                    // 0
    convert_w<<<dim3(DMODEL * DMODEL / 4 / 256, 1, 3), 256>>>(Wq, Wk, Wv); // 1
    qkv_gemm_mma<<<dim3(DMODEL / 128, MROWS / 128, 3), 256,
                   GEMM_SMEM_BYTES>>>(bq, bk, bv);                      // 2
    attn_mma<<<dim3(SEQ / 128, BATCH * HEADS), 256,
               ATTN_SMEM_BYTES>>>(out);                                 // 3
    finalize_kernel<<<1, 32>>>(out, out_size - 6);                      // 4
}

// round 13
// speedup vs baseline: 9.6851x; 1.0385x over previous
#include <cuda_runtime.h>
#include <cuda_fp16.h>
#include <cstdint>

// Problem constants: B=2, S=2048, DM=1024, H=16, DH=64
#define BATCH 2
#define SEQ 2048
#define DMODEL 1024
#define HEADS 16
#define HDIM 64
#define MROWS (BATCH*SEQ)                 // 4096
#define QKV_ELEMS (BATCH*HEADS*SEQ*HDIM)  // 4,194,304

// Q prescale: 0.125 * log2(e)  (scores arrive in exp2 domain)
#define QSCALE 0.18033688011112042f
// rawmax recovery: 1 / QSCALE * ... raw = s2 / (0.125*log2e)
#define RAWSCALE 5.5451774444795623f

// ---------------- device scratch (fp16) ----------------
__device__ __half g_x16[MROWS * DMODEL];
__device__ __half g_w16[3 * DMODEL * DMODEL];
__device__ __half g_q16[QKV_ELEMS];
__device__ __half g_k16[QKV_ELEMS];
__device__ __half g_v16[QKV_ELEMS];
// absmax slots: 0=q 1=k 2=qk_raw 3=aw 4=v
__device__ unsigned g_mx[5];

// ---------------- helpers ----------------
__device__ __forceinline__ void mma_f16(float (&c)[4], const uint32_t (&a)[4],
                                        uint32_t b0, uint32_t b1) {
    asm volatile(
        "mma.sync.aligned.m16n8k16.row.col.f32.f16.f16.f32 "
        "{%0,%1,%2,%3}, {%4,%5,%6,%7}, {%8,%9}, {%0,%1,%2,%3};"
        : "+f"(c[0]), "+f"(c[1]), "+f"(c[2]), "+f"(c[3])
        : "r"(a[0]), "r"(a[1]), "r"(a[2]), "r"(a[3]), "r"(b0), "r"(b1));
}
__device__ __forceinline__ uint32_t packh(float lo, float hi) {
    uint32_t r;
    asm("cvt.rn.f16x2.f32 %0, %1, %2;" : "=r"(r) : "f"(hi), "f"(lo));
    return r;
}
__device__ __forceinline__ uint32_t smem_u32(const void* p) {
    uint32_t a;
    asm("{ .reg .u64 t; cvta.to.shared.u64 t, %1; cvt.u32.u64 %0, t; }"
        : "=r"(a) : "l"(p));
    return a;
}
#define LDSM_X4(r0, r1, r2, r3, addr) \
    asm volatile("ldmatrix.sync.aligned.m8n8.x4.shared.b16 {%0,%1,%2,%3}, [%4];" \
                 : "=r"(r0), "=r"(r1), "=r"(r2), "=r"(r3) : "r"(addr))
#define LDSM_X4_T(r0, r1, r2, r3, addr) \
    asm volatile("ldmatrix.sync.aligned.m8n8.x4.trans.shared.b16 {%0,%1,%2,%3}, [%4];" \
                 : "=r"(r0), "=r"(r1), "=r"(r2), "=r"(r3) : "r"(addr))
#define CP_ASYNC16(dst, src) \
    asm volatile("cp.async.cg.shared.global [%0], [%1], 16;" \
                 :: "r"(dst), "l"(src))
#define CP_COMMIT() asm volatile("cp.async.commit_group;" ::: "memory")
#define CP_WAIT1() asm volatile("cp.async.wait_group 1;" ::: "memory")
#define ONES_F16X2 0x3C003C00u

// ---------------- fp32 -> fp16 conversion (init fused) ----------------
__global__ __launch_bounds__(256) void convert_x(const float* __restrict__ X) {
    if (blockIdx.x == 0 && threadIdx.x < 5) g_mx[threadIdx.x] = 0u;
    size_t i4 = ((size_t)blockIdx.x * 256 + threadIdx.x) * 4;
    float4 v = *(const float4*)(X + i4);
    *(__half2*)(g_x16 + i4 + 0) = __floats2half2_rn(v.x, v.y);
    *(__half2*)(g_x16 + i4 + 2) = __floats2half2_rn(v.z, v.w);
}

__global__ __launch_bounds__(256) void convert_w(
    const float* __restrict__ Wq, const float* __restrict__ Wk,
    const float* __restrict__ Wv) {
    const int z = blockIdx.z;
    const float* W = (z == 0) ? Wq : (z == 1) ? Wk : Wv;
    size_t base = (size_t)z * DMODEL * DMODEL;
    size_t i4 = ((size_t)blockIdx.x * 256 + threadIdx.x) * 4;
    float4 v = *(const float4*)(W + i4);
    *(__half2*)(g_w16 + base + i4 + 0) = __floats2half2_rn(v.x, v.y);
    *(__half2*)(g_w16 + base + i4 + 2) = __floats2half2_rn(v.z, v.w);
}

// ---- fp16 1-pass QKV GEMM: 256 thr, 2 CTA/SM, K-chunk 64, 2-stage ---------
#define GKC 64
#define GST 72                           // smem row stride (fp16), 144B
#define GTILE_B (128 * GST * 2)          // 18432 B per tile
#define GSTG_B (2 * GTILE_B)             // A B = 36864 B per stage
#define GEMM_SMEM_BYTES (2 * GSTG_B)     // 73728

__global__ __launch_bounds__(256, 2) void qkv_gemm_mma(
    const float* __restrict__ bq, const float* __restrict__ bk,
    const float* __restrict__ bv)
{
    extern __shared__ __half sm[];
    __shared__ unsigned s_amax;

    const int tid = threadIdx.x;
    const int wid = tid >> 5;
    const int lane = tid & 31;
    const int g = lane >> 2;
    const int t = lane & 3;
    const int wm = wid & 1;           // 0..1 (64 rows each)
    const int wn = wid >> 1;          // 0..3 (32 cols each)

    const int z = blockIdx.z;
    const int m0 = blockIdx.y * 128;
    const int n0 = blockIdx.x * 128;

    const float* __restrict__ bias = (z == 0) ? bq : (z == 1) ? bk : bv;
    __half* __restrict__ O = (z == 0) ? g_q16 : (z == 1) ? g_k16 : g_v16;
    const int mslot = (z == 0) ? 0 : (z == 1) ? 1 : 4;
    const float osc = (z == 0) ? QSCALE : 1.0f;   // Q prescale into exp2 domain

    const __half* __restrict__ A = g_x16 + (size_t)m0 * DMODEL;
    const __half* __restrict__ B = g_w16 + (size_t)z * DMODEL * DMODEL + (size_t)n0 * DMODEL;

    if (tid == 0) s_amax = 0u;

    const uint32_t sbase = smem_u32(sm);
    const int a_lrow = lane & 15;
    const int a_lcol = ((lane >> 4) & 1) * 8;
    const int b_lrow = (lane & 7) + (lane >> 4) * 8;
    const int b_lcol = ((lane >> 3) & 1) * 8;

    float c[4][4][4];
#pragma unroll
    for (int mt = 0; mt < 4; mt++)
#pragma unroll
        for (int nt = 0; nt < 4; nt++)
#pragma unroll
            for (int r = 0; r < 4; r++) c[mt][nt][r] = 0.f;

    const int NCH = DMODEL / GKC;     // 16

#define GEMM_LOAD_STAGE(ch, st) do {                                          \
        const int k0 = (ch) * GKC;                                            \
        const uint32_t stb = sbase + (uint32_t)(st) * GSTG_B;                 \
        _Pragma("unroll")                                                     \
        for (int i = 0; i < 4; i++) {                                         \
            const int cid = tid + i * 256;                                    \
            const int row = cid >> 3, du = cid & 7;                           \
            const size_t go = (size_t)row * DMODEL + k0 + du * 8;             \
            const uint32_t so = stb + (uint32_t)(row * GST + du * 8) * 2;     \
            CP_ASYNC16(so + 0 * GTILE_B, (const void*)(A + go));              \
            CP_ASYNC16(so + 1 * GTILE_B, (const void*)(B + go));              \
        }                                                                     \
    } while (0)

    GEMM_LOAD_STAGE(0, 0); CP_COMMIT();
    GEMM_LOAD_STAGE(1, 1); CP_COMMIT();

    for (int ch = 0; ch < NCH; ch++) {
        CP_WAIT1();
        __syncthreads();
        const int st = ch & 1;
        const uint32_t bA = sbase + (uint32_t)st * GSTG_B;
        const uint32_t bB = bA + GTILE_B;
#pragma unroll
        for (int ks = 0; ks < 4; ks++) {
            const int kc = ks * 16;
            uint32_t ah[4][4];
#pragma unroll
            for (int mt = 0; mt < 4; mt++) {
                const uint32_t off =
                    (uint32_t)(((wm * 64 + mt * 16 + a_lrow) * GST + kc + a_lcol) * 2);
                LDSM_X4(ah[mt][0], ah[mt][1], ah[mt][2], ah[mt][3], bA + off);
            }
            uint32_t bf[4][2];
#pragma unroll
            for (int ntp = 0; ntp < 2; ntp++) {
                const uint32_t off =
                    (uint32_t)(((wn * 32 + ntp * 16 + b_lrow) * GST + kc + b_lcol) * 2);
                LDSM_X4(bf[2 * ntp][0], bf[2 * ntp][1],
                        bf[2 * ntp + 1][0], bf[2 * ntp + 1][1], bB + off);
            }
#pragma unroll
            for (int mt = 0; mt < 4; mt++)
#pragma unroll
                for (int nt = 0; nt < 4; nt++)
                    mma_f16(c[mt][nt], ah[mt], bf[nt][0], bf[nt][1]);
        }
        __syncthreads();
        if (ch + 2 < NCH) {
            GEMM_LOAD_STAGE(ch + 2, st);
            CP_COMMIT();
        }
    }
#undef GEMM_LOAD_STAGE

    // epilogue: bias, absmax (pre-scale), fp16 store (Q prescaled)
    float lmax = 0.f;
#pragma unroll
    for (int nt = 0; nt < 4; nt++) {
        const int n = n0 + wn * 32 + nt * 8 + 2 * t;
        const float bn0 = bias[n], bn1 = bias[n + 1];
        const int h = n >> 6, d = n & 63;
#pragma unroll
        for (int mt = 0; mt < 4; mt++) {
            const int mr0 = m0 + wm * 64 + mt * 16 + g;
            const int mr1 = mr0 + 8;
            float v0 = c[mt][nt][0] + bn0;
            float v1 = c[mt][nt][1] + bn1;
            float v2 = c[mt][nt][2] + bn0;
            float v3 = c[mt][nt][3] + bn1;
            lmax = fmaxf(lmax, fmaxf(fmaxf(fabsf(v0), fabsf(v1)),
                                     fmaxf(fabsf(v2), fabsf(v3))));
            const int bb0 = mr0 >> 11, s0 = mr0 & 2047;
            const int bb1 = mr1 >> 11, s1 = mr1 & 2047;
            const size_t o0 = (((size_t)(bb0 * HEADS + h)) * SEQ + s0) * HDIM + d;
            const size_t o1 = (((size_t)(bb1 * HEADS + h)) * SEQ + s1) * HDIM + d;
            *(uint32_t*)(O + o0) = packh(v0 * osc, v1 * osc);
            *(uint32_t*)(O + o1) = packh(v2 * osc, v3 * osc);
        }
    }
    atomicMax(&s_amax, __float_as_uint(lmax));
    __syncthreads();
    if (tid == 0) atomicMax(&g_mx[mslot], s_amax);
}

// ------ flash attention: exp2 domain, rescale-skip, KV tile 32, 3-stage ----
#define AKV 32                            // kv rows per tile
#define KST 72                            // smem row stride (fp16), 144B
#define ATILE_B (AKV * KST * 2)           // 4608 B per tile
#define ASTG_B (2 * ATILE_B)              // k v = 9216 B per stage
#define ATTN_SMEM_BYTES (3 * ASTG_B)      // 27648

__global__ __launch_bounds__(256, 2) void attn_mma(float* __restrict__ out)
{
    extern __shared__ __half asm_buf[];
    __shared__ unsigned s_raw, s_aw;

    const int tid = threadIdx.x;
    const int wid = tid >> 5;
    const int lane = tid & 31;
    const int g = lane >> 2;
    const int t = lane & 3;

    const int bh = blockIdx.y;
    const int b = bh >> 4, h = bh & 15;
    const int q0 = blockIdx.x * 128;

    if (tid == 0) { s_raw = 0u; s_aw = 0u; }

    const uint32_t sbase = smem_u32(asm_buf);
    const int b_lrow = (lane & 7) + (lane >> 4) * 8;
    const int b_lcol = ((lane >> 3) & 1) * 8;
    const int v_lrow = (lane & 7) + ((lane >> 3) & 1) * 8;
    const int v_lcol = (lane >> 4) * 8;

    // Q fragments (fp16, prescaled to exp2 domain), loaded once
    const size_t qbase = ((size_t)bh * SEQ + q0 + wid * 16) * HDIM;
    const __half* Qh = g_q16 + qbase;
    uint32_t qh[4][4];
#pragma unroll
    for (int kk = 0; kk < 4; kk++) {
        const int c0 = kk * 16 + 2 * t;
        qh[kk][0] = *(const uint32_t*)(Qh + g * HDIM + c0);
        qh[kk][1] = *(const uint32_t*)(Qh + (g + 8) * HDIM + c0);
        qh[kk][2] = *(const uint32_t*)(Qh + g * HDIM + c0 + 8);
        qh[kk][3] = *(const uint32_t*)(Qh + (g + 8) * HDIM + c0 + 8);
    }

    const __half* K = g_k16 + (size_t)bh * SEQ * HDIM;
    const __half* V = g_v16 + (size_t)bh * SEQ * HDIM;

    float o[8][4];
#pragma unroll
    for (int j = 0; j < 8; j++)
#pragma unroll
        for (int r = 0; r < 4; r++) o[j][r] = 0.f;
    float lac[4] = {0.f, 0.f, 0.f, 0.f};   // row-sum accumulator (l via MMA)
    float m0 = -1e30f, m1 = -1e30f, raw = 0.f;

    const int NKV = SEQ / AKV;  // 64

#define ATTN_LOAD_STAGE(kv, st) do {                                          \
        const int base_row = (kv) * AKV;                                      \
        const uint32_t stb = sbase + (uint32_t)(st) * ASTG_B;                 \
        const int row = tid >> 3, du = tid & 7;                               \
        const size_t go = (size_t)(base_row + row) * HDIM + du * 8;           \
        const uint32_t so = stb + (uint32_t)(row * KST + du * 8) * 2;         \
        CP_ASYNC16(so + 0 * ATILE_B, (const void*)(K + go));                  \
        CP_ASYNC16(so + 1 * ATILE_B, (const void*)(V + go));                  \
    } while (0)

    ATTN_LOAD_STAGE(0, 0); CP_COMMIT();
    ATTN_LOAD_STAGE(1, 1); CP_COMMIT();

    int st = 0;
    for (int kv = 0; kv < NKV; kv++) {
        CP_WAIT1();
        __syncthreads();
        if (kv + 2 < NKV) {
            const int st2 = (st + 2 >= 3) ? st - 1 : st + 2;
            ATTN_LOAD_STAGE(kv + 2, st2);
        }
        CP_COMMIT();

        const uint32_t k_b = sbase + (uint32_t)st * ASTG_B;
        const uint32_t v_b = k_b + ATILE_B;

        // S2 = Qs·K^T (scores already in exp2 domain)
        float s[4][4];
#pragma unroll
        for (int j = 0; j < 4; j++)
#pragma unroll
            for (int r = 0; r < 4; r++) s[j][r] = 0.f;
#pragma unroll
        for (int kk = 0; kk < 4; kk++) {
            uint32_t kb[4][2];
#pragma unroll
            for (int jp = 0; jp < 2; jp++) {
                const uint32_t off =
                    (uint32_t)(((jp * 16 + b_lrow) * KST + kk * 16 + b_lcol) * 2);
                LDSM_X4(kb[2 * jp][0], kb[2 * jp][1],
                        kb[2 * jp + 1][0], kb[2 * jp + 1][1], k_b + off);
            }
#pragma unroll
            for (int j = 0; j < 4; j++)
                mma_f16(s[j], qh[kk], kb[j][0], kb[j][1]);
        }

        // absmax (exp2 domain, rescaled at end), online max
        float rm0 = -1e30f, rm1 = -1e30f;
#pragma unroll
        for (int j = 0; j < 4; j++) {
#pragma unroll
            for (int r = 0; r < 4; r++)
                raw = fmaxf(raw, fabsf(s[j][r]));
            rm0 = fmaxf(rm0, fmaxf(s[j][0], s[j][1]));
            rm1 = fmaxf(rm1, fmaxf(s[j][2], s[j][3]));
        }
        rm0 = fmaxf(rm0, __shfl_xor_sync(0xffffffffu, rm0, 1));
        rm0 = fmaxf(rm0, __shfl_xor_sync(0xffffffffu, rm0, 2));
        rm1 = fmaxf(rm1, __shfl_xor_sync(0xffffffffu, rm1, 1));
        rm1 = fmaxf(rm1, __shfl_xor_sync(0xffffffffu, rm1, 2));
        const float mn0 = fmaxf(m0, rm0), mn1 = fmaxf(m1, rm1);
        // rescale-skip: only when the running max advanced anywhere in warp
        const bool upd = (mn0 > m0) || (mn1 > m1);
        if (__any_sync(0xffffffffu, upd)) {
            const float f0 = exp2f(m0 - mn0), f1 = exp2f(m1 - mn1);
#pragma unroll
            for (int j = 0; j < 8; j++) {
                o[j][0] *= f0; o[j][1] *= f0;
                o[j][2] *= f1; o[j][3] *= f1;
            }
            lac[0] *= f0; lac[1] *= f0;
            lac[2] *= f1; lac[3] *= f1;
            m0 = mn0; m1 = mn1;
        }
#pragma unroll
        for (int j = 0; j < 4; j++) {
            s[j][0] = exp2f(s[j][0] - m0);
            s[j][1] = exp2f(s[j][1] - m0);
            s[j][2] = exp2f(s[j][2] - m1);
            s[j][3] = exp2f(s[j][3] - m1);
        }

        // P -> fp16 fragments
        uint32_t ph[4][2];
#pragma unroll
        for (int j = 0; j < 4; j++) {
            ph[j][0] = packh(s[j][0], s[j][1]);
            ph[j][1] = packh(s[j][2], s[j][3]);
        }

        // O += P·V + l += P·1 via extra MMA
#pragma unroll
        for (int kk = 0; kk < 2; kk++) {
            uint32_t pah[4] = {ph[2 * kk][0], ph[2 * kk][1],
                               ph[2 * kk + 1][0], ph[2 * kk + 1][1]};
            uint32_t vb[8][2];
#pragma unroll
            for (int jp = 0; jp < 4; jp++) {
                const uint32_t off =
                    (uint32_t)(((kk * 16 + v_lrow) * KST + jp * 16 + v_lcol) * 2);
                LDSM_X4_T(vb[2 * jp][0], vb[2 * jp][1],
                          vb[2 * jp + 1][0], vb[2 * jp + 1][1], v_b + off);
            }
#pragma unroll
            for (int j = 0; j < 8; j++)
                mma_f16(o[j], pah, vb[j][0], vb[j][1]);
            mma_f16(lac, pah, ONES_F16X2, ONES_F16X2);  // row sums -> l
        }
        __syncthreads();
        st = (st + 1 >= 3) ? 0 : st + 1;
    }
#undef ATTN_LOAD_STAGE

    // epilogue: l lives in lac[0] (rows g) and lac[2] (rows g+8)
    const float i0 = 1.f / lac[0], i1 = 1.f / lac[2];
    const int r0g = q0 + wid * 16 + g;
    const int r1g = r0g + 8;
    const size_t ob0 = ((size_t)b * SEQ + r0g) * DMODEL + h * HDIM;
    const size_t ob1 = ((size_t)b * SEQ + r1g) * DMODEL + h * HDIM;
#pragma unroll
    for (int j = 0; j < 8; j++) {
        const int d = 8 * j + 2 * t;
        float2 w0 = {o[j][0] * i0, o[j][1] * i0};
        float2 w1 = {o[j][2] * i1, o[j][3] * i1};
        *(float2*)(out + ob0 + d) = w0;
        *(float2*)(out + ob1 + d) = w1;
    }
    atomicMax(&s_raw, __float_as_uint(raw * RAWSCALE));  // back to raw domain
    atomicMax(&s_aw, __float_as_uint(fmaxf(i0, i1)));
    __syncthreads();
    if (tid == 0) {
        atomicMax(&g_mx[2], s_raw);
        atomicMax(&g_mx[3], s_aw);
    }
}

// ---------------- finalize scalars ----------------
__global__ void finalize_kernel(float* __restrict__ out, int base)
{
    if (threadIdx.x == 0) {
        const float qm  = __uint_as_float(g_mx[0]);
        const float km  = __uint_as_float(g_mx[1]);
        const float qkm = __uint_as_float(g_mx[2]);
        const float awm = __uint_as_float(g_mx[3]);
        const float vm  = __uint_as_float(g_mx[4]);
        out[base + 0] = qm;
        out[base + 1] = km;
        out[base + 2] = qkm;
        out[base + 3] = awm;
        out[base + 4] = vm;
        out[base + 5] = awm;  // v_out_max (faithful source bug)
    }
}

// ---------------- launch ----------------
extern "C" void kernel_launch(void* const* d_in, const int* in_sizes, int n_in,
                              void* d_out, int out_size)
{
    const float* X  = (const float*)d_in[0];
    const float* Wq = (const float*)d_in[1];
    const float* bq = (const float*)d_in[2];
    const float* Wk = (const float*)d_in[3];
    const float* bk = (const float*)d_in[4];
    const float* Wv = (const float*)d_in[5];
    const float* bv = (const float*)d_in[6];
    float* out = (float*)d_out;

    cudaFuncSetAttribute(qkv_gemm_mma,
                         cudaFuncAttributeMaxDynamicSharedMemorySize,
                         GEMM_SMEM_BYTES);
    cudaFuncSetAttribute(attn_mma,
                         cudaFuncAttributeMaxDynamicSharedMemorySize,
                         ATTN_SMEM_BYTES);

    convert_x<<<MROWS * DMODEL / 4 / 256, 256>>>(X);                    // 0
    convert_w<<<dim3(DMODEL * DMODEL / 4 / 256, 1, 3), 256>>>(Wq, Wk, Wv); // 1
    qkv_gemm_mma<<<dim3(DMODEL / 128, MROWS / 128, 3), 256,
                   GEMM_SMEM_BYTES>>>(bq, bk, bv);                      // 2
    attn_mma<<<dim3(SEQ / 128, BATCH * HEADS), 256,
               ATTN_SMEM_BYTES>>>(out);                                 // 3
    finalize_kernel<<<1, 32>>>(out, out_size - 6);                      // 4
}

// round 14
// speedup vs baseline: 9.9516x; 1.0275x over previous
#include <cuda_runtime.h>
#include <cuda_fp16.h>
#include <cstdint>

// Problem constants: B=2, S=2048, DM=1024, H=16, DH=64
#define BATCH 2
#define SEQ 2048
#define DMODEL 1024
#define HEADS 16
#define HDIM 64
#define MROWS (BATCH*SEQ)                 // 4096
#define QKV_ELEMS (BATCH*HEADS*SEQ*HDIM)  // 4,194,304

// Q prescale: 0.125 * log2(e)  (scores arrive in exp2 domain)
#define QSCALE 0.18033688011112042f
#define RAWSCALE 5.5451774444795623f

// ---------------- device scratch (fp16) ----------------
__device__ __half g_x16[MROWS * DMODEL];
__device__ __half g_w16[3 * DMODEL * DMODEL];
__device__ __half g_q16[QKV_ELEMS];
__device__ __half g_k16[QKV_ELEMS];
__device__ __half g_v16[QKV_ELEMS];
// absmax slots: 0=q 1=k 2=qk_raw 3=aw 4=v
__device__ unsigned g_mx[5];

// ---------------- helpers ----------------
__device__ __forceinline__ void mma_f16(float (&c)[4], const uint32_t (&a)[4],
                                        uint32_t b0, uint32_t b1) {
    asm volatile(
        "mma.sync.aligned.m16n8k16.row.col.f32.f16.f16.f32 "
        "{%0,%1,%2,%3}, {%4,%5,%6,%7}, {%8,%9}, {%0,%1,%2,%3};"
        : "+f"(c[0]), "+f"(c[1]), "+f"(c[2]), "+f"(c[3])
        : "r"(a[0]), "r"(a[1]), "r"(a[2]), "r"(a[3]), "r"(b0), "r"(b1));
}
__device__ __forceinline__ uint32_t packh(float lo, float hi) {
    uint32_t r;
    asm("cvt.rn.f16x2.f32 %0, %1, %2;" : "=r"(r) : "f"(hi), "f"(lo));
    return r;
}
__device__ __forceinline__ uint32_t ex2_h2(uint32_t a) {
    uint32_t r;
    asm("ex2.approx.f16x2 %0, %1;" : "=r"(r) : "r"(a));
    return r;
}
__device__ __forceinline__ uint32_t smem_u32(const void* p) {
    uint32_t a;
    asm("{ .reg .u64 t; cvta.to.shared.u64 t, %1; cvt.u32.u64 %0, t; }"
        : "=r"(a) : "l"(p));
    return a;
}
#define LDSM_X4(r0, r1, r2, r3, addr) \
    asm volatile("ldmatrix.sync.aligned.m8n8.x4.shared.b16 {%0,%1,%2,%3}, [%4];" \
                 : "=r"(r0), "=r"(r1), "=r"(r2), "=r"(r3) : "r"(addr))
#define LDSM_X4_T(r0, r1, r2, r3, addr) \
    asm volatile("ldmatrix.sync.aligned.m8n8.x4.trans.shared.b16 {%0,%1,%2,%3}, [%4];" \
                 : "=r"(r0), "=r"(r1), "=r"(r2), "=r"(r3) : "r"(addr))
#define CP_ASYNC16(dst, src) \
    asm volatile("cp.async.cg.shared.global [%0], [%1], 16;" \
                 :: "r"(dst), "l"(src))
#define CP_COMMIT() asm volatile("cp.async.commit_group;" ::: "memory")
#define CP_WAIT1() asm volatile("cp.async.wait_group 1;" ::: "memory")
#define ONES_F16X2 0x3C003C00u

// ---------------- fp32 -> fp16 conversion (init fused) ----------------
__global__ __launch_bounds__(256) void convert_x(const float* __restrict__ X) {
    if (blockIdx.x == 0 && threadIdx.x < 5) g_mx[threadIdx.x] = 0u;
    size_t i4 = ((size_t)blockIdx.x * 256 + threadIdx.x) * 4;
    float4 v = *(const float4*)(X + i4);
    *(__half2*)(g_x16 + i4 + 0) = __floats2half2_rn(v.x, v.y);
    *(__half2*)(g_x16 + i4 + 2) = __floats2half2_rn(v.z, v.w);
}

__global__ __launch_bounds__(256) void convert_w(
    const float* __restrict__ Wq, const float* __restrict__ Wk,
    const float* __restrict__ Wv) {
    const int z = blockIdx.z;
    const float* W = (z == 0) ? Wq : (z == 1) ? Wk : Wv;
    size_t base = (size_t)z * DMODEL * DMODEL;
    size_t i4 = ((size_t)blockIdx.x * 256 + threadIdx.x) * 4;
    float4 v = *(const float4*)(W + i4);
    *(__half2*)(g_w16 + base + i4 + 0) = __floats2half2_rn(v.x, v.y);
    *(__half2*)(g_w16 + base + i4 + 2) = __floats2half2_rn(v.z, v.w);
}

// ---- fp16 1-pass QKV GEMM: 256 thr, 2 CTA/SM, K-chunk 64, 2-stage ---------
#define GKC 64
#define GST 72                           // smem row stride (fp16), 144B
#define GTILE_B (128 * GST * 2)          // 18432 B per tile
#define GSTG_B (2 * GTILE_B)             // A B = 36864 B per stage
#define GEMM_SMEM_BYTES (2 * GSTG_B)     // 73728

__global__ __launch_bounds__(256, 2) void qkv_gemm_mma(
    const float* __restrict__ bq, const float* __restrict__ bk,
    const float* __restrict__ bv)
{
    extern __shared__ __half sm[];
    __shared__ unsigned s_amax;

    const int tid = threadIdx.x;
    const int wid = tid >> 5;
    const int lane = tid & 31;
    const int g = lane >> 2;
    const int t = lane & 3;
    const int wm = wid & 1;
    const int wn = wid >> 1;

    const int z = blockIdx.z;
    const int m0 = blockIdx.y * 128;
    const int n0 = blockIdx.x * 128;

    const float* __restrict__ bias = (z == 0) ? bq : (z == 1) ? bk : bv;
    __half* __restrict__ O = (z == 0) ? g_q16 : (z == 1) ? g_k16 : g_v16;
    const int mslot = (z == 0) ? 0 : (z == 1) ? 1 : 4;
    const float osc = (z == 0) ? QSCALE : 1.0f;

    const __half* __restrict__ A = g_x16 + (size_t)m0 * DMODEL;
    const __half* __restrict__ B = g_w16 + (size_t)z * DMODEL * DMODEL + (size_t)n0 * DMODEL;

    if (tid == 0) s_amax = 0u;

    const uint32_t sbase = smem_u32(sm);
    const int a_lrow = lane & 15;
    const int a_lcol = ((lane >> 4) & 1) * 8;
    const int b_lrow = (lane & 7) + (lane >> 4) * 8;
    const int b_lcol = ((lane >> 3) & 1) * 8;

    float c[4][4][4];
#pragma unroll
    for (int mt = 0; mt < 4; mt++)
#pragma unroll
        for (int nt = 0; nt < 4; nt++)
#pragma unroll
            for (int r = 0; r < 4; r++) c[mt][nt][r] = 0.f;

    const int NCH = DMODEL / GKC;     // 16

#define GEMM_LOAD_STAGE(ch, st) do {                                          \
        const int k0 = (ch) * GKC;                                            \
        const uint32_t stb = sbase + (uint32_t)(st) * GSTG_B;                 \
        _Pragma("unroll")                                                     \
        for (int i = 0; i < 4; i++) {                                         \
            const int cid = tid + i * 256;                                    \
            const int row = cid >> 3, du = cid & 7;                           \
            const size_t go = (size_t)row * DMODEL + k0 + du * 8;             \
            const uint32_t so = stb + (uint32_t)(row * GST + du * 8) * 2;     \
            CP_ASYNC16(so + 0 * GTILE_B, (const void*)(A + go));              \
            CP_ASYNC16(so + 1 * GTILE_B, (const void*)(B + go));              \
        }                                                                     \
    } while (0)

    GEMM_LOAD_STAGE(0, 0); CP_COMMIT();
    GEMM_LOAD_STAGE(1, 1); CP_COMMIT();

    for (int ch = 0; ch < NCH; ch++) {
        CP_WAIT1();
        __syncthreads();
        const int st = ch & 1;
        const uint32_t bA = sbase + (uint32_t)st * GSTG_B;
        const uint32_t bB = bA + GTILE_B;
#pragma unroll
        for (int ks = 0; ks < 4; ks++) {
            const int kc = ks * 16;
            uint32_t ah[4][4];
#pragma unroll
            for (int mt = 0; mt < 4; mt++) {
                const uint32_t off =
                    (uint32_t)(((wm * 64 + mt * 16 + a_lrow) * GST + kc + a_lcol) * 2);
                LDSM_X4(ah[mt][0], ah[mt][1], ah[mt][2], ah[mt][3], bA + off);
            }
            uint32_t bf[4][2];
#pragma unroll
            for (int ntp = 0; ntp < 2; ntp++) {
                const uint32_t off =
                    (uint32_t)(((wn * 32 + ntp * 16 + b_lrow) * GST + kc + b_lcol) * 2);
                LDSM_X4(bf[2 * ntp][0], bf[2 * ntp][1],
                        bf[2 * ntp + 1][0], bf[2 * ntp + 1][1], bB + off);
            }
#pragma unroll
            for (int mt = 0; mt < 4; mt++)
#pragma unroll
                for (int nt = 0; nt < 4; nt++)
                    mma_f16(c[mt][nt], ah[mt], bf[nt][0], bf[nt][1]);
        }
        __syncthreads();
        if (ch + 2 < NCH) {
            GEMM_LOAD_STAGE(ch + 2, st);
            CP_COMMIT();
        }
    }
#undef GEMM_LOAD_STAGE

    // epilogue: bias, absmax (pre-scale), fp16 store (Q prescaled)
    float lmax = 0.f;
#pragma unroll
    for (int nt = 0; nt < 4; nt++) {
        const int n = n0 + wn * 32 + nt * 8 + 2 * t;
        const float bn0 = bias[n], bn1 = bias[n + 1];
        const int h = n >> 6, d = n & 63;
#pragma unroll
        for (int mt = 0; mt < 4; mt++) {
            const int mr0 = m0 + wm * 64 + mt * 16 + g;
            const int mr1 = mr0 + 8;
            float v0 = c[mt][nt][0] + bn0;
            float v1 = c[mt][nt][1] + bn1;
            float v2 = c[mt][nt][2] + bn0;
            float v3 = c[mt][nt][3] + bn1;
            lmax = fmaxf(lmax, fmaxf(fmaxf(fabsf(v0), fabsf(v1)),
                                     fmaxf(fabsf(v2), fabsf(v3))));
            const int bb0 = mr0 >> 11, s0 = mr0 & 2047;
            const int bb1 = mr1 >> 11, s1 = mr1 & 2047;
            const size_t o0 = (((size_t)(bb0 * HEADS + h)) * SEQ + s0) * HDIM + d;
            const size_t o1 = (((size_t)(bb1 * HEADS + h)) * SEQ + s1) * HDIM + d;
            *(uint32_t*)(O + o0) = packh(v0 * osc, v1 * osc);
            *(uint32_t*)(O + o1) = packh(v2 * osc, v3 * osc);
        }
    }
    atomicMax(&s_amax, __float_as_uint(lmax));
    __syncthreads();
    if (tid == 0) atomicMax(&g_mx[mslot], s_amax);
}

// ------ flash attention: exp2 half2 P, rescale-skip, 1 bar/tile ------------
#define AKV 32                            // kv rows per tile
#define KST 72                            // smem row stride (fp16), 144B
#define ATILE_B (AKV * KST * 2)           // 4608 B per tile
#define ASTG_B (2 * ATILE_B)              // k v = 9216 B per stage
#define ATTN_SMEM_BYTES (3 * ASTG_B)      // 27648

__global__ __launch_bounds__(256, 2) void attn_mma(float* __restrict__ out)
{
    extern __shared__ __half asm_buf[];
    __shared__ unsigned s_raw, s_aw;

    const int tid = threadIdx.x;
    const int wid = tid >> 5;
    const int lane = tid & 31;
    const int g = lane >> 2;
    const int t = lane & 3;

    const int bh = blockIdx.y;
    const int b = bh >> 4, h = bh & 15;
    const int q0 = blockIdx.x * 128;

    if (tid == 0) { s_raw = 0u; s_aw = 0u; }

    const uint32_t sbase = smem_u32(asm_buf);
    const int b_lrow = (lane & 7) + (lane >> 4) * 8;
    const int b_lcol = ((lane >> 3) & 1) * 8;
    const int v_lrow = (lane & 7) + ((lane >> 3) & 1) * 8;
    const int v_lcol = (lane >> 4) * 8;

    // Q fragments (fp16, prescaled to exp2 domain), loaded once
    const size_t qbase = ((size_t)bh * SEQ + q0 + wid * 16) * HDIM;
    const __half* Qh = g_q16 + qbase;
    uint32_t qh[4][4];
#pragma unroll
    for (int kk = 0; kk < 4; kk++) {
        const int c0 = kk * 16 + 2 * t;
        qh[kk][0] = *(const uint32_t*)(Qh + g * HDIM + c0);
        qh[kk][1] = *(const uint32_t*)(Qh + (g + 8) * HDIM + c0);
        qh[kk][2] = *(const uint32_t*)(Qh + g * HDIM + c0 + 8);
        qh[kk][3] = *(const uint32_t*)(Qh + (g + 8) * HDIM + c0 + 8);
    }

    const __half* K = g_k16 + (size_t)bh * SEQ * HDIM;
    const __half* V = g_v16 + (size_t)bh * SEQ * HDIM;

    float o[8][4];
#pragma unroll
    for (int j = 0; j < 8; j++)
#pragma unroll
        for (int r = 0; r < 4; r++) o[j][r] = 0.f;
    float lac[4] = {0.f, 0.f, 0.f, 0.f};
    float m0 = -1e30f, m1 = -1e30f, raw = 0.f;

    const int NKV = SEQ / AKV;  // 64

#define ATTN_LOAD_STAGE(kv, st) do {                                          \
        const int base_row = (kv) * AKV;                                      \
        const uint32_t stb = sbase + (uint32_t)(st) * ASTG_B;                 \
        const int row = tid >> 3, du = tid & 7;                               \
        const size_t go = (size_t)(base_row + row) * HDIM + du * 8;           \
        const uint32_t so = stb + (uint32_t)(row * KST + du * 8) * 2;         \
        CP_ASYNC16(so + 0 * ATILE_B, (const void*)(K + go));                  \
        CP_ASYNC16(so + 1 * ATILE_B, (const void*)(V + go));                  \
    } while (0)

    ATTN_LOAD_STAGE(0, 0); CP_COMMIT();
    ATTN_LOAD_STAGE(1, 1); CP_COMMIT();

    int st = 0;
    for (int kv = 0; kv < NKV; kv++) {
        CP_WAIT1();
        __syncthreads();   // single barrier per tile: orders prior-iter reads
        if (kv + 2 < NKV) {
            const int st2 = (st + 2 >= 3) ? st - 1 : st + 2;
            ATTN_LOAD_STAGE(kv + 2, st2);
        }
        CP_COMMIT();

        const uint32_t k_b = sbase + (uint32_t)st * ASTG_B;
        const uint32_t v_b = k_b + ATILE_B;

        // S2 = Qs·K^T (scores already in exp2 domain)
        float s[4][4];
#pragma unroll
        for (int j = 0; j < 4; j++)
#pragma unroll
            for (int r = 0; r < 4; r++) s[j][r] = 0.f;
#pragma unroll
        for (int kk = 0; kk < 4; kk++) {
            uint32_t kb[4][2];
#pragma unroll
            for (int jp = 0; jp < 2; jp++) {
                const uint32_t off =
                    (uint32_t)(((jp * 16 + b_lrow) * KST + kk * 16 + b_lcol) * 2);
                LDSM_X4(kb[2 * jp][0], kb[2 * jp][1],
                        kb[2 * jp + 1][0], kb[2 * jp + 1][1], k_b + off);
            }
#pragma unroll
            for (int j = 0; j < 4; j++)
                mma_f16(s[j], qh[kk], kb[j][0], kb[j][1]);
        }

        // absmax, online max
        float rm0 = -1e30f, rm1 = -1e30f;
#pragma unroll
        for (int j = 0; j < 4; j++) {
#pragma unroll
            for (int r = 0; r < 4; r++)
                raw = fmaxf(raw, fabsf(s[j][r]));
            rm0 = fmaxf(rm0, fmaxf(s[j][0], s[j][1]));
            rm1 = fmaxf(rm1, fmaxf(s[j][2], s[j][3]));
        }
        rm0 = fmaxf(rm0, __shfl_xor_sync(0xffffffffu, rm0, 1));
        rm0 = fmaxf(rm0, __shfl_xor_sync(0xffffffffu, rm0, 2));
        rm1 = fmaxf(rm1, __shfl_xor_sync(0xffffffffu, rm1, 1));
        rm1 = fmaxf(rm1, __shfl_xor_sync(0xffffffffu, rm1, 2));
        const float mn0 = fmaxf(m0, rm0), mn1 = fmaxf(m1, rm1);
        const bool upd = (mn0 > m0) || (mn1 > m1);
        if (__any_sync(0xffffffffu, upd)) {
            const float f0 = exp2f(m0 - mn0), f1 = exp2f(m1 - mn1);
#pragma unroll
            for (int j = 0; j < 8; j++) {
                o[j][0] *= f0; o[j][1] *= f0;
                o[j][2] *= f1; o[j][3] *= f1;
            }
            lac[0] *= f0; lac[1] *= f0;
            lac[2] *= f1; lac[3] *= f1;
            m0 = mn0; m1 = mn1;
        }

        // P fragments directly in half2 via ex2.approx.f16x2
        uint32_t ph[4][2];
#pragma unroll
        for (int j = 0; j < 4; j++) {
            ph[j][0] = ex2_h2(packh(s[j][0] - m0, s[j][1] - m0));
            ph[j][1] = ex2_h2(packh(s[j][2] - m1, s[j][3] - m1));
        }

        // O += P·V + l += P·1 via extra MMA
#pragma unroll
        for (int kk = 0; kk < 2; kk++) {
            uint32_t pah[4] = {ph[2 * kk][0], ph[2 * kk][1],
                               ph[2 * kk + 1][0], ph[2 * kk + 1][1]};
            uint32_t vb[8][2];
#pragma unroll
            for (int jp = 0; jp < 4; jp++) {
                const uint32_t off =
                    (uint32_t)(((kk * 16 + v_lrow) * KST + jp * 16 + v_lcol) * 2);
                LDSM_X4_T(vb[2 * jp][0], vb[2 * jp][1],
                          vb[2 * jp + 1][0], vb[2 * jp + 1][1], v_b + off);
            }
#pragma unroll
            for (int j = 0; j < 8; j++)
                mma_f16(o[j], pah, vb[j][0], vb[j][1]);
            mma_f16(lac, pah, ONES_F16X2, ONES_F16X2);
        }
        st = (st + 1 >= 3) ? 0 : st + 1;
    }
#undef ATTN_LOAD_STAGE

    // epilogue
    const float i0 = 1.f / lac[0], i1 = 1.f / lac[2];
    const int r0g = q0 + wid * 16 + g;
    const int r1g = r0g + 8;
    const size_t ob0 = ((size_t)b * SEQ + r0g) * DMODEL + h * HDIM;
    const size_t ob1 = ((size_t)b * SEQ + r1g) * DMODEL + h * HDIM;
#pragma unroll
    for (int j = 0; j < 8; j++) {
        const int d = 8 * j + 2 * t;
        float2 w0 = {o[j][0] * i0, o[j][1] * i0};
        float2 w1 = {o[j][2] * i1, o[j][3] * i1};
        *(float2*)(out + ob0 + d) = w0;
        *(float2*)(out + ob1 + d) = w1;
    }
    atomicMax(&s_raw, __float_as_uint(raw * RAWSCALE));
    atomicMax(&s_aw, __float_as_uint(fmaxf(i0, i1)));
    __syncthreads();
    if (tid == 0) {
        atomicMax(&g_mx[2], s_raw);
        atomicMax(&g_mx[3], s_aw);
    }
}

// ---------------- finalize scalars ----------------
__global__ void finalize_kernel(float* __restrict__ out, int base)
{
    if (threadIdx.x == 0) {
        const float qm  = __uint_as_float(g_mx[0]);
        const float km  = __uint_as_float(g_mx[1]);
        const float qkm = __uint_as_float(g_mx[2]);
        const float awm = __uint_as_float(g_mx[3]);
        const float vm  = __uint_as_float(g_mx[4]);
        out[base + 0] = qm;
        out[base + 1] = km;
        out[base + 2] = qkm;
        out[base + 3] = awm;
        out[base + 4] = vm;
        out[base + 5] = awm;  // v_out_max (faithful source bug)
    }
}

// ---------------- launch ----------------
extern "C" void kernel_launch(void* const* d_in, const int* in_sizes, int n_in,
                              void* d_out, int out_size)
{
    const float* X  = (const float*)d_in[0];
    const float* Wq = (const float*)d_in[1];
    const float* bq = (const float*)d_in[2];
    const float* Wk = (const float*)d_in[3];
    const float* bk = (const float*)d_in[4];
    const float* Wv = (const float*)d_in[5];
    const float* bv = (const float*)d_in[6];
    float* out = (float*)d_out;

    cudaFuncSetAttribute(qkv_gemm_mma,
                         cudaFuncAttributeMaxDynamicSharedMemorySize,
                         GEMM_SMEM_BYTES);
    cudaFuncSetAttribute(attn_mma,
                         cudaFuncAttributeMaxDynamicSharedMemorySize,
                         ATTN_SMEM_BYTES);

    convert_x<<<MROWS * DMODEL / 4 / 256, 256>>>(X);                    // 0
    convert_w<<<dim3(DMODEL * DMODEL / 4 / 256, 1, 3), 256>>>(Wq, Wk, Wv); // 1
    qkv_gemm_mma<<<dim3(DMODEL / 128, MROWS / 128, 3), 256,
                   GEMM_SMEM_BYTES>>>(bq, bk, bv);                      // 2
    attn_mma<<<dim3(SEQ / 128, BATCH * HEADS), 256,
               ATTN_SMEM_BYTES>>>(out);                                 // 3
    finalize_kernel<<<1, 32>>>(out, out_size - 6);                      // 4
}